// round 9
// baseline (speedup 1.0000x reference)
#include <cuda_runtime.h>
#include <cstdint>

// ---------------------------------------------------------------------------
// LinearMultiheadAttention: x:(4,4096,1024), 16 heads x 64 dim, chunk 128.
// R9: GEMM inputs pre-converted ONCE to bf16 hi/lo (split-precision); GEMM hot
// loop is pure LDG-prefetch + STS + ldmatrix + mma.sync (no cvt). attn_out2
// emits bf16 hi/lo att directly for the output GEMM.
// RULE: __device__ symbols passed as kernel args MUST go through
// cudaGetSymbolAddress (GB300 ATS makes the host-shadow silently writable).
// ---------------------------------------------------------------------------

typedef unsigned long long u64;

// ---------------- f32x2 helpers ----------------
__device__ __forceinline__ u64 pack2(float x) {
    u64 r; asm("mov.b64 %0, {%1, %1};" : "=l"(r) : "f"(x)); return r;
}
__device__ __forceinline__ u64 ffma2(u64 a, u64 b, u64 c) {
    u64 d; asm("fma.rn.f32x2 %0, %1, %2, %3;" : "=l"(d) : "l"(a), "l"(b), "l"(c)); return d;
}
__device__ __forceinline__ void unpack2(u64 v, float& lo, float& hi) {
    asm("mov.b64 {%0, %1}, %2;" : "=f"(lo), "=f"(hi) : "l"(v));
}

// ---------------- tensor-core helpers (sm_80 baseline ISA) ----------------
__device__ __forceinline__ uint32_t smem_u32(const void* p) {
    return (uint32_t)__cvta_generic_to_shared(p);
}
__device__ __forceinline__ void ldsm_x4(uint32_t* r, uint32_t addr) {
    asm volatile("ldmatrix.sync.aligned.m8n8.x4.shared.b16 {%0,%1,%2,%3}, [%4];"
                 : "=r"(r[0]), "=r"(r[1]), "=r"(r[2]), "=r"(r[3]) : "r"(addr));
}
__device__ __forceinline__ void ldsm_x2(uint32_t* r, uint32_t addr) {
    asm volatile("ldmatrix.sync.aligned.m8n8.x2.shared.b16 {%0,%1}, [%2];"
                 : "=r"(r[0]), "=r"(r[1]) : "r"(addr));
}
__device__ __forceinline__ void mma_bf16(float* c, const uint32_t* a, const uint32_t* b) {
    asm volatile(
        "mma.sync.aligned.m16n8k16.row.col.f32.bf16.bf16.f32 "
        "{%0,%1,%2,%3}, {%4,%5,%6,%7}, {%8,%9}, {%0,%1,%2,%3};"
        : "+f"(c[0]), "+f"(c[1]), "+f"(c[2]), "+f"(c[3])
        : "r"(a[0]), "r"(a[1]), "r"(a[2]), "r"(a[3]), "r"(b[0]), "r"(b[1]));
}
// 8 fp32 -> 8 bf16 hi (16B) + 8 bf16 lo (16B); element order preserved.
__device__ __forceinline__ void cvt8(const float4 f0, const float4 f1,
                                     uint4& hi, uint4& lo)
{
    const float a[8] = {f0.x, f0.y, f0.z, f0.w, f1.x, f1.y, f1.z, f1.w};
    uint32_t h[4], l[4];
#pragma unroll
    for (int i = 0; i < 4; i++) {
        asm("cvt.rn.bf16x2.f32 %0, %1, %2;" : "=r"(h[i]) : "f"(a[2*i+1]), "f"(a[2*i]));
        const float flo = __uint_as_float(h[i] << 16);
        const float fhi = __uint_as_float(h[i] & 0xFFFF0000u);
        asm("cvt.rn.bf16x2.f32 %0, %1, %2;" : "=r"(l[i]) : "f"(a[2*i+1] - fhi), "f"(a[2*i] - flo));
    }
    hi = make_uint4(h[0], h[1], h[2], h[3]);
    lo = make_uint4(l[0], l[1], l[2], l[3]);
}

constexpr int Bn   = 4;
constexpr int Sq   = 4096;
constexpr int Dm   = 1024;
constexpr int Hn   = 16;
constexpr int Hd   = 64;
constexpr int Mtot = Bn * Sq;     // 16384
constexpr int Ck   = 128;
constexpr int Nch  = Sq / Ck;     // 32
constexpr int BHn  = Bn * Hn;     // 64
constexpr int DD   = Dm * Dm;

__device__ __align__(16) float g_q[(size_t)Mtot * Dm];
__device__ __align__(16) float g_k[(size_t)Mtot * Dm];
__device__ __align__(16) float g_v[(size_t)Mtot * Dm];
__device__ __align__(16) float g_Sp[(size_t)BHn * Nch * Hd * Hd];
__device__ __align__(16) float g_zp[(size_t)BHn * Nch * Hd];
__device__ __align__(16) float g_sc[(size_t)BHn * Nch * Ck * Ck];
// bf16 hi/lo operands
__device__ __align__(16) uint16_t g_xh[(size_t)Mtot * Dm];
__device__ __align__(16) uint16_t g_xl[(size_t)Mtot * Dm];
__device__ __align__(16) uint16_t g_wh[(size_t)4 * DD];
__device__ __align__(16) uint16_t g_wl[(size_t)4 * DD];
__device__ __align__(16) uint16_t g_ath[(size_t)Mtot * Dm];
__device__ __align__(16) uint16_t g_atl[(size_t)Mtot * Dm];

// ---------------------------------------------------------------------------
// fp32 -> bf16 hi/lo split, 8 elems/thread, grid-stride.
// ---------------------------------------------------------------------------
__global__ void __launch_bounds__(256)
cvt_split_k(const float* __restrict__ src, uint16_t* __restrict__ hi,
            uint16_t* __restrict__ lo, int n8)
{
    int i = blockIdx.x * blockDim.x + threadIdx.x;
    const int stride = gridDim.x * blockDim.x;
    for (; i < n8; i += stride) {
        const float4 f0 = ((const float4*)src)[2 * i];
        const float4 f1 = ((const float4*)src)[2 * i + 1];
        uint4 h, l;
        cvt8(f0, f1, h, l);
        ((uint4*)hi)[i] = h;
        ((uint4*)lo)[i] = l;
    }
}

// ---------------------------------------------------------------------------
// HMMA GEMM on pre-split bf16: Y = A.W^T + bias (logical fp32 via 3 MMAs).
// MODE 0: plain store | MODE 1: phi + permuted [bh][s][hd] | MODE 2: permuted
// 128x128 tile, BK=32, 8 warps (2m x 4n), warp tile 64x32, reg-prefetch pipeline.
// ---------------------------------------------------------------------------
constexpr int BK  = 32;
constexpr int LDK = 40;   // padded smem row (bf16 elems): 80B stride

template <int MODE>
__global__ void __launch_bounds__(256, 2)
bf_gemm_k(const uint16_t* __restrict__ Ah_g, const uint16_t* __restrict__ Al_g,
          const uint16_t* __restrict__ Bh_g, const uint16_t* __restrict__ Bl_g,
          const float* __restrict__ bias, float* __restrict__ out)
{
    __shared__ __align__(16) uint16_t Ahs[128 * LDK];
    __shared__ __align__(16) uint16_t Als[128 * LDK];
    __shared__ __align__(16) uint16_t Bhs[128 * LDK];
    __shared__ __align__(16) uint16_t Bls[128 * LDK];

    const int tid  = threadIdx.x;
    const int lane = tid & 31;
    const int wid  = tid >> 5;
    const int wm   = wid >> 2;
    const int wn   = wid & 3;
    const int bm   = blockIdx.y << 7;
    const int bn   = blockIdx.x << 7;

    const int lrow  = tid >> 1;
    const int lhalf = (tid & 1) << 4;   // 0 or 16 (bf16 elems)
    const uint16_t* pAh = Ah_g + (size_t)(bm + lrow) * Dm + lhalf;
    const uint16_t* pAl = Al_g + (size_t)(bm + lrow) * Dm + lhalf;
    const uint16_t* pBh = Bh_g + (size_t)(bn + lrow) * Dm + lhalf;
    const uint16_t* pBl = Bl_g + (size_t)(bn + lrow) * Dm + lhalf;
    const uint32_t sbyte = (uint32_t)(lrow * LDK + lhalf) * 2;

    float acc[4][4][4];
#pragma unroll
    for (int i = 0; i < 4; i++)
#pragma unroll
        for (int j = 0; j < 4; j++)
#pragma unroll
            for (int r = 0; r < 4; r++) acc[i][j][r] = 0.f;

    const uint32_t aB = smem_u32(Ahs), alB = smem_u32(Als);
    const uint32_t bB = smem_u32(Bhs), blB = smem_u32(Bls);

    uint4 pre[4][2];
#define LD_PRE(kc) do { const size_t o = (size_t)(kc) * BK;                     \
        pre[0][0] = *(const uint4*)(pAh + o); pre[0][1] = *(const uint4*)(pAh + o + 8); \
        pre[1][0] = *(const uint4*)(pAl + o); pre[1][1] = *(const uint4*)(pAl + o + 8); \
        pre[2][0] = *(const uint4*)(pBh + o); pre[2][1] = *(const uint4*)(pBh + o + 8); \
        pre[3][0] = *(const uint4*)(pBl + o); pre[3][1] = *(const uint4*)(pBl + o + 8); } while (0)

    LD_PRE(0);

    for (int kc = 0; kc < Dm / BK; kc++) {
        __syncthreads();   // previous MMAs done reading smem
        *(uint4*)((char*)Ahs + sbyte)      = pre[0][0];
        *(uint4*)((char*)Ahs + sbyte + 16) = pre[0][1];
        *(uint4*)((char*)Als + sbyte)      = pre[1][0];
        *(uint4*)((char*)Als + sbyte + 16) = pre[1][1];
        *(uint4*)((char*)Bhs + sbyte)      = pre[2][0];
        *(uint4*)((char*)Bhs + sbyte + 16) = pre[2][1];
        *(uint4*)((char*)Bls + sbyte)      = pre[3][0];
        *(uint4*)((char*)Bls + sbyte + 16) = pre[3][1];
        __syncthreads();
        if (kc + 1 < Dm / BK) LD_PRE(kc + 1);   // overlap LDG with MMAs below

#pragma unroll
        for (int ks = 0; ks < BK; ks += 16) {
            uint32_t bh_[4][2], bl_[4][2];
            const uint32_t brow = (uint32_t)(wn * 32 + (lane & 7));
            const uint32_t bk_  = (uint32_t)(ks + ((lane >> 3) & 1) * 8);
#pragma unroll
            for (int an = 0; an < 4; an++) {
                const uint32_t off = ((brow + an * 8) * LDK + bk_) * 2;
                ldsm_x2(bh_[an], bB + off);
                ldsm_x2(bl_[an], blB + off);
            }
            const uint32_t arow = (uint32_t)(wm * 64 + (lane & 15));
            const uint32_t ak_  = (uint32_t)(ks + (lane >> 4) * 8);
#pragma unroll
            for (int am = 0; am < 4; am++) {
                uint32_t ah_[4], al_[4];
                const uint32_t off = ((arow + am * 16) * LDK + ak_) * 2;
                ldsm_x4(ah_, aB + off);
                ldsm_x4(al_, alB + off);
#pragma unroll
                for (int an = 0; an < 4; an++) {
                    mma_bf16(acc[am][an], ah_, bh_[an]);
                    mma_bf16(acc[am][an], ah_, bl_[an]);
                    mma_bf16(acc[am][an], al_, bh_[an]);
                }
            }
        }
    }
#undef LD_PRE

    // Epilogue: c0/c1 -> (row, col..col+1), c2/c3 -> row+8.
    const int fr = lane >> 2;
    const int fc = (lane & 3) << 1;
#pragma unroll
    for (int am = 0; am < 4; am++) {
        const int m0 = bm + wm * 64 + am * 16 + fr;
#pragma unroll
        for (int an = 0; an < 4; an++) {
            const int c = bn + wn * 32 + an * 8 + fc;
            const float b0 = bias[c], b1 = bias[c + 1];
#pragma unroll
            for (int half = 0; half < 2; half++) {
                const int m = m0 + half * 8;
                float y0 = acc[am][an][2 * half]     + b0;
                float y1 = acc[am][an][2 * half + 1] + b1;
                if (MODE == 1) {
                    y0 = (y0 > 0.f) ? (y0 + 1.f) : __expf(y0);
                    y1 = (y1 > 0.f) ? (y1 + 1.f) : __expf(y1);
                }
                float* dst;
                if (MODE == 0) {
                    dst = out + (size_t)m * Dm + c;
                } else {
                    const int b  = m >> 12;
                    const int s  = m & 4095;
                    const int h  = c >> 6;
                    const int e0 = c & 63;
                    dst = out + ((size_t)(b * Hn + h) * Sq + s) * Hd + e0;
                }
                *(float2*)dst = make_float2(y0, y1);
            }
        }
    }
}

// ---------------------------------------------------------------------------
// Per-chunk partials: Sp[bh][c][d][e] = sum_t k[t,d] v[t,e];  zp = sum_t k
// ---------------------------------------------------------------------------
__global__ void __launch_bounds__(256)
chunk_kv_k()
{
    __shared__ __align__(16) float ks[64 * Hd];
    __shared__ __align__(16) float vs[64 * Hd];
    const int c   = blockIdx.x;
    const int bh  = blockIdx.y;
    const int tid = threadIdx.x;
    const size_t base = ((size_t)bh * Sq + (size_t)c * Ck) * Hd;

    const int r  = tid & 63;
    const int j0 = (tid >> 6) << 4;

    float acc[16];
#pragma unroll
    for (int j = 0; j < 16; j++) acc[j] = 0.f;
    float zacc = 0.f;

    for (int half = 0; half < 2; half++) {
        const float4* kg = (const float4*)(g_k + base + (size_t)half * 64 * Hd);
        const float4* vg = (const float4*)(g_v + base + (size_t)half * 64 * Hd);
        __syncthreads();
        for (int i = tid; i < 64 * Hd / 4; i += 256) {
            ((float4*)ks)[i] = kg[i];
            ((float4*)vs)[i] = vg[i];
        }
        __syncthreads();
        for (int t = 0; t < 64; t++) {
            const float kv = ks[t * Hd + r];
            zacc += kv;
#pragma unroll
            for (int j = 0; j < 16; j++)
                acc[j] = fmaf(kv, vs[t * Hd + j0 + j], acc[j]);
        }
    }

    float* Sd = g_Sp + ((size_t)bh * Nch + c) * (Hd * Hd) + r * Hd + j0;
#pragma unroll
    for (int j = 0; j < 16; j++) Sd[j] = acc[j];
    if (tid < Hd) g_zp[((size_t)bh * Nch + c) * Hd + tid] = zacc;
}

// ---------------------------------------------------------------------------
__global__ void __launch_bounds__(256)
scan_k()
{
    const int bh = blockIdx.x;
    float* Sb = g_Sp + (size_t)bh * Nch * Hd * Hd;
    for (int e = threadIdx.x; e < Hd * Hd; e += 256) {
        float acc = 0.f;
        for (int c2 = 0; c2 < Nch; c2++) {
            const float v = Sb[(size_t)c2 * Hd * Hd + e];
            Sb[(size_t)c2 * Hd * Hd + e] = acc;
            acc += v;
        }
    }
    if (threadIdx.x < Hd) {
        float* zb = g_zp + (size_t)bh * Nch * Hd + threadIdx.x;
        float acc = 0.f;
        for (int c2 = 0; c2 < Nch; c2++) {
            const float v = zb[(size_t)c2 * Hd];
            zb[(size_t)c2 * Hd] = acc;
            acc += v;
        }
    }
}

// ---------------------------------------------------------------------------
// Masked score tiles. grid (4, Nch, BHn). Tile 3 = fully masked -> zeros.
// ---------------------------------------------------------------------------
__global__ void __launch_bounds__(256)
attn_scores_k()
{
    __shared__ __align__(16) float qT[64][68];
    __shared__ __align__(16) float kT[64][68];
    const int tile = blockIdx.x;
    const int c    = blockIdx.y;
    const int bh   = blockIdx.z;
    const int tid  = threadIdx.x;

    const int lt0 = (tid >> 4) << 2;
    const int lu0 = (tid & 15) << 2;

    if (tile == 3) {
        float* dst = g_sc + (((size_t)bh * Nch + c) * Ck + lt0) * Ck + 64 + lu0;
#pragma unroll
        for (int i = 0; i < 4; i++)
            *(float4*)(dst + (size_t)i * Ck) = make_float4(0.f, 0.f, 0.f, 0.f);
        return;
    }

    const int th = (tile == 0) ? 0 : 1;
    const int uh = (tile == 2) ? 1 : 0;

    const size_t qbase = ((size_t)bh * Sq + (size_t)c * Ck + th * 64) * Hd;
    const size_t kbase = ((size_t)bh * Sq + (size_t)c * Ck + uh * 64) * Hd;

    for (int i = tid; i < 64 * Hd; i += 256) {
        const int t = i >> 6, d = i & 63;
        qT[d][t] = g_q[qbase + i];
        kT[d][t] = g_k[kbase + i];
    }
    __syncthreads();

    float acc[4][4];
#pragma unroll
    for (int i = 0; i < 4; i++)
#pragma unroll
        for (int j = 0; j < 4; j++) acc[i][j] = 0.f;

    for (int d = 0; d < Hd; d++) {
        float a[4], b[4];
        *(float4*)a = *(const float4*)&qT[d][lt0];
        *(float4*)b = *(const float4*)&kT[d][lu0];
#pragma unroll
        for (int i = 0; i < 4; i++)
#pragma unroll
            for (int j = 0; j < 4; j++)
                acc[i][j] = fmaf(a[i], b[j], acc[i][j]);
    }

    const int tg0 = th * 64 + lt0;
    const int ug0 = uh * 64 + lu0;
    float* dst = g_sc + (((size_t)bh * Nch + c) * Ck + tg0) * Ck + ug0;
#pragma unroll
    for (int i = 0; i < 4; i++) {
        float y[4];
#pragma unroll
        for (int j = 0; j < 4; j++)
            y[j] = (ug0 + j <= tg0 + i) ? acc[i][j] : 0.f;
        *(float4*)(dst + (size_t)i * Ck) = make_float4(y[0], y[1], y[2], y[3]);
    }
}

// ---------------------------------------------------------------------------
// Per-chunk output (f32x2). Writes bf16 hi/lo att for the output GEMM.
// ---------------------------------------------------------------------------
__global__ void __launch_bounds__(256)
attn_out2_k()
{
    __shared__ __align__(16) float vs[Ck][Hd];
    __shared__ __align__(16) float Sx[Hd][Hd];

    const int c   = blockIdx.x;
    const int bh  = blockIdx.y;
    const int tid = threadIdx.x;
    const size_t base = ((size_t)bh * Sq + (size_t)c * Ck) * Hd;

    {
        const float4* vg = (const float4*)(g_v + base);
        for (int i = tid; i < Ck * Hd / 4; i += 256) ((float4*)vs)[i] = vg[i];
        const float4* sg = (const float4*)(g_Sp + ((size_t)bh * Nch + c) * (Hd * Hd));
        for (int i = tid; i < Hd * Hd / 4; i += 256) ((float4*)Sx)[i] = sg[i];
    }
    __syncthreads();

    const int e0 = (tid & 7) << 3;
    const int t0 = (tid >> 3) << 2;

    u64 num2[4][4];
    float rs[4], qz[4];
#pragma unroll
    for (int i = 0; i < 4; i++) {
        rs[i] = 0.f; qz[i] = 0.f;
#pragma unroll
        for (int j = 0; j < 4; j++) num2[i][j] = 0ULL;
    }

    const float* scb = g_sc + ((size_t)bh * Nch + c) * Ck * Ck;
    for (int u4 = 0; u4 < Ck; u4 += 4) {
        float4 sv4[4];
#pragma unroll
        for (int i = 0; i < 4; i++)
            sv4[i] = *(const float4*)&scb[(size_t)(t0 + i) * Ck + u4];
#pragma unroll
        for (int uu = 0; uu < 4; uu++) {
            const int u = u4 + uu;
            const ulonglong2 v01 = *(const ulonglong2*)&vs[u][e0];
            const ulonglong2 v23 = *(const ulonglong2*)&vs[u][e0 + 4];
            const u64 vv2[4] = {v01.x, v01.y, v23.x, v23.y};
#pragma unroll
            for (int i = 0; i < 4; i++) {
                const float* sp = (const float*)&sv4[i];
                const float s = sp[uu];
                rs[i] += s;
                const u64 s2 = pack2(s);
#pragma unroll
                for (int j = 0; j < 4; j++)
                    num2[i][j] = ffma2(s2, vv2[j], num2[i][j]);
            }
        }
    }

    const float* qb = g_q + base;
    const float* zb = g_zp + ((size_t)bh * Nch + c) * Hd;
    for (int d4 = 0; d4 < Hd; d4 += 4) {
        float4 qv4[4];
#pragma unroll
        for (int i = 0; i < 4; i++)
            qv4[i] = *(const float4*)&qb[(size_t)(t0 + i) * Hd + d4];
        const float4 z4 = *(const float4*)&zb[d4];
        const float* zp4 = (const float*)&z4;
#pragma unroll
        for (int dd = 0; dd < 4; dd++) {
            const int d = d4 + dd;
            const float zc = zp4[dd];
            const ulonglong2 s01 = *(const ulonglong2*)&Sx[d][e0];
            const ulonglong2 s23 = *(const ulonglong2*)&Sx[d][e0 + 4];
            const u64 sx2[4] = {s01.x, s01.y, s23.x, s23.y};
#pragma unroll
            for (int i = 0; i < 4; i++) {
                const float* qp = (const float*)&qv4[i];
                const float qv = qp[dd];
                qz[i] = fmaf(qv, zc, qz[i]);
                const u64 q2 = pack2(qv);
#pragma unroll
                for (int j = 0; j < 4; j++)
                    num2[i][j] = ffma2(q2, sx2[j], num2[i][j]);
            }
        }
    }

    const int b = bh >> 4, h = bh & 15;
    const size_t obase = ((size_t)b * Sq + (size_t)c * Ck) * Dm + h * Hd + e0;
#pragma unroll
    for (int i = 0; i < 4; i++) {
        const float inv = 1.0f / (rs[i] + qz[i]);
        float y[8];
#pragma unroll
        for (int j = 0; j < 4; j++) unpack2(num2[i][j], y[2 * j], y[2 * j + 1]);
        uint4 hi, lo;
        cvt8(make_float4(y[0] * inv, y[1] * inv, y[2] * inv, y[3] * inv),
             make_float4(y[4] * inv, y[5] * inv, y[6] * inv, y[7] * inv), hi, lo);
        *(uint4*)(g_ath + obase + (size_t)(t0 + i) * Dm) = hi;
        *(uint4*)(g_atl + obase + (size_t)(t0 + i) * Dm) = lo;
    }
}

// ---------------------------------------------------------------------------
extern "C" void kernel_launch(void* const* d_in, const int* in_sizes, int n_in,
                              void* d_out, int out_size)
{
    // Size-based input resolution (identity under expected metadata order).
    const float* x = nullptr;
    const float* Ws[4] = {nullptr, nullptr, nullptr, nullptr};
    const float* bs[4] = {nullptr, nullptr, nullptr, nullptr};
    int wi = 0, bi = 0;
    for (int i = 0; i < n_in; i++) {
        const int sz = in_sizes[i];
        if (sz == Mtot * Dm)      { x = (const float*)d_in[i]; }
        else if (sz == DD)        { if (wi < 4) Ws[wi++] = (const float*)d_in[i]; }
        else if (sz == Dm)        { if (bi < 4) bs[bi++] = (const float*)d_in[i]; }
    }
    float* out = (float*)d_out;

    // TRUE device addresses (never pass __device__ symbols from host — ATS!)
    float *pq, *pk, *pv;
    uint16_t *pxh, *pxl, *pwh, *pwl, *path, *patl;
    cudaGetSymbolAddress((void**)&pq,   g_q);
    cudaGetSymbolAddress((void**)&pk,   g_k);
    cudaGetSymbolAddress((void**)&pv,   g_v);
    cudaGetSymbolAddress((void**)&pxh,  g_xh);
    cudaGetSymbolAddress((void**)&pxl,  g_xl);
    cudaGetSymbolAddress((void**)&pwh,  g_wh);
    cudaGetSymbolAddress((void**)&pwl,  g_wl);
    cudaGetSymbolAddress((void**)&path, g_ath);
    cudaGetSymbolAddress((void**)&patl, g_atl);

    // Pre-convert operands to bf16 hi/lo (once).
    cvt_split_k<<<4096, 256>>>(x, pxh, pxl, Mtot * Dm / 8);
    for (int i = 0; i < 4; i++)
        cvt_split_k<<<512, 256>>>(Ws[i], pwh + (size_t)i * DD, pwl + (size_t)i * DD, DD / 8);

    const dim3 gg(Dm / 128, Mtot / 128);   // (8, 128)
    bf_gemm_k<1><<<gg, 256>>>(pxh, pxl, pwh + 0 * (size_t)DD, pwl + 0 * (size_t)DD, bs[0], pq);
    bf_gemm_k<1><<<gg, 256>>>(pxh, pxl, pwh + 1 * (size_t)DD, pwl + 1 * (size_t)DD, bs[1], pk);
    bf_gemm_k<2><<<gg, 256>>>(pxh, pxl, pwh + 2 * (size_t)DD, pwl + 2 * (size_t)DD, bs[2], pv);

    chunk_kv_k<<<dim3(Nch, BHn), 256>>>();
    scan_k<<<BHn, 256>>>();
    attn_scores_k<<<dim3(4, Nch, BHn), 256>>>();
    attn_out2_k<<<dim3(Nch, BHn), 256>>>();

    bf_gemm_k<0><<<gg, 256>>>(path, patl, pwh + 3 * (size_t)DD, pwl + 3 * (size_t)DD, bs[3], out);
}

// round 10
// speedup vs baseline: 1.1682x; 1.1682x over previous
#include <cuda_runtime.h>
#include <cstdint>

// ---------------------------------------------------------------------------
// LinearMultiheadAttention: x:(4,4096,1024), 16 heads x 64 dim, chunk 128.
// R10: pre-split bf16 GEMM with cp.async double-buffered pipeline (no register
// prefetch -> no spills). Attention mid-section unchanged (R8/R9-verified).
// RULE: __device__ symbols passed as kernel args MUST go through
// cudaGetSymbolAddress (GB300 ATS makes the host-shadow silently writable).
// ---------------------------------------------------------------------------

typedef unsigned long long u64;

// ---------------- f32x2 helpers ----------------
__device__ __forceinline__ u64 pack2(float x) {
    u64 r; asm("mov.b64 %0, {%1, %1};" : "=l"(r) : "f"(x)); return r;
}
__device__ __forceinline__ u64 ffma2(u64 a, u64 b, u64 c) {
    u64 d; asm("fma.rn.f32x2 %0, %1, %2, %3;" : "=l"(d) : "l"(a), "l"(b), "l"(c)); return d;
}
__device__ __forceinline__ void unpack2(u64 v, float& lo, float& hi) {
    asm("mov.b64 {%0, %1}, %2;" : "=f"(lo), "=f"(hi) : "l"(v));
}

// ---------------- tensor-core helpers (sm_80 baseline ISA) ----------------
__device__ __forceinline__ uint32_t smem_u32(const void* p) {
    return (uint32_t)__cvta_generic_to_shared(p);
}
__device__ __forceinline__ void ldsm_x4(uint32_t* r, uint32_t addr) {
    asm volatile("ldmatrix.sync.aligned.m8n8.x4.shared.b16 {%0,%1,%2,%3}, [%4];"
                 : "=r"(r[0]), "=r"(r[1]), "=r"(r[2]), "=r"(r[3]) : "r"(addr));
}
__device__ __forceinline__ void ldsm_x2(uint32_t* r, uint32_t addr) {
    asm volatile("ldmatrix.sync.aligned.m8n8.x2.shared.b16 {%0,%1}, [%2];"
                 : "=r"(r[0]), "=r"(r[1]) : "r"(addr));
}
__device__ __forceinline__ void mma_bf16(float* c, const uint32_t* a, const uint32_t* b) {
    asm volatile(
        "mma.sync.aligned.m16n8k16.row.col.f32.bf16.bf16.f32 "
        "{%0,%1,%2,%3}, {%4,%5,%6,%7}, {%8,%9}, {%0,%1,%2,%3};"
        : "+f"(c[0]), "+f"(c[1]), "+f"(c[2]), "+f"(c[3])
        : "r"(a[0]), "r"(a[1]), "r"(a[2]), "r"(a[3]), "r"(b[0]), "r"(b[1]));
}
__device__ __forceinline__ void cp_async16(uint32_t smem, const void* g) {
    asm volatile("cp.async.cg.shared.global [%0], [%1], 16;" :: "r"(smem), "l"(g));
}
__device__ __forceinline__ void cp_commit() {
    asm volatile("cp.async.commit_group;" ::: "memory");
}
__device__ __forceinline__ void cp_wait0() {
    asm volatile("cp.async.wait_group 0;" ::: "memory");
}
// 8 fp32 -> 8 bf16 hi (16B) + 8 bf16 lo (16B); element order preserved.
__device__ __forceinline__ void cvt8(const float4 f0, const float4 f1,
                                     uint4& hi, uint4& lo)
{
    const float a[8] = {f0.x, f0.y, f0.z, f0.w, f1.x, f1.y, f1.z, f1.w};
    uint32_t h[4], l[4];
#pragma unroll
    for (int i = 0; i < 4; i++) {
        asm("cvt.rn.bf16x2.f32 %0, %1, %2;" : "=r"(h[i]) : "f"(a[2*i+1]), "f"(a[2*i]));
        const float flo = __uint_as_float(h[i] << 16);
        const float fhi = __uint_as_float(h[i] & 0xFFFF0000u);
        asm("cvt.rn.bf16x2.f32 %0, %1, %2;" : "=r"(l[i]) : "f"(a[2*i+1] - fhi), "f"(a[2*i] - flo));
    }
    hi = make_uint4(h[0], h[1], h[2], h[3]);
    lo = make_uint4(l[0], l[1], l[2], l[3]);
}

constexpr int Bn   = 4;
constexpr int Sq   = 4096;
constexpr int Dm   = 1024;
constexpr int Hn   = 16;
constexpr int Hd   = 64;
constexpr int Mtot = Bn * Sq;     // 16384
constexpr int Ck   = 128;
constexpr int Nch  = Sq / Ck;     // 32
constexpr int BHn  = Bn * Hn;     // 64
constexpr int DD   = Dm * Dm;

__device__ __align__(16) float g_q[(size_t)Mtot * Dm];
__device__ __align__(16) float g_k[(size_t)Mtot * Dm];
__device__ __align__(16) float g_v[(size_t)Mtot * Dm];
__device__ __align__(16) float g_Sp[(size_t)BHn * Nch * Hd * Hd];
__device__ __align__(16) float g_zp[(size_t)BHn * Nch * Hd];
__device__ __align__(16) float g_sc[(size_t)BHn * Nch * Ck * Ck];
// bf16 hi/lo operands
__device__ __align__(16) uint16_t g_xh[(size_t)Mtot * Dm];
__device__ __align__(16) uint16_t g_xl[(size_t)Mtot * Dm];
__device__ __align__(16) uint16_t g_wh[(size_t)4 * DD];
__device__ __align__(16) uint16_t g_wl[(size_t)4 * DD];
__device__ __align__(16) uint16_t g_ath[(size_t)Mtot * Dm];
__device__ __align__(16) uint16_t g_atl[(size_t)Mtot * Dm];

// ---------------------------------------------------------------------------
// fp32 -> bf16 hi/lo split, 8 elems/thread, grid-stride.
// ---------------------------------------------------------------------------
__global__ void __launch_bounds__(256)
cvt_split_k(const float* __restrict__ src, uint16_t* __restrict__ hi,
            uint16_t* __restrict__ lo, int n8)
{
    int i = blockIdx.x * blockDim.x + threadIdx.x;
    const int stride = gridDim.x * blockDim.x;
    for (; i < n8; i += stride) {
        const float4 f0 = ((const float4*)src)[2 * i];
        const float4 f1 = ((const float4*)src)[2 * i + 1];
        uint4 h, l;
        cvt8(f0, f1, h, l);
        ((uint4*)hi)[i] = h;
        ((uint4*)lo)[i] = l;
    }
}

// ---------------------------------------------------------------------------
// HMMA GEMM on pre-split bf16: Y = A.W^T + bias (logical fp32 via 3 MMAs).
// MODE 0: plain store | MODE 1: phi + permuted [bh][s][hd] | MODE 2: permuted
// 128x128 tile, BK=32, 8 warps (2m x 4n), cp.async 2-stage pipeline.
// ---------------------------------------------------------------------------
constexpr int BK  = 32;
constexpr int LDK = 40;                       // padded smem row (80B stride)
constexpr int TILE_B  = 128 * LDK * 2;        // 10240 bytes per matrix tile
constexpr int STAGE_B = 4 * TILE_B;           // 40960 bytes per stage
constexpr int GEMM_DSMEM = 2 * STAGE_B;       // 81920 bytes

template <int MODE>
__global__ void __launch_bounds__(256)
bf_gemm_k(const uint16_t* __restrict__ Ah_g, const uint16_t* __restrict__ Al_g,
          const uint16_t* __restrict__ Bh_g, const uint16_t* __restrict__ Bl_g,
          const float* __restrict__ bias, float* __restrict__ out)
{
    extern __shared__ __align__(16) uint16_t dsm[];
    const uint32_t sbase = smem_u32(dsm);

    const int tid  = threadIdx.x;
    const int lane = tid & 31;
    const int wid  = tid >> 5;
    const int wm   = wid >> 2;
    const int wn   = wid & 3;
    const int bm   = blockIdx.y << 7;
    const int bn   = blockIdx.x << 7;

    const int lrow  = tid >> 1;
    const int lhalf = (tid & 1) << 4;   // 0 or 16 (bf16 elems)
    const uint16_t* pAh = Ah_g + (size_t)(bm + lrow) * Dm + lhalf;
    const uint16_t* pAl = Al_g + (size_t)(bm + lrow) * Dm + lhalf;
    const uint16_t* pBh = Bh_g + (size_t)(bn + lrow) * Dm + lhalf;
    const uint16_t* pBl = Bl_g + (size_t)(bn + lrow) * Dm + lhalf;
    const uint32_t sbyte = (uint32_t)(lrow * LDK + lhalf) * 2;

    float acc[4][4][4];
#pragma unroll
    for (int i = 0; i < 4; i++)
#pragma unroll
        for (int j = 0; j < 4; j++)
#pragma unroll
            for (int r = 0; r < 4; r++) acc[i][j][r] = 0.f;

#define ISSUE(stage, kc) do {                                                  \
        const uint32_t s0 = sbase + (stage) * STAGE_B + sbyte;                 \
        const size_t go = (size_t)(kc) * BK;                                   \
        cp_async16(s0,                 pAh + go);                              \
        cp_async16(s0 + 16,            pAh + go + 8);                          \
        cp_async16(s0 + TILE_B,        pAl + go);                              \
        cp_async16(s0 + TILE_B + 16,   pAl + go + 8);                          \
        cp_async16(s0 + 2*TILE_B,      pBh + go);                              \
        cp_async16(s0 + 2*TILE_B + 16, pBh + go + 8);                          \
        cp_async16(s0 + 3*TILE_B,      pBl + go);                              \
        cp_async16(s0 + 3*TILE_B + 16, pBl + go + 8);                          \
        cp_commit();                                                           \
    } while (0)

    constexpr int NK = Dm / BK;   // 32
    ISSUE(0, 0);

    for (int kc = 0; kc < NK; kc++) {
        cp_wait0();
        __syncthreads();          // stage kc ready; all prior MMAs drained
        if (kc + 1 < NK) ISSUE((kc + 1) & 1, kc + 1);   // overlaps MMAs below

        const uint32_t st  = sbase + (kc & 1) * STAGE_B;
        const uint32_t aB  = st;
        const uint32_t alB = st + TILE_B;
        const uint32_t bB  = st + 2 * TILE_B;
        const uint32_t blB = st + 3 * TILE_B;

#pragma unroll
        for (int ks = 0; ks < BK; ks += 16) {
            uint32_t bh_[4][2], bl_[4][2];
            const uint32_t brow = (uint32_t)(wn * 32 + (lane & 7));
            const uint32_t bk_  = (uint32_t)(ks + ((lane >> 3) & 1) * 8);
#pragma unroll
            for (int an = 0; an < 4; an++) {
                const uint32_t off = ((brow + an * 8) * LDK + bk_) * 2;
                ldsm_x2(bh_[an], bB + off);
                ldsm_x2(bl_[an], blB + off);
            }
            const uint32_t arow = (uint32_t)(wm * 64 + (lane & 15));
            const uint32_t ak_  = (uint32_t)(ks + (lane >> 4) * 8);
#pragma unroll
            for (int am = 0; am < 4; am++) {
                uint32_t ah_[4], al_[4];
                const uint32_t off = ((arow + am * 16) * LDK + ak_) * 2;
                ldsm_x4(ah_, aB + off);
                ldsm_x4(al_, alB + off);
#pragma unroll
                for (int an = 0; an < 4; an++) {
                    mma_bf16(acc[am][an], ah_, bh_[an]);
                    mma_bf16(acc[am][an], ah_, bl_[an]);
                    mma_bf16(acc[am][an], al_, bh_[an]);
                }
            }
        }
    }
#undef ISSUE

    // Epilogue: c0/c1 -> (row, col..col+1), c2/c3 -> row+8.
    const int fr = lane >> 2;
    const int fc = (lane & 3) << 1;
#pragma unroll
    for (int am = 0; am < 4; am++) {
        const int m0 = bm + wm * 64 + am * 16 + fr;
#pragma unroll
        for (int an = 0; an < 4; an++) {
            const int c = bn + wn * 32 + an * 8 + fc;
            const float b0 = bias[c], b1 = bias[c + 1];
#pragma unroll
            for (int half = 0; half < 2; half++) {
                const int m = m0 + half * 8;
                float y0 = acc[am][an][2 * half]     + b0;
                float y1 = acc[am][an][2 * half + 1] + b1;
                if (MODE == 1) {
                    y0 = (y0 > 0.f) ? (y0 + 1.f) : __expf(y0);
                    y1 = (y1 > 0.f) ? (y1 + 1.f) : __expf(y1);
                }
                float* dst;
                if (MODE == 0) {
                    dst = out + (size_t)m * Dm + c;
                } else {
                    const int b  = m >> 12;
                    const int s  = m & 4095;
                    const int h  = c >> 6;
                    const int e0 = c & 63;
                    dst = out + ((size_t)(b * Hn + h) * Sq + s) * Hd + e0;
                }
                *(float2*)dst = make_float2(y0, y1);
            }
        }
    }
}

// ---------------------------------------------------------------------------
// Per-chunk partials: Sp[bh][c][d][e] = sum_t k[t,d] v[t,e];  zp = sum_t k
// ---------------------------------------------------------------------------
__global__ void __launch_bounds__(256)
chunk_kv_k()
{
    __shared__ __align__(16) float ks[64 * Hd];
    __shared__ __align__(16) float vs[64 * Hd];
    const int c   = blockIdx.x;
    const int bh  = blockIdx.y;
    const int tid = threadIdx.x;
    const size_t base = ((size_t)bh * Sq + (size_t)c * Ck) * Hd;

    const int r  = tid & 63;
    const int j0 = (tid >> 6) << 4;

    float acc[16];
#pragma unroll
    for (int j = 0; j < 16; j++) acc[j] = 0.f;
    float zacc = 0.f;

    for (int half = 0; half < 2; half++) {
        const float4* kg = (const float4*)(g_k + base + (size_t)half * 64 * Hd);
        const float4* vg = (const float4*)(g_v + base + (size_t)half * 64 * Hd);
        __syncthreads();
        for (int i = tid; i < 64 * Hd / 4; i += 256) {
            ((float4*)ks)[i] = kg[i];
            ((float4*)vs)[i] = vg[i];
        }
        __syncthreads();
        for (int t = 0; t < 64; t++) {
            const float kv = ks[t * Hd + r];
            zacc += kv;
#pragma unroll
            for (int j = 0; j < 16; j++)
                acc[j] = fmaf(kv, vs[t * Hd + j0 + j], acc[j]);
        }
    }

    float* Sd = g_Sp + ((size_t)bh * Nch + c) * (Hd * Hd) + r * Hd + j0;
#pragma unroll
    for (int j = 0; j < 16; j++) Sd[j] = acc[j];
    if (tid < Hd) g_zp[((size_t)bh * Nch + c) * Hd + tid] = zacc;
}

// ---------------------------------------------------------------------------
__global__ void __launch_bounds__(256)
scan_k()
{
    const int bh = blockIdx.x;
    float* Sb = g_Sp + (size_t)bh * Nch * Hd * Hd;
    for (int e = threadIdx.x; e < Hd * Hd; e += 256) {
        float acc = 0.f;
        for (int c2 = 0; c2 < Nch; c2++) {
            const float v = Sb[(size_t)c2 * Hd * Hd + e];
            Sb[(size_t)c2 * Hd * Hd + e] = acc;
            acc += v;
        }
    }
    if (threadIdx.x < Hd) {
        float* zb = g_zp + (size_t)bh * Nch * Hd + threadIdx.x;
        float acc = 0.f;
        for (int c2 = 0; c2 < Nch; c2++) {
            const float v = zb[(size_t)c2 * Hd];
            zb[(size_t)c2 * Hd] = acc;
            acc += v;
        }
    }
}

// ---------------------------------------------------------------------------
// Masked score tiles. grid (4, Nch, BHn). Tile 3 = fully masked -> zeros.
// ---------------------------------------------------------------------------
__global__ void __launch_bounds__(256)
attn_scores_k()
{
    __shared__ __align__(16) float qT[64][68];
    __shared__ __align__(16) float kT[64][68];
    const int tile = blockIdx.x;
    const int c    = blockIdx.y;
    const int bh   = blockIdx.z;
    const int tid  = threadIdx.x;

    const int lt0 = (tid >> 4) << 2;
    const int lu0 = (tid & 15) << 2;

    if (tile == 3) {
        float* dst = g_sc + (((size_t)bh * Nch + c) * Ck + lt0) * Ck + 64 + lu0;
#pragma unroll
        for (int i = 0; i < 4; i++)
            *(float4*)(dst + (size_t)i * Ck) = make_float4(0.f, 0.f, 0.f, 0.f);
        return;
    }

    const int th = (tile == 0) ? 0 : 1;
    const int uh = (tile == 2) ? 1 : 0;

    const size_t qbase = ((size_t)bh * Sq + (size_t)c * Ck + th * 64) * Hd;
    const size_t kbase = ((size_t)bh * Sq + (size_t)c * Ck + uh * 64) * Hd;

    for (int i = tid; i < 64 * Hd; i += 256) {
        const int t = i >> 6, d = i & 63;
        qT[d][t] = g_q[qbase + i];
        kT[d][t] = g_k[kbase + i];
    }
    __syncthreads();

    float acc[4][4];
#pragma unroll
    for (int i = 0; i < 4; i++)
#pragma unroll
        for (int j = 0; j < 4; j++) acc[i][j] = 0.f;

    for (int d = 0; d < Hd; d++) {
        float a[4], b[4];
        *(float4*)a = *(const float4*)&qT[d][lt0];
        *(float4*)b = *(const float4*)&kT[d][lu0];
#pragma unroll
        for (int i = 0; i < 4; i++)
#pragma unroll
            for (int j = 0; j < 4; j++)
                acc[i][j] = fmaf(a[i], b[j], acc[i][j]);
    }

    const int tg0 = th * 64 + lt0;
    const int ug0 = uh * 64 + lu0;
    float* dst = g_sc + (((size_t)bh * Nch + c) * Ck + tg0) * Ck + ug0;
#pragma unroll
    for (int i = 0; i < 4; i++) {
        float y[4];
#pragma unroll
        for (int j = 0; j < 4; j++)
            y[j] = (ug0 + j <= tg0 + i) ? acc[i][j] : 0.f;
        *(float4*)(dst + (size_t)i * Ck) = make_float4(y[0], y[1], y[2], y[3]);
    }
}

// ---------------------------------------------------------------------------
// Per-chunk output (f32x2). Writes bf16 hi/lo att for the output GEMM.
// ---------------------------------------------------------------------------
__global__ void __launch_bounds__(256)
attn_out2_k()
{
    __shared__ __align__(16) float vs[Ck][Hd];
    __shared__ __align__(16) float Sx[Hd][Hd];

    const int c   = blockIdx.x;
    const int bh  = blockIdx.y;
    const int tid = threadIdx.x;
    const size_t base = ((size_t)bh * Sq + (size_t)c * Ck) * Hd;

    {
        const float4* vg = (const float4*)(g_v + base);
        for (int i = tid; i < Ck * Hd / 4; i += 256) ((float4*)vs)[i] = vg[i];
        const float4* sg = (const float4*)(g_Sp + ((size_t)bh * Nch + c) * (Hd * Hd));
        for (int i = tid; i < Hd * Hd / 4; i += 256) ((float4*)Sx)[i] = sg[i];
    }
    __syncthreads();

    const int e0 = (tid & 7) << 3;
    const int t0 = (tid >> 3) << 2;

    u64 num2[4][4];
    float rs[4], qz[4];
#pragma unroll
    for (int i = 0; i < 4; i++) {
        rs[i] = 0.f; qz[i] = 0.f;
#pragma unroll
        for (int j = 0; j < 4; j++) num2[i][j] = 0ULL;
    }

    const float* scb = g_sc + ((size_t)bh * Nch + c) * Ck * Ck;
    for (int u4 = 0; u4 < Ck; u4 += 4) {
        float4 sv4[4];
#pragma unroll
        for (int i = 0; i < 4; i++)
            sv4[i] = *(const float4*)&scb[(size_t)(t0 + i) * Ck + u4];
#pragma unroll
        for (int uu = 0; uu < 4; uu++) {
            const int u = u4 + uu;
            const ulonglong2 v01 = *(const ulonglong2*)&vs[u][e0];
            const ulonglong2 v23 = *(const ulonglong2*)&vs[u][e0 + 4];
            const u64 vv2[4] = {v01.x, v01.y, v23.x, v23.y};
#pragma unroll
            for (int i = 0; i < 4; i++) {
                const float* sp = (const float*)&sv4[i];
                const float s = sp[uu];
                rs[i] += s;
                const u64 s2 = pack2(s);
#pragma unroll
                for (int j = 0; j < 4; j++)
                    num2[i][j] = ffma2(s2, vv2[j], num2[i][j]);
            }
        }
    }

    const float* qb = g_q + base;
    const float* zb = g_zp + ((size_t)bh * Nch + c) * Hd;
    for (int d4 = 0; d4 < Hd; d4 += 4) {
        float4 qv4[4];
#pragma unroll
        for (int i = 0; i < 4; i++)
            qv4[i] = *(const float4*)&qb[(size_t)(t0 + i) * Hd + d4];
        const float4 z4 = *(const float4*)&zb[d4];
        const float* zp4 = (const float*)&z4;
#pragma unroll
        for (int dd = 0; dd < 4; dd++) {
            const int d = d4 + dd;
            const float zc = zp4[dd];
            const ulonglong2 s01 = *(const ulonglong2*)&Sx[d][e0];
            const ulonglong2 s23 = *(const ulonglong2*)&Sx[d][e0 + 4];
            const u64 sx2[4] = {s01.x, s01.y, s23.x, s23.y};
#pragma unroll
            for (int i = 0; i < 4; i++) {
                const float* qp = (const float*)&qv4[i];
                const float qv = qp[dd];
                qz[i] = fmaf(qv, zc, qz[i]);
                const u64 q2 = pack2(qv);
#pragma unroll
                for (int j = 0; j < 4; j++)
                    num2[i][j] = ffma2(q2, sx2[j], num2[i][j]);
            }
        }
    }

    const int b = bh >> 4, h = bh & 15;
    const size_t obase = ((size_t)b * Sq + (size_t)c * Ck) * Dm + h * Hd + e0;
#pragma unroll
    for (int i = 0; i < 4; i++) {
        const float inv = 1.0f / (rs[i] + qz[i]);
        float y[8];
#pragma unroll
        for (int j = 0; j < 4; j++) unpack2(num2[i][j], y[2 * j], y[2 * j + 1]);
        uint4 hi, lo;
        cvt8(make_float4(y[0] * inv, y[1] * inv, y[2] * inv, y[3] * inv),
             make_float4(y[4] * inv, y[5] * inv, y[6] * inv, y[7] * inv), hi, lo);
        *(uint4*)(g_ath + obase + (size_t)(t0 + i) * Dm) = hi;
        *(uint4*)(g_atl + obase + (size_t)(t0 + i) * Dm) = lo;
    }
}

// ---------------------------------------------------------------------------
extern "C" void kernel_launch(void* const* d_in, const int* in_sizes, int n_in,
                              void* d_out, int out_size)
{
    // Size-based input resolution (identity under expected metadata order).
    const float* x = nullptr;
    const float* Ws[4] = {nullptr, nullptr, nullptr, nullptr};
    const float* bs[4] = {nullptr, nullptr, nullptr, nullptr};
    int wi = 0, bi = 0;
    for (int i = 0; i < n_in; i++) {
        const int sz = in_sizes[i];
        if (sz == Mtot * Dm)      { x = (const float*)d_in[i]; }
        else if (sz == DD)        { if (wi < 4) Ws[wi++] = (const float*)d_in[i]; }
        else if (sz == Dm)        { if (bi < 4) bs[bi++] = (const float*)d_in[i]; }
    }
    float* out = (float*)d_out;

    // TRUE device addresses (never pass __device__ symbols from host — ATS!)
    float *pq, *pk, *pv;
    uint16_t *pxh, *pxl, *pwh, *pwl, *path, *patl;
    cudaGetSymbolAddress((void**)&pq,   g_q);
    cudaGetSymbolAddress((void**)&pk,   g_k);
    cudaGetSymbolAddress((void**)&pv,   g_v);
    cudaGetSymbolAddress((void**)&pxh,  g_xh);
    cudaGetSymbolAddress((void**)&pxl,  g_xl);
    cudaGetSymbolAddress((void**)&pwh,  g_wh);
    cudaGetSymbolAddress((void**)&pwl,  g_wl);
    cudaGetSymbolAddress((void**)&path, g_ath);
    cudaGetSymbolAddress((void**)&patl, g_atl);

    // Opt-in to 80KB dynamic smem for the GEMMs (host-side attr, idempotent).
    cudaFuncSetAttribute(bf_gemm_k<0>, cudaFuncAttributeMaxDynamicSharedMemorySize, GEMM_DSMEM);
    cudaFuncSetAttribute(bf_gemm_k<1>, cudaFuncAttributeMaxDynamicSharedMemorySize, GEMM_DSMEM);
    cudaFuncSetAttribute(bf_gemm_k<2>, cudaFuncAttributeMaxDynamicSharedMemorySize, GEMM_DSMEM);

    // Pre-convert operands to bf16 hi/lo (once).
    cvt_split_k<<<4096, 256>>>(x, pxh, pxl, Mtot * Dm / 8);
    for (int i = 0; i < 4; i++)
        cvt_split_k<<<512, 256>>>(Ws[i], pwh + (size_t)i * DD, pwl + (size_t)i * DD, DD / 8);

    const dim3 gg(Dm / 128, Mtot / 128);   // (8, 128)
    bf_gemm_k<1><<<gg, 256, GEMM_DSMEM>>>(pxh, pxl, pwh + 0 * (size_t)DD, pwl + 0 * (size_t)DD, bs[0], pq);
    bf_gemm_k<1><<<gg, 256, GEMM_DSMEM>>>(pxh, pxl, pwh + 1 * (size_t)DD, pwl + 1 * (size_t)DD, bs[1], pk);
    bf_gemm_k<2><<<gg, 256, GEMM_DSMEM>>>(pxh, pxl, pwh + 2 * (size_t)DD, pwl + 2 * (size_t)DD, bs[2], pv);

    chunk_kv_k<<<dim3(Nch, BHn), 256>>>();
    scan_k<<<BHn, 256>>>();
    attn_scores_k<<<dim3(4, Nch, BHn), 256>>>();
    attn_out2_k<<<dim3(Nch, BHn), 256>>>();

    bf_gemm_k<0><<<gg, 256, GEMM_DSMEM>>>(path, patl, pwh + 3 * (size_t)DD, pwl + 3 * (size_t)DD, bs[3], out);
}

// round 12
// speedup vs baseline: 1.1891x; 1.0179x over previous
#include <cuda_runtime.h>
#include <cstdint>

// ---------------------------------------------------------------------------
// LinearMultiheadAttention: x:(4,4096,1024), 16 heads x 64 dim, chunk 128.
// R12 = R11 with the extern-shared type conflict fixed (single char dsm[]).
// Fused tensor-core attention (scores+output in one kernel, smem-resident
// bf16-split scores, no g_sc round-trip). Proj GEMMs emit q,k,v bf16 hi/lo.
// RULE: __device__ symbols passed as kernel args MUST go through
// cudaGetSymbolAddress (GB300 ATS makes the host-shadow silently writable).
// ---------------------------------------------------------------------------

// ---------------- tensor-core helpers (sm_80 baseline ISA) ----------------
__device__ __forceinline__ uint32_t smem_u32(const void* p) {
    return (uint32_t)__cvta_generic_to_shared(p);
}
__device__ __forceinline__ void ldsm_x4(uint32_t* r, uint32_t addr) {
    asm volatile("ldmatrix.sync.aligned.m8n8.x4.shared.b16 {%0,%1,%2,%3}, [%4];"
                 : "=r"(r[0]), "=r"(r[1]), "=r"(r[2]), "=r"(r[3]) : "r"(addr));
}
__device__ __forceinline__ void ldsm_x2(uint32_t* r, uint32_t addr) {
    asm volatile("ldmatrix.sync.aligned.m8n8.x2.shared.b16 {%0,%1}, [%2];"
                 : "=r"(r[0]), "=r"(r[1]) : "r"(addr));
}
__device__ __forceinline__ void ldsm_x2_t(uint32_t* r, uint32_t addr) {
    asm volatile("ldmatrix.sync.aligned.m8n8.x2.trans.shared.b16 {%0,%1}, [%2];"
                 : "=r"(r[0]), "=r"(r[1]) : "r"(addr));
}
__device__ __forceinline__ void mma_bf16(float* c, const uint32_t* a, const uint32_t* b) {
    asm volatile(
        "mma.sync.aligned.m16n8k16.row.col.f32.bf16.bf16.f32 "
        "{%0,%1,%2,%3}, {%4,%5,%6,%7}, {%8,%9}, {%0,%1,%2,%3};"
        : "+f"(c[0]), "+f"(c[1]), "+f"(c[2]), "+f"(c[3])
        : "r"(a[0]), "r"(a[1]), "r"(a[2]), "r"(a[3]), "r"(b[0]), "r"(b[1]));
}
__device__ __forceinline__ void cp_async16(uint32_t smem, const void* g) {
    asm volatile("cp.async.cg.shared.global [%0], [%1], 16;" :: "r"(smem), "l"(g));
}
__device__ __forceinline__ void cp_commit() {
    asm volatile("cp.async.commit_group;" ::: "memory");
}
__device__ __forceinline__ void cp_wait0() {
    asm volatile("cp.async.wait_group 0;" ::: "memory");
}
// fp32 pair -> bf16 hi pair (packed u32, elem0 low) + lo residual pair
__device__ __forceinline__ void cvt_pair(float y0, float y1, uint32_t& hi, uint32_t& lo)
{
    asm("cvt.rn.bf16x2.f32 %0, %1, %2;" : "=r"(hi) : "f"(y1), "f"(y0));
    const float f0 = __uint_as_float(hi << 16);
    const float f1 = __uint_as_float(hi & 0xFFFF0000u);
    asm("cvt.rn.bf16x2.f32 %0, %1, %2;" : "=r"(lo) : "f"(y1 - f1), "f"(y0 - f0));
}
__device__ __forceinline__ void cvt8(const float4 f0, const float4 f1,
                                     uint4& hi, uint4& lo)
{
    const float a[8] = {f0.x, f0.y, f0.z, f0.w, f1.x, f1.y, f1.z, f1.w};
    uint32_t h[4], l[4];
#pragma unroll
    for (int i = 0; i < 4; i++) cvt_pair(a[2*i], a[2*i+1], h[i], l[i]);
    hi = make_uint4(h[0], h[1], h[2], h[3]);
    lo = make_uint4(l[0], l[1], l[2], l[3]);
}
__device__ __forceinline__ float b2f(uint16_t b) {
    return __uint_as_float((uint32_t)b << 16);
}

constexpr int Bn   = 4;
constexpr int Sq   = 4096;
constexpr int Dm   = 1024;
constexpr int Hn   = 16;
constexpr int Hd   = 64;
constexpr int Mtot = Bn * Sq;     // 16384
constexpr int Ck   = 128;
constexpr int Nch  = Sq / Ck;     // 32
constexpr int BHn  = Bn * Hn;     // 64
constexpr int DD   = Dm * Dm;

__device__ __align__(16) float g_k[(size_t)Mtot * Dm];    // fp32 k (chunk_kv)
__device__ __align__(16) float g_v[(size_t)Mtot * Dm];    // fp32 v (chunk_kv)
__device__ __align__(16) float g_Sp[(size_t)BHn * Nch * Hd * Hd];
__device__ __align__(16) float g_zp[(size_t)BHn * Nch * Hd];
// bf16 hi/lo operands
__device__ __align__(16) uint16_t g_xh[(size_t)Mtot * Dm];
__device__ __align__(16) uint16_t g_xl[(size_t)Mtot * Dm];
__device__ __align__(16) uint16_t g_wh[(size_t)4 * DD];
__device__ __align__(16) uint16_t g_wl[(size_t)4 * DD];
__device__ __align__(16) uint16_t g_qh[(size_t)Mtot * Dm];
__device__ __align__(16) uint16_t g_ql[(size_t)Mtot * Dm];
__device__ __align__(16) uint16_t g_kh[(size_t)Mtot * Dm];
__device__ __align__(16) uint16_t g_kl[(size_t)Mtot * Dm];
__device__ __align__(16) uint16_t g_vh[(size_t)Mtot * Dm];
__device__ __align__(16) uint16_t g_vl[(size_t)Mtot * Dm];
__device__ __align__(16) uint16_t g_sph[(size_t)BHn * Nch * Hd * Hd];
__device__ __align__(16) uint16_t g_spl[(size_t)BHn * Nch * Hd * Hd];
__device__ __align__(16) uint16_t g_ath[(size_t)Mtot * Dm];
__device__ __align__(16) uint16_t g_atl[(size_t)Mtot * Dm];

// single extern-shared symbol shape for ALL kernels (nvcc: one type per TU)
// (declared inside kernels as: extern __shared__ char dsm[];)

// ---------------------------------------------------------------------------
// fp32 -> bf16 hi/lo split, 8 elems/thread, grid-stride.
// ---------------------------------------------------------------------------
__global__ void __launch_bounds__(256)
cvt_split_k(const float* __restrict__ src, uint16_t* __restrict__ hi,
            uint16_t* __restrict__ lo, int n8)
{
    int i = blockIdx.x * blockDim.x + threadIdx.x;
    const int stride = gridDim.x * blockDim.x;
    for (; i < n8; i += stride) {
        const float4 f0 = ((const float4*)src)[2 * i];
        const float4 f1 = ((const float4*)src)[2 * i + 1];
        uint4 h, l;
        cvt8(f0, f1, h, l);
        ((uint4*)hi)[i] = h;
        ((uint4*)lo)[i] = l;
    }
}

// ---------------------------------------------------------------------------
// HMMA GEMM on pre-split bf16: Y = A.W^T + bias (logical fp32 via 3 MMAs).
// MODE 0: fp32 plain | MODE 1: phi, split-only permuted | MODE 2: fp32+split
// permuted (v) | MODE 3: phi, fp32+split permuted (k).
// 128x128 tile, BK=32, 8 warps (2m x 4n), cp.async 2-stage pipeline.
// ---------------------------------------------------------------------------
constexpr int BK  = 32;
constexpr int LDK = 40;
constexpr int TILE_B  = 128 * LDK * 2;
constexpr int STAGE_B = 4 * TILE_B;
constexpr int GEMM_DSMEM = 2 * STAGE_B;       // 81920 bytes

template <int MODE>
__global__ void __launch_bounds__(256)
bf_gemm_k(const uint16_t* __restrict__ Ah_g, const uint16_t* __restrict__ Al_g,
          const uint16_t* __restrict__ Bh_g, const uint16_t* __restrict__ Bl_g,
          const float* __restrict__ bias, float* __restrict__ out,
          uint16_t* __restrict__ outh, uint16_t* __restrict__ outl)
{
    extern __shared__ char dsm[];
    const uint32_t sbase = smem_u32(dsm);

    const int tid  = threadIdx.x;
    const int lane = tid & 31;
    const int wid  = tid >> 5;
    const int wm   = wid >> 2;
    const int wn   = wid & 3;
    const int bm   = blockIdx.y << 7;
    const int bn   = blockIdx.x << 7;

    const int lrow  = tid >> 1;
    const int lhalf = (tid & 1) << 4;
    const uint16_t* pAh = Ah_g + (size_t)(bm + lrow) * Dm + lhalf;
    const uint16_t* pAl = Al_g + (size_t)(bm + lrow) * Dm + lhalf;
    const uint16_t* pBh = Bh_g + (size_t)(bn + lrow) * Dm + lhalf;
    const uint16_t* pBl = Bl_g + (size_t)(bn + lrow) * Dm + lhalf;
    const uint32_t sbyte = (uint32_t)(lrow * LDK + lhalf) * 2;

    float acc[4][4][4];
#pragma unroll
    for (int i = 0; i < 4; i++)
#pragma unroll
        for (int j = 0; j < 4; j++)
#pragma unroll
            for (int r = 0; r < 4; r++) acc[i][j][r] = 0.f;

#define ISSUE(stage, kc) do {                                                  \
        const uint32_t s0 = sbase + (stage) * STAGE_B + sbyte;                 \
        const size_t go = (size_t)(kc) * BK;                                   \
        cp_async16(s0,                 pAh + go);                              \
        cp_async16(s0 + 16,            pAh + go + 8);                          \
        cp_async16(s0 + TILE_B,        pAl + go);                              \
        cp_async16(s0 + TILE_B + 16,   pAl + go + 8);                          \
        cp_async16(s0 + 2*TILE_B,      pBh + go);                              \
        cp_async16(s0 + 2*TILE_B + 16, pBh + go + 8);                          \
        cp_async16(s0 + 3*TILE_B,      pBl + go);                              \
        cp_async16(s0 + 3*TILE_B + 16, pBl + go + 8);                          \
        cp_commit();                                                           \
    } while (0)

    constexpr int NK = Dm / BK;
    ISSUE(0, 0);

    for (int kc = 0; kc < NK; kc++) {
        cp_wait0();
        __syncthreads();
        if (kc + 1 < NK) ISSUE((kc + 1) & 1, kc + 1);

        const uint32_t st  = sbase + (kc & 1) * STAGE_B;
        const uint32_t aB  = st;
        const uint32_t alB = st + TILE_B;
        const uint32_t bB  = st + 2 * TILE_B;
        const uint32_t blB = st + 3 * TILE_B;

#pragma unroll
        for (int ks = 0; ks < BK; ks += 16) {
            uint32_t bh_[4][2], bl_[4][2];
            const uint32_t brow = (uint32_t)(wn * 32 + (lane & 7));
            const uint32_t bk_  = (uint32_t)(ks + ((lane >> 3) & 1) * 8);
#pragma unroll
            for (int an = 0; an < 4; an++) {
                const uint32_t off = ((brow + an * 8) * LDK + bk_) * 2;
                ldsm_x2(bh_[an], bB + off);
                ldsm_x2(bl_[an], blB + off);
            }
            const uint32_t arow = (uint32_t)(wm * 64 + (lane & 15));
            const uint32_t ak_  = (uint32_t)(ks + (lane >> 4) * 8);
#pragma unroll
            for (int am = 0; am < 4; am++) {
                uint32_t ah_[4], al_[4];
                const uint32_t off = ((arow + am * 16) * LDK + ak_) * 2;
                ldsm_x4(ah_, aB + off);
                ldsm_x4(al_, alB + off);
#pragma unroll
                for (int an = 0; an < 4; an++) {
                    mma_bf16(acc[am][an], ah_, bh_[an]);
                    mma_bf16(acc[am][an], ah_, bl_[an]);
                    mma_bf16(acc[am][an], al_, bh_[an]);
                }
            }
        }
    }
#undef ISSUE

    const int fr = lane >> 2;
    const int fc = (lane & 3) << 1;
#pragma unroll
    for (int am = 0; am < 4; am++) {
        const int m0 = bm + wm * 64 + am * 16 + fr;
#pragma unroll
        for (int an = 0; an < 4; an++) {
            const int c = bn + wn * 32 + an * 8 + fc;
            const float b0 = bias[c], b1 = bias[c + 1];
#pragma unroll
            for (int half = 0; half < 2; half++) {
                const int m = m0 + half * 8;
                float y0 = acc[am][an][2 * half]     + b0;
                float y1 = acc[am][an][2 * half + 1] + b1;
                if (MODE == 1 || MODE == 3) {
                    y0 = (y0 > 0.f) ? (y0 + 1.f) : __expf(y0);
                    y1 = (y1 > 0.f) ? (y1 + 1.f) : __expf(y1);
                }
                if (MODE == 0) {
                    *(float2*)(out + (size_t)m * Dm + c) = make_float2(y0, y1);
                } else {
                    const int b  = m >> 12;
                    const int s  = m & 4095;
                    const int h  = c >> 6;
                    const int e0 = c & 63;
                    const size_t idx = ((size_t)(b * Hn + h) * Sq + s) * Hd + e0;
                    if (MODE != 1)
                        *(float2*)(out + idx) = make_float2(y0, y1);
                    uint32_t hi, lo;
                    cvt_pair(y0, y1, hi, lo);
                    *(uint32_t*)(outh + idx) = hi;
                    *(uint32_t*)(outl + idx) = lo;
                }
            }
        }
    }
}

// ---------------------------------------------------------------------------
// Per-chunk partials: Sp[bh][c][d][e] = sum_t k[t,d] v[t,e];  zp = sum_t k
// ---------------------------------------------------------------------------
__global__ void __launch_bounds__(256)
chunk_kv_k()
{
    __shared__ __align__(16) float ks[64 * Hd];
    __shared__ __align__(16) float vs[64 * Hd];
    const int c   = blockIdx.x;
    const int bh  = blockIdx.y;
    const int tid = threadIdx.x;
    const size_t base = ((size_t)bh * Sq + (size_t)c * Ck) * Hd;

    const int r  = tid & 63;
    const int j0 = (tid >> 6) << 4;

    float acc[16];
#pragma unroll
    for (int j = 0; j < 16; j++) acc[j] = 0.f;
    float zacc = 0.f;

    for (int half = 0; half < 2; half++) {
        const float4* kg = (const float4*)(g_k + base + (size_t)half * 64 * Hd);
        const float4* vg = (const float4*)(g_v + base + (size_t)half * 64 * Hd);
        __syncthreads();
        for (int i = tid; i < 64 * Hd / 4; i += 256) {
            ((float4*)ks)[i] = kg[i];
            ((float4*)vs)[i] = vg[i];
        }
        __syncthreads();
        for (int t = 0; t < 64; t++) {
            const float kv = ks[t * Hd + r];
            zacc += kv;
#pragma unroll
            for (int j = 0; j < 16; j++)
                acc[j] = fmaf(kv, vs[t * Hd + j0 + j], acc[j]);
        }
    }

    float* Sd = g_Sp + ((size_t)bh * Nch + c) * (Hd * Hd) + r * Hd + j0;
#pragma unroll
    for (int j = 0; j < 16; j++) Sd[j] = acc[j];
    if (tid < Hd) g_zp[((size_t)bh * Nch + c) * Hd + tid] = zacc;
}

// ---------------------------------------------------------------------------
__global__ void __launch_bounds__(256)
scan_k()
{
    const int bh = blockIdx.x;
    float* Sb = g_Sp + (size_t)bh * Nch * Hd * Hd;
    for (int e = threadIdx.x; e < Hd * Hd; e += 256) {
        float acc = 0.f;
        for (int c2 = 0; c2 < Nch; c2++) {
            const float v = Sb[(size_t)c2 * Hd * Hd + e];
            Sb[(size_t)c2 * Hd * Hd + e] = acc;
            acc += v;
        }
    }
    if (threadIdx.x < Hd) {
        float* zb = g_zp + (size_t)bh * Nch * Hd + threadIdx.x;
        float acc = 0.f;
        for (int c2 = 0; c2 < Nch; c2++) {
            const float v = zb[(size_t)c2 * Hd];
            zb[(size_t)c2 * Hd] = acc;
            acc += v;
        }
    }
}

// ---------------------------------------------------------------------------
// Fused attention per (chunk, bh): scores (TC) -> mask/den -> num (TC) -> out.
// smem (bytes): qh,ql,kh(->vh),kl(->vl): 4x18432 | sch,scl: 2x34816 |
// sxh,sxl: 2x9216 | den: 512 | denp: 2048  => 164352
// ---------------------------------------------------------------------------
constexpr int QK_STR = 72;    // bf16 elems/row (144B, ldsm conflict-free)
constexpr int SC_STR = 136;   // (272B)
constexpr int OFF_QH  = 0;
constexpr int OFF_QL  = OFF_QH + 128 * QK_STR * 2;   // 18432
constexpr int OFF_KH  = OFF_QL + 18432;              // 36864 (v in phase2)
constexpr int OFF_KL  = OFF_KH + 18432;              // 55296
constexpr int OFF_SCH = OFF_KL + 18432;              // 73728
constexpr int OFF_SCL = OFF_SCH + 128 * SC_STR * 2;  // 108544
constexpr int OFF_SXH = OFF_SCL + 34816;             // 143360
constexpr int OFF_SXL = OFF_SXH + 64 * QK_STR * 2;   // 152576
constexpr int OFF_DEN = OFF_SXL + 9216;              // 161792
constexpr int OFF_DENP = OFF_DEN + 512;              // 162304
constexpr int ATTN_SMEM = OFF_DENP + 2048;           // 164352

__global__ void __launch_bounds__(256)
attn_fused_k()
{
    extern __shared__ char dsm[];
    const uint32_t sb = smem_u32(dsm);
    const int c    = blockIdx.x;
    const int bh   = blockIdx.y;
    const int tid  = threadIdx.x;
    const int lane = tid & 31;
    const int wid  = tid >> 5;
    const int wm   = wid >> 2;
    const int wn   = wid & 3;
    const size_t base = ((size_t)bh * Sq + (size_t)c * Ck) * Hd;

    // ---- load q,k hi/lo -> smem (padded rows) ----
    {
        const uint4* qh = (const uint4*)(g_qh + base);
        const uint4* ql = (const uint4*)(g_ql + base);
        const uint4* kh = (const uint4*)(g_kh + base);
        const uint4* kl = (const uint4*)(g_kl + base);
        for (int i = tid; i < 128 * 8; i += 256) {
            const int so = (i >> 3) * (QK_STR * 2) + (i & 7) * 16;
            *(uint4*)(dsm + OFF_QH + so) = qh[i];
            *(uint4*)(dsm + OFF_QL + so) = ql[i];
            *(uint4*)(dsm + OFF_KH + so) = kh[i];
            *(uint4*)(dsm + OFF_KL + so) = kl[i];
        }
    }
    __syncthreads();

    const int fr = lane >> 2;
    const int fc = (lane & 3) << 1;

    // ---- phase 1: sc = q.k^T (128x128, K=64) ----
    {
        float acc[4][4][4];
#pragma unroll
        for (int i = 0; i < 4; i++)
#pragma unroll
            for (int j = 0; j < 4; j++)
#pragma unroll
                for (int r = 0; r < 4; r++) acc[i][j][r] = 0.f;

#pragma unroll
        for (int ksk = 0; ksk < 64; ksk += 16) {
            uint32_t bh_[4][2], bl_[4][2];
            const uint32_t brow = (uint32_t)(wn * 32 + (lane & 7));
            const uint32_t bk_  = (uint32_t)(ksk + ((lane >> 3) & 1) * 8);
#pragma unroll
            for (int an = 0; an < 4; an++) {
                const uint32_t off = ((brow + an * 8) * QK_STR + bk_) * 2;
                ldsm_x2(bh_[an], sb + OFF_KH + off);
                ldsm_x2(bl_[an], sb + OFF_KL + off);
            }
            const uint32_t arow = (uint32_t)(wm * 64 + (lane & 15));
            const uint32_t ak_  = (uint32_t)(ksk + (lane >> 4) * 8);
#pragma unroll
            for (int am = 0; am < 4; am++) {
                uint32_t ah_[4], al_[4];
                const uint32_t off = ((arow + am * 16) * QK_STR + ak_) * 2;
                ldsm_x4(ah_, sb + OFF_QH + off);
                ldsm_x4(al_, sb + OFF_QL + off);
#pragma unroll
                for (int an = 0; an < 4; an++) {
                    mma_bf16(acc[am][an], ah_, bh_[an]);
                    mma_bf16(acc[am][an], ah_, bl_[an]);
                    mma_bf16(acc[am][an], al_, bh_[an]);
                }
            }
        }

        // mask + row-sum partials + bf16-split store to smem
        float rs[8];
#pragma unroll
        for (int i = 0; i < 8; i++) rs[i] = 0.f;
#pragma unroll
        for (int am = 0; am < 4; am++) {
            const int t0r = wm * 64 + am * 16 + fr;
#pragma unroll
            for (int an = 0; an < 4; an++) {
                const int u0 = wn * 32 + an * 8 + fc;
#pragma unroll
                for (int half = 0; half < 2; half++) {
                    const int t = t0r + half * 8;
                    float v0 = (u0     <= t) ? acc[am][an][2 * half]     : 0.f;
                    float v1 = (u0 + 1 <= t) ? acc[am][an][2 * half + 1] : 0.f;
                    rs[am * 2 + half] += v0 + v1;
                    uint32_t hi, lo;
                    cvt_pair(v0, v1, hi, lo);
                    *(uint32_t*)(dsm + OFF_SCH + (t * SC_STR + u0) * 2) = hi;
                    *(uint32_t*)(dsm + OFF_SCL + (t * SC_STR + u0) * 2) = lo;
                }
            }
        }
#pragma unroll
        for (int idx = 0; idx < 8; idx++) {
            float s = rs[idx];
            s += __shfl_xor_sync(0xffffffffu, s, 1);
            s += __shfl_xor_sync(0xffffffffu, s, 2);
            if ((lane & 3) == 0) {
                const int row = wm * 64 + (idx >> 1) * 16 + fr + (idx & 1) * 8;
                *(float*)(dsm + OFF_DENP + (row * 4 + wn) * 4) = s;
            }
        }
    }
    __syncthreads();

    // ---- load v, Sx (overwrite k region); compute den ----
    {
        const uint4* vh = (const uint4*)(g_vh + base);
        const uint4* vl = (const uint4*)(g_vl + base);
        for (int i = tid; i < 128 * 8; i += 256) {
            const int so = (i >> 3) * (QK_STR * 2) + (i & 7) * 16;
            *(uint4*)(dsm + OFF_KH + so) = vh[i];
            *(uint4*)(dsm + OFF_KL + so) = vl[i];
        }
        const size_t sxb = ((size_t)bh * Nch + c) * (Hd * Hd);
        const uint4* xh = (const uint4*)(g_sph + sxb);
        const uint4* xl = (const uint4*)(g_spl + sxb);
        for (int i = tid; i < 64 * 8; i += 256) {
            const int so = (i >> 3) * (QK_STR * 2) + (i & 7) * 16;
            *(uint4*)(dsm + OFF_SXH + so) = xh[i];
            *(uint4*)(dsm + OFF_SXL + so) = xl[i];
        }
    }
    if (tid < 128) {
        const int t = tid;
        float s = 0.f;
#pragma unroll
        for (int j = 0; j < 4; j++)
            s += *(float*)(dsm + OFF_DENP + (t * 4 + j) * 4);
        const float* z = g_zp + ((size_t)bh * Nch + c) * Hd;
        for (int d = 0; d < Hd; d++) {
            const uint16_t hb = *(const uint16_t*)(dsm + OFF_QH + (t * QK_STR + d) * 2);
            const uint16_t lb = *(const uint16_t*)(dsm + OFF_QL + (t * QK_STR + d) * 2);
            s = fmaf(b2f(hb) + b2f(lb), z[d], s);
        }
        *(float*)(dsm + OFF_DEN + t * 4) = s;
    }
    __syncthreads();

    // ---- phase 2: num = sc@V (K=128) + q@Sx (K=64), 128x64 ----
    float a2[4][2][4];
#pragma unroll
    for (int i = 0; i < 4; i++)
#pragma unroll
        for (int j = 0; j < 2; j++)
#pragma unroll
            for (int r = 0; r < 4; r++) a2[i][j][r] = 0.f;

#pragma unroll
    for (int ksk = 0; ksk < 128; ksk += 16) {
        uint32_t bh2[2][2], bl2[2][2];
        const uint32_t krow = (uint32_t)(ksk + (lane & 15));
#pragma unroll
        for (int an = 0; an < 2; an++) {
            const uint32_t n0 = (uint32_t)(wn * 16 + an * 8);
            const uint32_t off = (krow * QK_STR + n0) * 2;
            ldsm_x2_t(bh2[an], sb + OFF_KH + off);   // v hi
            ldsm_x2_t(bl2[an], sb + OFF_KL + off);   // v lo
        }
        const uint32_t arow = (uint32_t)(wm * 64 + (lane & 15));
        const uint32_t ak_  = (uint32_t)(ksk + (lane >> 4) * 8);
#pragma unroll
        for (int am = 0; am < 4; am++) {
            uint32_t ah_[4], al_[4];
            const uint32_t off = ((arow + am * 16) * SC_STR + ak_) * 2;
            ldsm_x4(ah_, sb + OFF_SCH + off);
            ldsm_x4(al_, sb + OFF_SCL + off);
#pragma unroll
            for (int an = 0; an < 2; an++) {
                mma_bf16(a2[am][an], ah_, bh2[an]);
                mma_bf16(a2[am][an], ah_, bl2[an]);
                mma_bf16(a2[am][an], al_, bh2[an]);
            }
        }
    }
#pragma unroll
    for (int ksk = 0; ksk < 64; ksk += 16) {
        uint32_t bh2[2][2], bl2[2][2];
        const uint32_t krow = (uint32_t)(ksk + (lane & 15));
#pragma unroll
        for (int an = 0; an < 2; an++) {
            const uint32_t n0 = (uint32_t)(wn * 16 + an * 8);
            const uint32_t off = (krow * QK_STR + n0) * 2;
            ldsm_x2_t(bh2[an], sb + OFF_SXH + off);
            ldsm_x2_t(bl2[an], sb + OFF_SXL + off);
        }
        const uint32_t arow = (uint32_t)(wm * 64 + (lane & 15));
        const uint32_t ak_  = (uint32_t)(ksk + (lane >> 4) * 8);
#pragma unroll
        for (int am = 0; am < 4; am++) {
            uint32_t ah_[4], al_[4];
            const uint32_t off = ((arow + am * 16) * QK_STR + ak_) * 2;
            ldsm_x4(ah_, sb + OFF_QH + off);
            ldsm_x4(al_, sb + OFF_QL + off);
#pragma unroll
            for (int an = 0; an < 2; an++) {
                mma_bf16(a2[am][an], ah_, bh2[an]);
                mma_bf16(a2[am][an], ah_, bl2[an]);
                mma_bf16(a2[am][an], al_, bh2[an]);
            }
        }
    }

    // ---- epilogue: divide by den, write bf16 hi/lo att ----
    const int b = bh >> 4, h = bh & 15;
#pragma unroll
    for (int am = 0; am < 4; am++) {
        const int t0r = wm * 64 + am * 16 + fr;
        const float inv0 = 1.f / *(const float*)(dsm + OFF_DEN + t0r * 4);
        const float inv1 = 1.f / *(const float*)(dsm + OFF_DEN + (t0r + 8) * 4);
#pragma unroll
        for (int an = 0; an < 2; an++) {
            const int e0 = wn * 16 + an * 8 + fc;
            const size_t idx0 = ((size_t)b * Sq + (size_t)c * Ck + t0r) * Dm + h * Hd + e0;
            uint32_t hi, lo;
            cvt_pair(a2[am][an][0] * inv0, a2[am][an][1] * inv0, hi, lo);
            *(uint32_t*)(g_ath + idx0) = hi;
            *(uint32_t*)(g_atl + idx0) = lo;
            cvt_pair(a2[am][an][2] * inv1, a2[am][an][3] * inv1, hi, lo);
            *(uint32_t*)(g_ath + idx0 + (size_t)8 * Dm) = hi;
            *(uint32_t*)(g_atl + idx0 + (size_t)8 * Dm) = lo;
        }
    }
}

// ---------------------------------------------------------------------------
extern "C" void kernel_launch(void* const* d_in, const int* in_sizes, int n_in,
                              void* d_out, int out_size)
{
    const float* x = nullptr;
    const float* Ws[4] = {nullptr, nullptr, nullptr, nullptr};
    const float* bs[4] = {nullptr, nullptr, nullptr, nullptr};
    int wi = 0, bi = 0;
    for (int i = 0; i < n_in; i++) {
        const int sz = in_sizes[i];
        if (sz == Mtot * Dm)      { x = (const float*)d_in[i]; }
        else if (sz == DD)        { if (wi < 4) Ws[wi++] = (const float*)d_in[i]; }
        else if (sz == Dm)        { if (bi < 4) bs[bi++] = (const float*)d_in[i]; }
    }
    float* out = (float*)d_out;

    // TRUE device addresses (never pass __device__ symbols from host — ATS!)
    float *pk, *pv, *psp;
    uint16_t *pxh, *pxl, *pwh, *pwl, *pqh, *pql, *pkh, *pkl, *pvh, *pvl;
    uint16_t *psph, *pspl, *path, *patl;
    cudaGetSymbolAddress((void**)&pk,   g_k);
    cudaGetSymbolAddress((void**)&pv,   g_v);
    cudaGetSymbolAddress((void**)&psp,  g_Sp);
    cudaGetSymbolAddress((void**)&pxh,  g_xh);
    cudaGetSymbolAddress((void**)&pxl,  g_xl);
    cudaGetSymbolAddress((void**)&pwh,  g_wh);
    cudaGetSymbolAddress((void**)&pwl,  g_wl);
    cudaGetSymbolAddress((void**)&pqh,  g_qh);
    cudaGetSymbolAddress((void**)&pql,  g_ql);
    cudaGetSymbolAddress((void**)&pkh,  g_kh);
    cudaGetSymbolAddress((void**)&pkl,  g_kl);
    cudaGetSymbolAddress((void**)&pvh,  g_vh);
    cudaGetSymbolAddress((void**)&pvl,  g_vl);
    cudaGetSymbolAddress((void**)&psph, g_sph);
    cudaGetSymbolAddress((void**)&pspl, g_spl);
    cudaGetSymbolAddress((void**)&path, g_ath);
    cudaGetSymbolAddress((void**)&patl, g_atl);

    cudaFuncSetAttribute(bf_gemm_k<0>, cudaFuncAttributeMaxDynamicSharedMemorySize, GEMM_DSMEM);
    cudaFuncSetAttribute(bf_gemm_k<1>, cudaFuncAttributeMaxDynamicSharedMemorySize, GEMM_DSMEM);
    cudaFuncSetAttribute(bf_gemm_k<2>, cudaFuncAttributeMaxDynamicSharedMemorySize, GEMM_DSMEM);
    cudaFuncSetAttribute(bf_gemm_k<3>, cudaFuncAttributeMaxDynamicSharedMemorySize, GEMM_DSMEM);
    cudaFuncSetAttribute(attn_fused_k, cudaFuncAttributeMaxDynamicSharedMemorySize, ATTN_SMEM);

    // Pre-convert operands to bf16 hi/lo (once).
    cvt_split_k<<<4096, 256>>>(x, pxh, pxl, Mtot * Dm / 8);
    for (int i = 0; i < 4; i++)
        cvt_split_k<<<512, 256>>>(Ws[i], pwh + (size_t)i * DD, pwl + (size_t)i * DD, DD / 8);

    const dim3 gg(Dm / 128, Mtot / 128);   // (8, 128)
    bf_gemm_k<1><<<gg, 256, GEMM_DSMEM>>>(pxh, pxl, pwh + 0 * (size_t)DD, pwl + 0 * (size_t)DD,
                                          bs[0], nullptr, pqh, pql);
    bf_gemm_k<3><<<gg, 256, GEMM_DSMEM>>>(pxh, pxl, pwh + 1 * (size_t)DD, pwl + 1 * (size_t)DD,
                                          bs[1], pk, pkh, pkl);
    bf_gemm_k<2><<<gg, 256, GEMM_DSMEM>>>(pxh, pxl, pwh + 2 * (size_t)DD, pwl + 2 * (size_t)DD,
                                          bs[2], pv, pvh, pvl);

    chunk_kv_k<<<dim3(Nch, BHn), 256>>>();
    scan_k<<<BHn, 256>>>();
    cvt_split_k<<<2048, 256>>>(psp, psph, pspl, BHn * Nch * Hd * Hd / 8);
    attn_fused_k<<<dim3(Nch, BHn), 256, ATTN_SMEM>>>();

    bf_gemm_k<0><<<gg, 256, GEMM_DSMEM>>>(path, patl, pwh + 3 * (size_t)DD, pwl + 3 * (size_t)DD,
                                          bs[3], out, nullptr, nullptr);
}

// round 13
// speedup vs baseline: 1.2425x; 1.0449x over previous
#include <cuda_runtime.h>
#include <cstdint>

// ---------------------------------------------------------------------------
// LinearMultiheadAttention: x:(4,4096,1024), 16 heads x 64 dim, chunk 128.
// R13: GEMM tiles 128x256 (L2-traffic -25%), attn_fused fully cp.async
// (two groups, v/Sx prefetched under phase-1 MMAs), fp32 k/v eliminated.
// RULE: __device__ symbols passed as kernel args MUST go through
// cudaGetSymbolAddress (GB300 ATS makes the host-shadow silently writable).
// ---------------------------------------------------------------------------

// ---------------- tensor-core helpers (sm_80 baseline ISA) ----------------
__device__ __forceinline__ uint32_t smem_u32(const void* p) {
    return (uint32_t)__cvta_generic_to_shared(p);
}
__device__ __forceinline__ void ldsm_x4(uint32_t* r, uint32_t addr) {
    asm volatile("ldmatrix.sync.aligned.m8n8.x4.shared.b16 {%0,%1,%2,%3}, [%4];"
                 : "=r"(r[0]), "=r"(r[1]), "=r"(r[2]), "=r"(r[3]) : "r"(addr));
}
__device__ __forceinline__ void ldsm_x2(uint32_t* r, uint32_t addr) {
    asm volatile("ldmatrix.sync.aligned.m8n8.x2.shared.b16 {%0,%1}, [%2];"
                 : "=r"(r[0]), "=r"(r[1]) : "r"(addr));
}
__device__ __forceinline__ void ldsm_x2_t(uint32_t* r, uint32_t addr) {
    asm volatile("ldmatrix.sync.aligned.m8n8.x2.trans.shared.b16 {%0,%1}, [%2];"
                 : "=r"(r[0]), "=r"(r[1]) : "r"(addr));
}
__device__ __forceinline__ void mma_bf16(float* c, const uint32_t* a, const uint32_t* b) {
    asm volatile(
        "mma.sync.aligned.m16n8k16.row.col.f32.bf16.bf16.f32 "
        "{%0,%1,%2,%3}, {%4,%5,%6,%7}, {%8,%9}, {%0,%1,%2,%3};"
        : "+f"(c[0]), "+f"(c[1]), "+f"(c[2]), "+f"(c[3])
        : "r"(a[0]), "r"(a[1]), "r"(a[2]), "r"(a[3]), "r"(b[0]), "r"(b[1]));
}
__device__ __forceinline__ void cp_async16(uint32_t smem, const void* g) {
    asm volatile("cp.async.cg.shared.global [%0], [%1], 16;" :: "r"(smem), "l"(g));
}
__device__ __forceinline__ void cp_commit() {
    asm volatile("cp.async.commit_group;" ::: "memory");
}
__device__ __forceinline__ void cp_wait0() {
    asm volatile("cp.async.wait_group 0;" ::: "memory");
}
__device__ __forceinline__ void cp_wait1() {
    asm volatile("cp.async.wait_group 1;" ::: "memory");
}
// fp32 pair -> bf16 hi pair (packed u32, elem0 low) + lo residual pair
__device__ __forceinline__ void cvt_pair(float y0, float y1, uint32_t& hi, uint32_t& lo)
{
    asm("cvt.rn.bf16x2.f32 %0, %1, %2;" : "=r"(hi) : "f"(y1), "f"(y0));
    const float f0 = __uint_as_float(hi << 16);
    const float f1 = __uint_as_float(hi & 0xFFFF0000u);
    asm("cvt.rn.bf16x2.f32 %0, %1, %2;" : "=r"(lo) : "f"(y1 - f1), "f"(y0 - f0));
}
__device__ __forceinline__ void cvt8(const float4 f0, const float4 f1,
                                     uint4& hi, uint4& lo)
{
    const float a[8] = {f0.x, f0.y, f0.z, f0.w, f1.x, f1.y, f1.z, f1.w};
    uint32_t h[4], l[4];
#pragma unroll
    for (int i = 0; i < 4; i++) cvt_pair(a[2*i], a[2*i+1], h[i], l[i]);
    hi = make_uint4(h[0], h[1], h[2], h[3]);
    lo = make_uint4(l[0], l[1], l[2], l[3]);
}
__device__ __forceinline__ float b2f(uint32_t b) {
    return __uint_as_float(b << 16);
}
__device__ __forceinline__ float u32lo(uint32_t u) { return b2f(u & 0xFFFFu); }
__device__ __forceinline__ float u32hi(uint32_t u) { return b2f(u >> 16); }

constexpr int Bn   = 4;
constexpr int Sq   = 4096;
constexpr int Dm   = 1024;
constexpr int Hn   = 16;
constexpr int Hd   = 64;
constexpr int Mtot = Bn * Sq;     // 16384
constexpr int Ck   = 128;
constexpr int Nch  = Sq / Ck;     // 32
constexpr int BHn  = Bn * Hn;     // 64
constexpr int DD   = Dm * Dm;

__device__ __align__(16) float g_Sp[(size_t)BHn * Nch * Hd * Hd];
__device__ __align__(16) float g_zp[(size_t)BHn * Nch * Hd];
// bf16 hi/lo operands
__device__ __align__(16) uint16_t g_xh[(size_t)Mtot * Dm];
__device__ __align__(16) uint16_t g_xl[(size_t)Mtot * Dm];
__device__ __align__(16) uint16_t g_wh[(size_t)4 * DD];
__device__ __align__(16) uint16_t g_wl[(size_t)4 * DD];
__device__ __align__(16) uint16_t g_qh[(size_t)Mtot * Dm];
__device__ __align__(16) uint16_t g_ql[(size_t)Mtot * Dm];
__device__ __align__(16) uint16_t g_kh[(size_t)Mtot * Dm];
__device__ __align__(16) uint16_t g_kl[(size_t)Mtot * Dm];
__device__ __align__(16) uint16_t g_vh[(size_t)Mtot * Dm];
__device__ __align__(16) uint16_t g_vl[(size_t)Mtot * Dm];
__device__ __align__(16) uint16_t g_sph[(size_t)BHn * Nch * Hd * Hd];
__device__ __align__(16) uint16_t g_spl[(size_t)BHn * Nch * Hd * Hd];
__device__ __align__(16) uint16_t g_ath[(size_t)Mtot * Dm];
__device__ __align__(16) uint16_t g_atl[(size_t)Mtot * Dm];

// ---------------------------------------------------------------------------
// fp32 -> bf16 hi/lo split, 8 elems/thread, grid-stride.
// ---------------------------------------------------------------------------
__global__ void __launch_bounds__(256)
cvt_split_k(const float* __restrict__ src, uint16_t* __restrict__ hi,
            uint16_t* __restrict__ lo, int n8)
{
    int i = blockIdx.x * blockDim.x + threadIdx.x;
    const int stride = gridDim.x * blockDim.x;
    for (; i < n8; i += stride) {
        const float4 f0 = ((const float4*)src)[2 * i];
        const float4 f1 = ((const float4*)src)[2 * i + 1];
        uint4 h, l;
        cvt8(f0, f1, h, l);
        ((uint4*)hi)[i] = h;
        ((uint4*)lo)[i] = l;
    }
}

// ---------------------------------------------------------------------------
// HMMA GEMM on pre-split bf16: Y = A.W^T + bias (logical fp32 via 3 MMAs).
// MODE 0: fp32 plain | MODE 1: phi + split permuted | MODE 2: split permuted
// Tile 128(M) x 256(N), BK=32, 512 threads, 16 warps (2m x 8n), warp 64x32.
// cp.async 2-stage pipeline, 123KB smem, 1 CTA/SM.
// ---------------------------------------------------------------------------
constexpr int BK  = 32;
constexpr int LDK = 40;                        // padded smem row (80B)
constexpr int A_TILE_B = 128 * LDK * 2;        // 10240
constexpr int B_TILE_B = 256 * LDK * 2;        // 20480
constexpr int STAGE_B  = 2 * A_TILE_B + 2 * B_TILE_B;  // 61440
constexpr int GEMM_DSMEM = 2 * STAGE_B;        // 122880

template <int MODE>
__global__ void __launch_bounds__(512)
bf_gemm_k(const uint16_t* __restrict__ Ah_g, const uint16_t* __restrict__ Al_g,
          const uint16_t* __restrict__ Bh_g, const uint16_t* __restrict__ Bl_g,
          const float* __restrict__ bias, float* __restrict__ out,
          uint16_t* __restrict__ outh, uint16_t* __restrict__ outl)
{
    extern __shared__ char dsm[];
    const uint32_t sbase = smem_u32(dsm);

    const int tid  = threadIdx.x;
    const int lane = tid & 31;
    const int wid  = tid >> 5;        // 0..15
    const int wm   = wid >> 3;        // 0..1
    const int wn   = wid & 7;         // 0..7
    const int bm   = blockIdx.y << 7;   // M tile 128
    const int bn   = blockIdx.x << 8;   // N tile 256

    // loaders: B uses all 512 threads (256 rows x 2 halves); A uses tid<256.
    const int lrow  = tid >> 1;
    const int lhalf = (tid & 1) << 4;
    const uint16_t* pBh = Bh_g + (size_t)(bn + lrow) * Dm + lhalf;
    const uint16_t* pBl = Bl_g + (size_t)(bn + lrow) * Dm + lhalf;
    const uint16_t* pAh = Ah_g + (size_t)(bm + (lrow & 127)) * Dm + lhalf;
    const uint16_t* pAl = Al_g + (size_t)(bm + (lrow & 127)) * Dm + lhalf;
    const uint32_t sbA = (uint32_t)((lrow & 127) * LDK + lhalf) * 2;
    const uint32_t sbB = (uint32_t)(lrow * LDK + lhalf) * 2;

    float acc[4][4][4];
#pragma unroll
    for (int i = 0; i < 4; i++)
#pragma unroll
        for (int j = 0; j < 4; j++)
#pragma unroll
            for (int r = 0; r < 4; r++) acc[i][j][r] = 0.f;

#define ISSUE(stage, kc) do {                                                  \
        const uint32_t s0 = sbase + (stage) * STAGE_B;                         \
        const size_t go = (size_t)(kc) * BK;                                   \
        if (tid < 256) {                                                       \
            cp_async16(s0 + sbA,                pAh + go);                     \
            cp_async16(s0 + sbA + 16,           pAh + go + 8);                 \
            cp_async16(s0 + A_TILE_B + sbA,     pAl + go);                     \
            cp_async16(s0 + A_TILE_B + sbA + 16, pAl + go + 8);                \
        }                                                                      \
        const uint32_t b0 = s0 + 2 * A_TILE_B;                                 \
        cp_async16(b0 + sbB,                    pBh + go);                     \
        cp_async16(b0 + sbB + 16,               pBh + go + 8);                 \
        cp_async16(b0 + B_TILE_B + sbB,         pBl + go);                     \
        cp_async16(b0 + B_TILE_B + sbB + 16,    pBl + go + 8);                 \
        cp_commit();                                                           \
    } while (0)

    constexpr int NK = Dm / BK;
    ISSUE(0, 0);

    for (int kc = 0; kc < NK; kc++) {
        cp_wait0();
        __syncthreads();
        if (kc + 1 < NK) ISSUE((kc + 1) & 1, kc + 1);

        const uint32_t st  = sbase + (kc & 1) * STAGE_B;
        const uint32_t aB  = st;
        const uint32_t alB = st + A_TILE_B;
        const uint32_t bB  = st + 2 * A_TILE_B;
        const uint32_t blB = bB + B_TILE_B;

#pragma unroll
        for (int ks = 0; ks < BK; ks += 16) {
            uint32_t bh_[4][2], bl_[4][2];
            const uint32_t brow = (uint32_t)(wn * 32 + (lane & 7));
            const uint32_t bk_  = (uint32_t)(ks + ((lane >> 3) & 1) * 8);
#pragma unroll
            for (int an = 0; an < 4; an++) {
                const uint32_t off = ((brow + an * 8) * LDK + bk_) * 2;
                ldsm_x2(bh_[an], bB + off);
                ldsm_x2(bl_[an], blB + off);
            }
            const uint32_t arow = (uint32_t)(wm * 64 + (lane & 15));
            const uint32_t ak_  = (uint32_t)(ks + (lane >> 4) * 8);
#pragma unroll
            for (int am = 0; am < 4; am++) {
                uint32_t ah_[4], al_[4];
                const uint32_t off = ((arow + am * 16) * LDK + ak_) * 2;
                ldsm_x4(ah_, aB + off);
                ldsm_x4(al_, alB + off);
#pragma unroll
                for (int an = 0; an < 4; an++) {
                    mma_bf16(acc[am][an], ah_, bh_[an]);
                    mma_bf16(acc[am][an], ah_, bl_[an]);
                    mma_bf16(acc[am][an], al_, bh_[an]);
                }
            }
        }
    }
#undef ISSUE

    const int fr = lane >> 2;
    const int fc = (lane & 3) << 1;
#pragma unroll
    for (int am = 0; am < 4; am++) {
        const int m0 = bm + wm * 64 + am * 16 + fr;
#pragma unroll
        for (int an = 0; an < 4; an++) {
            const int c = bn + wn * 32 + an * 8 + fc;
            const float b0 = bias[c], b1 = bias[c + 1];
#pragma unroll
            for (int half = 0; half < 2; half++) {
                const int m = m0 + half * 8;
                float y0 = acc[am][an][2 * half]     + b0;
                float y1 = acc[am][an][2 * half + 1] + b1;
                if (MODE == 1) {
                    y0 = (y0 > 0.f) ? (y0 + 1.f) : __expf(y0);
                    y1 = (y1 > 0.f) ? (y1 + 1.f) : __expf(y1);
                }
                if (MODE == 0) {
                    *(float2*)(out + (size_t)m * Dm + c) = make_float2(y0, y1);
                } else {
                    const int b  = m >> 12;
                    const int s  = m & 4095;
                    const int h  = c >> 6;
                    const int e0 = c & 63;
                    const size_t idx = ((size_t)(b * Hn + h) * Sq + s) * Hd + e0;
                    uint32_t hi, lo;
                    cvt_pair(y0, y1, hi, lo);
                    *(uint32_t*)(outh + idx) = hi;
                    *(uint32_t*)(outl + idx) = lo;
                }
            }
        }
    }
}

// ---------------------------------------------------------------------------
// Per-chunk partials from bf16 hi/lo: Sp = sum_t k^T v; zp = sum_t k
// ---------------------------------------------------------------------------
__global__ void __launch_bounds__(256)
chunk_kv_k()
{
    __shared__ __align__(16) float ks[64 * Hd];
    __shared__ __align__(16) float vs[64 * Hd];
    const int c   = blockIdx.x;
    const int bh  = blockIdx.y;
    const int tid = threadIdx.x;
    const size_t base = ((size_t)bh * Sq + (size_t)c * Ck) * Hd;

    const int r  = tid & 63;
    const int j0 = (tid >> 6) << 4;

    float acc[16];
#pragma unroll
    for (int j = 0; j < 16; j++) acc[j] = 0.f;
    float zacc = 0.f;

    for (int half = 0; half < 2; half++) {
        const size_t hb = base + (size_t)half * 64 * Hd;
        __syncthreads();
        for (int i = tid; i < 64 * Hd / 4; i += 256) {
            const uint2 kh = ((const uint2*)(g_kh + hb))[i];
            const uint2 kl = ((const uint2*)(g_kl + hb))[i];
            const uint2 vh = ((const uint2*)(g_vh + hb))[i];
            const uint2 vl = ((const uint2*)(g_vl + hb))[i];
            ((float4*)ks)[i] = make_float4(
                u32lo(kh.x) + u32lo(kl.x), u32hi(kh.x) + u32hi(kl.x),
                u32lo(kh.y) + u32lo(kl.y), u32hi(kh.y) + u32hi(kl.y));
            ((float4*)vs)[i] = make_float4(
                u32lo(vh.x) + u32lo(vl.x), u32hi(vh.x) + u32hi(vl.x),
                u32lo(vh.y) + u32lo(vl.y), u32hi(vh.y) + u32hi(vl.y));
        }
        __syncthreads();
        for (int t = 0; t < 64; t++) {
            const float kv = ks[t * Hd + r];
            zacc += kv;
#pragma unroll
            for (int j = 0; j < 16; j++)
                acc[j] = fmaf(kv, vs[t * Hd + j0 + j], acc[j]);
        }
    }

    float* Sd = g_Sp + ((size_t)bh * Nch + c) * (Hd * Hd) + r * Hd + j0;
#pragma unroll
    for (int j = 0; j < 16; j++) Sd[j] = acc[j];
    if (tid < Hd) g_zp[((size_t)bh * Nch + c) * Hd + tid] = zacc;
}

// ---------------------------------------------------------------------------
__global__ void __launch_bounds__(256)
scan_k()
{
    const int bh = blockIdx.x;
    float* Sb = g_Sp + (size_t)bh * Nch * Hd * Hd;
    for (int e = threadIdx.x; e < Hd * Hd; e += 256) {
        float acc = 0.f;
        for (int c2 = 0; c2 < Nch; c2++) {
            const float v = Sb[(size_t)c2 * Hd * Hd + e];
            Sb[(size_t)c2 * Hd * Hd + e] = acc;
            acc += v;
        }
    }
    if (threadIdx.x < Hd) {
        float* zb = g_zp + (size_t)bh * Nch * Hd + threadIdx.x;
        float acc = 0.f;
        for (int c2 = 0; c2 < Nch; c2++) {
            const float v = zb[(size_t)c2 * Hd];
            zb[(size_t)c2 * Hd] = acc;
            acc += v;
        }
    }
}

// ---------------------------------------------------------------------------
// Fused attention per (chunk, bh): cp.async everything; v/Sx prefetch rides
// under phase-1 MMAs (wait_group 1 / 0 split). 197KB smem, 1 CTA/SM.
// ---------------------------------------------------------------------------
constexpr int QK_STR = 72;    // bf16 elems/row (144B)
constexpr int SC_STR = 136;   // (272B)
constexpr int OFF_QH  = 0;
constexpr int OFF_QL  = OFF_QH + 128 * QK_STR * 2;   // 18432
constexpr int OFF_KH  = OFF_QL + 18432;              // 36864
constexpr int OFF_KL  = OFF_KH + 18432;              // 55296
constexpr int OFF_VH  = OFF_KL + 18432;              // 73728
constexpr int OFF_VL  = OFF_VH + 18432;              // 92160
constexpr int OFF_SXH = OFF_VL + 18432;              // 110592
constexpr int OFF_SXL = OFF_SXH + 64 * QK_STR * 2;   // 119808
constexpr int OFF_SCH = OFF_SXL + 9216;              // 129024
constexpr int OFF_SCL = OFF_SCH + 128 * SC_STR * 2;  // 163840
constexpr int OFF_DEN = OFF_SCL + 34816;             // 198656
constexpr int OFF_DENP = OFF_DEN + 512;              // 199168
constexpr int ATTN_SMEM = OFF_DENP + 2048;           // 201216

__global__ void __launch_bounds__(256)
attn_fused_k()
{
    extern __shared__ char dsm[];
    const uint32_t sb = smem_u32(dsm);
    const int c    = blockIdx.x;
    const int bh   = blockIdx.y;
    const int tid  = threadIdx.x;
    const int lane = tid & 31;
    const int wid  = tid >> 5;
    const int wm   = wid >> 2;
    const int wn   = wid & 3;
    const size_t base = ((size_t)bh * Sq + (size_t)c * Ck) * Hd;

    // ---- group 1: q,k ----
    for (int i = tid; i < 128 * 8; i += 256) {
        const uint32_t so = (uint32_t)((i >> 3) * (QK_STR * 2) + (i & 7) * 16);
        const size_t g = base + (size_t)(i >> 3) * Hd + (i & 7) * 8;
        cp_async16(sb + OFF_QH + so, g_qh + g);
        cp_async16(sb + OFF_QL + so, g_ql + g);
        cp_async16(sb + OFF_KH + so, g_kh + g);
        cp_async16(sb + OFF_KL + so, g_kl + g);
    }
    cp_commit();
    // ---- group 2: v, Sx (lands during phase 1) ----
    {
        const size_t sxb = ((size_t)bh * Nch + c) * (Hd * Hd);
        for (int i = tid; i < 128 * 8; i += 256) {
            const uint32_t so = (uint32_t)((i >> 3) * (QK_STR * 2) + (i & 7) * 16);
            const size_t g = base + (size_t)(i >> 3) * Hd + (i & 7) * 8;
            cp_async16(sb + OFF_VH + so, g_vh + g);
            cp_async16(sb + OFF_VL + so, g_vl + g);
            if (i < 64 * 8) {
                const size_t gx = sxb + (size_t)(i >> 3) * Hd + (i & 7) * 8;
                cp_async16(sb + OFF_SXH + so, g_sph + gx);
                cp_async16(sb + OFF_SXL + so, g_spl + gx);
            }
        }
        cp_commit();
    }
    cp_wait1();         // q,k ready (v,Sx still in flight)
    __syncthreads();

    const int fr = lane >> 2;
    const int fc = (lane & 3) << 1;

    // ---- phase 1: sc = q.k^T (128x128, K=64) ----
    {
        float acc[4][4][4];
#pragma unroll
        for (int i = 0; i < 4; i++)
#pragma unroll
            for (int j = 0; j < 4; j++)
#pragma unroll
                for (int r = 0; r < 4; r++) acc[i][j][r] = 0.f;

#pragma unroll
        for (int ksk = 0; ksk < 64; ksk += 16) {
            uint32_t bh_[4][2], bl_[4][2];
            const uint32_t brow = (uint32_t)(wn * 32 + (lane & 7));
            const uint32_t bk_  = (uint32_t)(ksk + ((lane >> 3) & 1) * 8);
#pragma unroll
            for (int an = 0; an < 4; an++) {
                const uint32_t off = ((brow + an * 8) * QK_STR + bk_) * 2;
                ldsm_x2(bh_[an], sb + OFF_KH + off);
                ldsm_x2(bl_[an], sb + OFF_KL + off);
            }
            const uint32_t arow = (uint32_t)(wm * 64 + (lane & 15));
            const uint32_t ak_  = (uint32_t)(ksk + (lane >> 4) * 8);
#pragma unroll
            for (int am = 0; am < 4; am++) {
                uint32_t ah_[4], al_[4];
                const uint32_t off = ((arow + am * 16) * QK_STR + ak_) * 2;
                ldsm_x4(ah_, sb + OFF_QH + off);
                ldsm_x4(al_, sb + OFF_QL + off);
#pragma unroll
                for (int an = 0; an < 4; an++) {
                    mma_bf16(acc[am][an], ah_, bh_[an]);
                    mma_bf16(acc[am][an], ah_, bl_[an]);
                    mma_bf16(acc[am][an], al_, bh_[an]);
                }
            }
        }

        // mask + row-sum partials + bf16-split store to smem
        float rs[8];
#pragma unroll
        for (int i = 0; i < 8; i++) rs[i] = 0.f;
#pragma unroll
        for (int am = 0; am < 4; am++) {
            const int t0r = wm * 64 + am * 16 + fr;
#pragma unroll
            for (int an = 0; an < 4; an++) {
                const int u0 = wn * 32 + an * 8 + fc;
#pragma unroll
                for (int half = 0; half < 2; half++) {
                    const int t = t0r + half * 8;
                    float v0 = (u0     <= t) ? acc[am][an][2 * half]     : 0.f;
                    float v1 = (u0 + 1 <= t) ? acc[am][an][2 * half + 1] : 0.f;
                    rs[am * 2 + half] += v0 + v1;
                    uint32_t hi, lo;
                    cvt_pair(v0, v1, hi, lo);
                    *(uint32_t*)(dsm + OFF_SCH + (t * SC_STR + u0) * 2) = hi;
                    *(uint32_t*)(dsm + OFF_SCL + (t * SC_STR + u0) * 2) = lo;
                }
            }
        }
#pragma unroll
        for (int idx = 0; idx < 8; idx++) {
            float s = rs[idx];
            s += __shfl_xor_sync(0xffffffffu, s, 1);
            s += __shfl_xor_sync(0xffffffffu, s, 2);
            if ((lane & 3) == 0) {
                const int row = wm * 64 + (idx >> 1) * 16 + fr + (idx & 1) * 8;
                *(float*)(dsm + OFF_DENP + (row * 4 + wn) * 4) = s;
            }
        }
    }
    cp_wait0();         // v, Sx ready
    __syncthreads();

    // ---- den (parallel over 256 threads: 2 per row) ----
    {
        const int t  = tid >> 1;
        const int d0 = (tid & 1) << 5;
        float s = 0.f;
        if ((tid & 1) == 0) {
#pragma unroll
            for (int j = 0; j < 4; j++)
                s += *(float*)(dsm + OFF_DENP + (t * 4 + j) * 4);
        }
        const float* z = g_zp + ((size_t)bh * Nch + c) * Hd + d0;
#pragma unroll
        for (int d = 0; d < 32; d++) {
            const uint16_t hb = *(const uint16_t*)(dsm + OFF_QH + (t * QK_STR + d0 + d) * 2);
            const uint16_t lb = *(const uint16_t*)(dsm + OFF_QL + (t * QK_STR + d0 + d) * 2);
            s = fmaf(b2f(hb) + b2f(lb), z[d], s);
        }
        s += __shfl_xor_sync(0xffffffffu, s, 1);
        if ((tid & 1) == 0) *(float*)(dsm + OFF_DEN + t * 4) = s;
    }
    __syncthreads();

    // ---- phase 2: num = sc@V (K=128) + q@Sx (K=64), 128x64 ----
    float a2[4][2][4];
#pragma unroll
    for (int i = 0; i < 4; i++)
#pragma unroll
        for (int j = 0; j < 2; j++)
#pragma unroll
            for (int r = 0; r < 4; r++) a2[i][j][r] = 0.f;

#pragma unroll
    for (int ksk = 0; ksk < 128; ksk += 16) {
        uint32_t bh2[2][2], bl2[2][2];
        const uint32_t krow = (uint32_t)(ksk + (lane & 15));
#pragma unroll
        for (int an = 0; an < 2; an++) {
            const uint32_t n0 = (uint32_t)(wn * 16 + an * 8);
            const uint32_t off = (krow * QK_STR + n0) * 2;
            ldsm_x2_t(bh2[an], sb + OFF_VH + off);
            ldsm_x2_t(bl2[an], sb + OFF_VL + off);
        }
        const uint32_t arow = (uint32_t)(wm * 64 + (lane & 15));
        const uint32_t ak_  = (uint32_t)(ksk + (lane >> 4) * 8);
#pragma unroll
        for (int am = 0; am < 4; am++) {
            uint32_t ah_[4], al_[4];
            const uint32_t off = ((arow + am * 16) * SC_STR + ak_) * 2;
            ldsm_x4(ah_, sb + OFF_SCH + off);
            ldsm_x4(al_, sb + OFF_SCL + off);
#pragma unroll
            for (int an = 0; an < 2; an++) {
                mma_bf16(a2[am][an], ah_, bh2[an]);
                mma_bf16(a2[am][an], ah_, bl2[an]);
                mma_bf16(a2[am][an], al_, bh2[an]);
            }
        }
    }
#pragma unroll
    for (int ksk = 0; ksk < 64; ksk += 16) {
        uint32_t bh2[2][2], bl2[2][2];
        const uint32_t krow = (uint32_t)(ksk + (lane & 15));
#pragma unroll
        for (int an = 0; an < 2; an++) {
            const uint32_t n0 = (uint32_t)(wn * 16 + an * 8);
            const uint32_t off = (krow * QK_STR + n0) * 2;
            ldsm_x2_t(bh2[an], sb + OFF_SXH + off);
            ldsm_x2_t(bl2[an], sb + OFF_SXL + off);
        }
        const uint32_t arow = (uint32_t)(wm * 64 + (lane & 15));
        const uint32_t ak_  = (uint32_t)(ksk + (lane >> 4) * 8);
#pragma unroll
        for (int am = 0; am < 4; am++) {
            uint32_t ah_[4], al_[4];
            const uint32_t off = ((arow + am * 16) * QK_STR + ak_) * 2;
            ldsm_x4(ah_, sb + OFF_QH + off);
            ldsm_x4(al_, sb + OFF_QL + off);
#pragma unroll
            for (int an = 0; an < 2; an++) {
                mma_bf16(a2[am][an], ah_, bh2[an]);
                mma_bf16(a2[am][an], ah_, bl2[an]);
                mma_bf16(a2[am][an], al_, bh2[an]);
            }
        }
    }

    // ---- epilogue: divide by den, write bf16 hi/lo att ----
    const int b = bh >> 4, h = bh & 15;
#pragma unroll
    for (int am = 0; am < 4; am++) {
        const int t0r = wm * 64 + am * 16 + fr;
        const float inv0 = 1.f / *(const float*)(dsm + OFF_DEN + t0r * 4);
        const float inv1 = 1.f / *(const float*)(dsm + OFF_DEN + (t0r + 8) * 4);
#pragma unroll
        for (int an = 0; an < 2; an++) {
            const int e0 = wn * 16 + an * 8 + fc;
            const size_t idx0 = ((size_t)b * Sq + (size_t)c * Ck + t0r) * Dm + h * Hd + e0;
            uint32_t hi, lo;
            cvt_pair(a2[am][an][0] * inv0, a2[am][an][1] * inv0, hi, lo);
            *(uint32_t*)(g_ath + idx0) = hi;
            *(uint32_t*)(g_atl + idx0) = lo;
            cvt_pair(a2[am][an][2] * inv1, a2[am][an][3] * inv1, hi, lo);
            *(uint32_t*)(g_ath + idx0 + (size_t)8 * Dm) = hi;
            *(uint32_t*)(g_atl + idx0 + (size_t)8 * Dm) = lo;
        }
    }
}

// ---------------------------------------------------------------------------
extern "C" void kernel_launch(void* const* d_in, const int* in_sizes, int n_in,
                              void* d_out, int out_size)
{
    const float* x = nullptr;
    const float* Ws[4] = {nullptr, nullptr, nullptr, nullptr};
    const float* bs[4] = {nullptr, nullptr, nullptr, nullptr};
    int wi = 0, bi = 0;
    for (int i = 0; i < n_in; i++) {
        const int sz = in_sizes[i];
        if (sz == Mtot * Dm)      { x = (const float*)d_in[i]; }
        else if (sz == DD)        { if (wi < 4) Ws[wi++] = (const float*)d_in[i]; }
        else if (sz == Dm)        { if (bi < 4) bs[bi++] = (const float*)d_in[i]; }
    }
    float* out = (float*)d_out;

    // TRUE device addresses (never pass __device__ symbols from host — ATS!)
    float *psp;
    uint16_t *pxh, *pxl, *pwh, *pwl, *pqh, *pql, *pkh, *pkl, *pvh, *pvl;
    uint16_t *psph, *pspl, *path, *patl;
    cudaGetSymbolAddress((void**)&psp,  g_Sp);
    cudaGetSymbolAddress((void**)&pxh,  g_xh);
    cudaGetSymbolAddress((void**)&pxl,  g_xl);
    cudaGetSymbolAddress((void**)&pwh,  g_wh);
    cudaGetSymbolAddress((void**)&pwl,  g_wl);
    cudaGetSymbolAddress((void**)&pqh,  g_qh);
    cudaGetSymbolAddress((void**)&pql,  g_ql);
    cudaGetSymbolAddress((void**)&pkh,  g_kh);
    cudaGetSymbolAddress((void**)&pkl,  g_kl);
    cudaGetSymbolAddress((void**)&pvh,  g_vh);
    cudaGetSymbolAddress((void**)&pvl,  g_vl);
    cudaGetSymbolAddress((void**)&psph, g_sph);
    cudaGetSymbolAddress((void**)&pspl, g_spl);
    cudaGetSymbolAddress((void**)&path, g_ath);
    cudaGetSymbolAddress((void**)&patl, g_atl);

    cudaFuncSetAttribute(bf_gemm_k<0>, cudaFuncAttributeMaxDynamicSharedMemorySize, GEMM_DSMEM);
    cudaFuncSetAttribute(bf_gemm_k<1>, cudaFuncAttributeMaxDynamicSharedMemorySize, GEMM_DSMEM);
    cudaFuncSetAttribute(bf_gemm_k<2>, cudaFuncAttributeMaxDynamicSharedMemorySize, GEMM_DSMEM);
    cudaFuncSetAttribute(attn_fused_k, cudaFuncAttributeMaxDynamicSharedMemorySize, ATTN_SMEM);

    // Pre-convert operands to bf16 hi/lo (once).
    cvt_split_k<<<4096, 256>>>(x, pxh, pxl, Mtot * Dm / 8);
    for (int i = 0; i < 4; i++)
        cvt_split_k<<<512, 256>>>(Ws[i], pwh + (size_t)i * DD, pwl + (size_t)i * DD, DD / 8);

    const dim3 gg(Dm / 256, Mtot / 128);   // (4, 128)
    bf_gemm_k<1><<<gg, 512, GEMM_DSMEM>>>(pxh, pxl, pwh + 0 * (size_t)DD, pwl + 0 * (size_t)DD,
                                          bs[0], nullptr, pqh, pql);
    bf_gemm_k<1><<<gg, 512, GEMM_DSMEM>>>(pxh, pxl, pwh + 1 * (size_t)DD, pwl + 1 * (size_t)DD,
                                          bs[1], nullptr, pkh, pkl);
    bf_gemm_k<2><<<gg, 512, GEMM_DSMEM>>>(pxh, pxl, pwh + 2 * (size_t)DD, pwl + 2 * (size_t)DD,
                                          bs[2], nullptr, pvh, pvl);

    chunk_kv_k<<<dim3(Nch, BHn), 256>>>();
    scan_k<<<BHn, 256>>>();
    cvt_split_k<<<2048, 256>>>(psp, psph, pspl, BHn * Nch * Hd * Hd / 8);
    attn_fused_k<<<dim3(Nch, BHn), 256, ATTN_SMEM>>>();

    bf_gemm_k<0><<<gg, 512, GEMM_DSMEM>>>(path, patl, pwh + 3 * (size_t)DD, pwl + 3 * (size_t)DD,
                                          bs[3], out, nullptr, nullptr);
}

// round 14
// speedup vs baseline: 1.6882x; 1.3587x over previous
#include <cuda_runtime.h>
#include <cuda_fp16.h>
#include <cstdint>

// ---------------------------------------------------------------------------
// LinearMultiheadAttention: x:(4,4096,1024), 16 heads x 64 dim, chunk 128.
// R14: fp16 split-precision. GEMMs use 2 terms ((Ah+Al).Bh, W residual
// dropped; err ~2.8e-4/stage); attention keeps 3 terms (negligible err).
// GEMMs are MMA-issue-bound -> 2/3 the MMAs. B tile halves (hi only).
// RULE: __device__ symbols passed as kernel args MUST go through
// cudaGetSymbolAddress (GB300 ATS makes the host-shadow silently writable).
// ---------------------------------------------------------------------------

// ---------------- tensor-core helpers (sm_80 baseline ISA) ----------------
__device__ __forceinline__ uint32_t smem_u32(const void* p) {
    return (uint32_t)__cvta_generic_to_shared(p);
}
__device__ __forceinline__ void ldsm_x4(uint32_t* r, uint32_t addr) {
    asm volatile("ldmatrix.sync.aligned.m8n8.x4.shared.b16 {%0,%1,%2,%3}, [%4];"
                 : "=r"(r[0]), "=r"(r[1]), "=r"(r[2]), "=r"(r[3]) : "r"(addr));
}
__device__ __forceinline__ void ldsm_x2(uint32_t* r, uint32_t addr) {
    asm volatile("ldmatrix.sync.aligned.m8n8.x2.shared.b16 {%0,%1}, [%2];"
                 : "=r"(r[0]), "=r"(r[1]) : "r"(addr));
}
__device__ __forceinline__ void ldsm_x2_t(uint32_t* r, uint32_t addr) {
    asm volatile("ldmatrix.sync.aligned.m8n8.x2.trans.shared.b16 {%0,%1}, [%2];"
                 : "=r"(r[0]), "=r"(r[1]) : "r"(addr));
}
__device__ __forceinline__ void mma_f16(float* c, const uint32_t* a, const uint32_t* b) {
    asm volatile(
        "mma.sync.aligned.m16n8k16.row.col.f32.f16.f16.f32 "
        "{%0,%1,%2,%3}, {%4,%5,%6,%7}, {%8,%9}, {%0,%1,%2,%3};"
        : "+f"(c[0]), "+f"(c[1]), "+f"(c[2]), "+f"(c[3])
        : "r"(a[0]), "r"(a[1]), "r"(a[2]), "r"(a[3]), "r"(b[0]), "r"(b[1]));
}
__device__ __forceinline__ void cp_async16(uint32_t smem, const void* g) {
    asm volatile("cp.async.cg.shared.global [%0], [%1], 16;" :: "r"(smem), "l"(g));
}
__device__ __forceinline__ void cp_commit() {
    asm volatile("cp.async.commit_group;" ::: "memory");
}
__device__ __forceinline__ void cp_wait0() {
    asm volatile("cp.async.wait_group 0;" ::: "memory");
}
__device__ __forceinline__ void cp_wait1() {
    asm volatile("cp.async.wait_group 1;" ::: "memory");
}
// fp32 pair -> fp16 hi pair (packed u32, elem0 low) + fp16 lo residual pair
__device__ __forceinline__ void cvt_pair(float y0, float y1, uint32_t& hi, uint32_t& lo)
{
    __half2 h2 = __floats2half2_rn(y0, y1);
    hi = *reinterpret_cast<uint32_t*>(&h2);
    const float2 r = __half22float2(h2);
    __half2 l2 = __floats2half2_rn(y0 - r.x, y1 - r.y);
    lo = *reinterpret_cast<uint32_t*>(&l2);
}
__device__ __forceinline__ void cvt8(const float4 f0, const float4 f1,
                                     uint4& hi, uint4& lo)
{
    const float a[8] = {f0.x, f0.y, f0.z, f0.w, f1.x, f1.y, f1.z, f1.w};
    uint32_t h[4], l[4];
#pragma unroll
    for (int i = 0; i < 4; i++) cvt_pair(a[2*i], a[2*i+1], h[i], l[i]);
    hi = make_uint4(h[0], h[1], h[2], h[3]);
    lo = make_uint4(l[0], l[1], l[2], l[3]);
}
__device__ __forceinline__ float h2f16(uint16_t u) {
    return __half2float(__ushort_as_half(u));
}
__device__ __forceinline__ float u32lo(uint32_t u) { return h2f16((uint16_t)(u & 0xFFFFu)); }
__device__ __forceinline__ float u32hi(uint32_t u) { return h2f16((uint16_t)(u >> 16)); }

constexpr int Bn   = 4;
constexpr int Sq   = 4096;
constexpr int Dm   = 1024;
constexpr int Hn   = 16;
constexpr int Hd   = 64;
constexpr int Mtot = Bn * Sq;     // 16384
constexpr int Ck   = 128;
constexpr int Nch  = Sq / Ck;     // 32
constexpr int BHn  = Bn * Hn;     // 64
constexpr int DD   = Dm * Dm;

__device__ __align__(16) float g_Sp[(size_t)BHn * Nch * Hd * Hd];
__device__ __align__(16) float g_zp[(size_t)BHn * Nch * Hd];
// fp16 hi/lo operands
__device__ __align__(16) uint16_t g_xh[(size_t)Mtot * Dm];
__device__ __align__(16) uint16_t g_xl[(size_t)Mtot * Dm];
__device__ __align__(16) uint16_t g_wh[(size_t)4 * DD];
__device__ __align__(16) uint16_t g_wl[(size_t)4 * DD];
__device__ __align__(16) uint16_t g_qh[(size_t)Mtot * Dm];
__device__ __align__(16) uint16_t g_ql[(size_t)Mtot * Dm];
__device__ __align__(16) uint16_t g_kh[(size_t)Mtot * Dm];
__device__ __align__(16) uint16_t g_kl[(size_t)Mtot * Dm];
__device__ __align__(16) uint16_t g_vh[(size_t)Mtot * Dm];
__device__ __align__(16) uint16_t g_vl[(size_t)Mtot * Dm];
__device__ __align__(16) uint16_t g_sph[(size_t)BHn * Nch * Hd * Hd];
__device__ __align__(16) uint16_t g_spl[(size_t)BHn * Nch * Hd * Hd];
__device__ __align__(16) uint16_t g_ath[(size_t)Mtot * Dm];
__device__ __align__(16) uint16_t g_atl[(size_t)Mtot * Dm];

// ---------------------------------------------------------------------------
// fp32 -> fp16 hi/lo split, 8 elems/thread, grid-stride.
// ---------------------------------------------------------------------------
__global__ void __launch_bounds__(256)
cvt_split_k(const float* __restrict__ src, uint16_t* __restrict__ hi,
            uint16_t* __restrict__ lo, int n8)
{
    int i = blockIdx.x * blockDim.x + threadIdx.x;
    const int stride = gridDim.x * blockDim.x;
    for (; i < n8; i += stride) {
        const float4 f0 = ((const float4*)src)[2 * i];
        const float4 f1 = ((const float4*)src)[2 * i + 1];
        uint4 h, l;
        cvt8(f0, f1, h, l);
        ((uint4*)hi)[i] = h;
        ((uint4*)lo)[i] = l;
    }
}

// ---------------------------------------------------------------------------
// HMMA GEMM, fp16 2-term: Y ~= (Ah + Al) . Bh^T + bias.
// MODE 0: fp32 plain | MODE 1: phi + split permuted | MODE 2: split permuted
// Tile 128(M) x 256(N), BK=32, 512 threads, 16 warps (2m x 8n), warp 64x32.
// cp.async 2-stage pipeline, 80KB smem.
// ---------------------------------------------------------------------------
constexpr int BK  = 32;
constexpr int LDK = 40;                        // padded smem row (80B)
constexpr int A_TILE_B = 128 * LDK * 2;        // 10240
constexpr int B_TILE_B = 256 * LDK * 2;        // 20480
constexpr int STAGE_B  = 2 * A_TILE_B + B_TILE_B;      // 40960
constexpr int GEMM_DSMEM = 2 * STAGE_B;        // 81920

template <int MODE>
__global__ void __launch_bounds__(512)
fp_gemm_k(const uint16_t* __restrict__ Ah_g, const uint16_t* __restrict__ Al_g,
          const uint16_t* __restrict__ Bh_g,
          const float* __restrict__ bias, float* __restrict__ out,
          uint16_t* __restrict__ outh, uint16_t* __restrict__ outl)
{
    extern __shared__ char dsm[];
    const uint32_t sbase = smem_u32(dsm);

    const int tid  = threadIdx.x;
    const int lane = tid & 31;
    const int wid  = tid >> 5;        // 0..15
    const int wm   = wid >> 3;        // 0..1
    const int wn   = wid & 7;         // 0..7
    const int bm   = blockIdx.y << 7;   // M tile 128
    const int bn   = blockIdx.x << 8;   // N tile 256

    const int lrow  = tid >> 1;
    const int lhalf = (tid & 1) << 4;
    const uint16_t* pBh = Bh_g + (size_t)(bn + lrow) * Dm + lhalf;
    const uint16_t* pAh = Ah_g + (size_t)(bm + (lrow & 127)) * Dm + lhalf;
    const uint16_t* pAl = Al_g + (size_t)(bm + (lrow & 127)) * Dm + lhalf;
    const uint32_t sbA = (uint32_t)((lrow & 127) * LDK + lhalf) * 2;
    const uint32_t sbB = (uint32_t)(lrow * LDK + lhalf) * 2;

    float acc[4][4][4];
#pragma unroll
    for (int i = 0; i < 4; i++)
#pragma unroll
        for (int j = 0; j < 4; j++)
#pragma unroll
            for (int r = 0; r < 4; r++) acc[i][j][r] = 0.f;

#define ISSUE(stage, kc) do {                                                  \
        const uint32_t s0 = sbase + (stage) * STAGE_B;                         \
        const size_t go = (size_t)(kc) * BK;                                   \
        if (tid < 256) {                                                       \
            cp_async16(s0 + sbA,                 pAh + go);                    \
            cp_async16(s0 + sbA + 16,            pAh + go + 8);                \
            cp_async16(s0 + A_TILE_B + sbA,      pAl + go);                    \
            cp_async16(s0 + A_TILE_B + sbA + 16, pAl + go + 8);                \
        }                                                                      \
        const uint32_t b0 = s0 + 2 * A_TILE_B;                                 \
        cp_async16(b0 + sbB,      pBh + go);                                   \
        cp_async16(b0 + sbB + 16, pBh + go + 8);                               \
        cp_commit();                                                           \
    } while (0)

    constexpr int NK = Dm / BK;
    ISSUE(0, 0);

    for (int kc = 0; kc < NK; kc++) {
        cp_wait0();
        __syncthreads();
        if (kc + 1 < NK) ISSUE((kc + 1) & 1, kc + 1);

        const uint32_t st  = sbase + (kc & 1) * STAGE_B;
        const uint32_t aB  = st;
        const uint32_t alB = st + A_TILE_B;
        const uint32_t bB  = st + 2 * A_TILE_B;

#pragma unroll
        for (int ks = 0; ks < BK; ks += 16) {
            uint32_t bh_[4][2];
            const uint32_t brow = (uint32_t)(wn * 32 + (lane & 7));
            const uint32_t bk_  = (uint32_t)(ks + ((lane >> 3) & 1) * 8);
#pragma unroll
            for (int an = 0; an < 4; an++) {
                const uint32_t off = ((brow + an * 8) * LDK + bk_) * 2;
                ldsm_x2(bh_[an], bB + off);
            }
            const uint32_t arow = (uint32_t)(wm * 64 + (lane & 15));
            const uint32_t ak_  = (uint32_t)(ks + (lane >> 4) * 8);
#pragma unroll
            for (int am = 0; am < 4; am++) {
                uint32_t ah_[4], al_[4];
                const uint32_t off = ((arow + am * 16) * LDK + ak_) * 2;
                ldsm_x4(ah_, aB + off);
                ldsm_x4(al_, alB + off);
#pragma unroll
                for (int an = 0; an < 4; an++) {
                    mma_f16(acc[am][an], ah_, bh_[an]);
                    mma_f16(acc[am][an], al_, bh_[an]);
                }
            }
        }
    }
#undef ISSUE

    const int fr = lane >> 2;
    const int fc = (lane & 3) << 1;
#pragma unroll
    for (int am = 0; am < 4; am++) {
        const int m0 = bm + wm * 64 + am * 16 + fr;
#pragma unroll
        for (int an = 0; an < 4; an++) {
            const int c = bn + wn * 32 + an * 8 + fc;
            const float b0 = bias[c], b1 = bias[c + 1];
#pragma unroll
            for (int half = 0; half < 2; half++) {
                const int m = m0 + half * 8;
                float y0 = acc[am][an][2 * half]     + b0;
                float y1 = acc[am][an][2 * half + 1] + b1;
                if (MODE == 1) {
                    y0 = (y0 > 0.f) ? (y0 + 1.f) : __expf(y0);
                    y1 = (y1 > 0.f) ? (y1 + 1.f) : __expf(y1);
                }
                if (MODE == 0) {
                    *(float2*)(out + (size_t)m * Dm + c) = make_float2(y0, y1);
                } else {
                    const int b  = m >> 12;
                    const int s  = m & 4095;
                    const int h  = c >> 6;
                    const int e0 = c & 63;
                    const size_t idx = ((size_t)(b * Hn + h) * Sq + s) * Hd + e0;
                    uint32_t hi, lo;
                    cvt_pair(y0, y1, hi, lo);
                    *(uint32_t*)(outh + idx) = hi;
                    *(uint32_t*)(outl + idx) = lo;
                }
            }
        }
    }
}

// ---------------------------------------------------------------------------
// Per-chunk partials from fp16 hi/lo: Sp = sum_t k^T v; zp = sum_t k
// ---------------------------------------------------------------------------
__global__ void __launch_bounds__(256)
chunk_kv_k()
{
    __shared__ __align__(16) float ks[64 * Hd];
    __shared__ __align__(16) float vs[64 * Hd];
    const int c   = blockIdx.x;
    const int bh  = blockIdx.y;
    const int tid = threadIdx.x;
    const size_t base = ((size_t)bh * Sq + (size_t)c * Ck) * Hd;

    const int r  = tid & 63;
    const int j0 = (tid >> 6) << 4;

    float acc[16];
#pragma unroll
    for (int j = 0; j < 16; j++) acc[j] = 0.f;
    float zacc = 0.f;

    for (int half = 0; half < 2; half++) {
        const size_t hb = base + (size_t)half * 64 * Hd;
        __syncthreads();
        for (int i = tid; i < 64 * Hd / 4; i += 256) {
            const uint2 kh = ((const uint2*)(g_kh + hb))[i];
            const uint2 kl = ((const uint2*)(g_kl + hb))[i];
            const uint2 vh = ((const uint2*)(g_vh + hb))[i];
            const uint2 vl = ((const uint2*)(g_vl + hb))[i];
            ((float4*)ks)[i] = make_float4(
                u32lo(kh.x) + u32lo(kl.x), u32hi(kh.x) + u32hi(kl.x),
                u32lo(kh.y) + u32lo(kl.y), u32hi(kh.y) + u32hi(kl.y));
            ((float4*)vs)[i] = make_float4(
                u32lo(vh.x) + u32lo(vl.x), u32hi(vh.x) + u32hi(vl.x),
                u32lo(vh.y) + u32lo(vl.y), u32hi(vh.y) + u32hi(vl.y));
        }
        __syncthreads();
        for (int t = 0; t < 64; t++) {
            const float kv = ks[t * Hd + r];
            zacc += kv;
#pragma unroll
            for (int j = 0; j < 16; j++)
                acc[j] = fmaf(kv, vs[t * Hd + j0 + j], acc[j]);
        }
    }

    float* Sd = g_Sp + ((size_t)bh * Nch + c) * (Hd * Hd) + r * Hd + j0;
#pragma unroll
    for (int j = 0; j < 16; j++) Sd[j] = acc[j];
    if (tid < Hd) g_zp[((size_t)bh * Nch + c) * Hd + tid] = zacc;
}

// ---------------------------------------------------------------------------
__global__ void __launch_bounds__(256)
scan_k()
{
    const int bh = blockIdx.x;
    float* Sb = g_Sp + (size_t)bh * Nch * Hd * Hd;
    for (int e = threadIdx.x; e < Hd * Hd; e += 256) {
        float acc = 0.f;
        for (int c2 = 0; c2 < Nch; c2++) {
            const float v = Sb[(size_t)c2 * Hd * Hd + e];
            Sb[(size_t)c2 * Hd * Hd + e] = acc;
            acc += v;
        }
    }
    if (threadIdx.x < Hd) {
        float* zb = g_zp + (size_t)bh * Nch * Hd + threadIdx.x;
        float acc = 0.f;
        for (int c2 = 0; c2 < Nch; c2++) {
            const float v = zb[(size_t)c2 * Hd];
            zb[(size_t)c2 * Hd] = acc;
            acc += v;
        }
    }
}

// ---------------------------------------------------------------------------
// Fused attention per (chunk, bh): fp16 3-term (negligible error).
// cp.async everything; v/Sx prefetch rides under phase-1 MMAs.
// ---------------------------------------------------------------------------
constexpr int QK_STR = 72;    // fp16 elems/row (144B)
constexpr int SC_STR = 136;   // (272B)
constexpr int OFF_QH  = 0;
constexpr int OFF_QL  = OFF_QH + 128 * QK_STR * 2;   // 18432
constexpr int OFF_KH  = OFF_QL + 18432;              // 36864
constexpr int OFF_KL  = OFF_KH + 18432;              // 55296
constexpr int OFF_VH  = OFF_KL + 18432;              // 73728
constexpr int OFF_VL  = OFF_VH + 18432;              // 92160
constexpr int OFF_SXH = OFF_VL + 18432;              // 110592
constexpr int OFF_SXL = OFF_SXH + 64 * QK_STR * 2;   // 119808
constexpr int OFF_SCH = OFF_SXL + 9216;              // 129024
constexpr int OFF_SCL = OFF_SCH + 128 * SC_STR * 2;  // 163840
constexpr int OFF_DEN = OFF_SCL + 34816;             // 198656
constexpr int OFF_DENP = OFF_DEN + 512;              // 199168
constexpr int ATTN_SMEM = OFF_DENP + 2048;           // 201216

__global__ void __launch_bounds__(256)
attn_fused_k()
{
    extern __shared__ char dsm[];
    const uint32_t sb = smem_u32(dsm);
    const int c    = blockIdx.x;
    const int bh   = blockIdx.y;
    const int tid  = threadIdx.x;
    const int lane = tid & 31;
    const int wid  = tid >> 5;
    const int wm   = wid >> 2;
    const int wn   = wid & 3;
    const size_t base = ((size_t)bh * Sq + (size_t)c * Ck) * Hd;

    // ---- group 1: q,k ----
    for (int i = tid; i < 128 * 8; i += 256) {
        const uint32_t so = (uint32_t)((i >> 3) * (QK_STR * 2) + (i & 7) * 16);
        const size_t g = base + (size_t)(i >> 3) * Hd + (i & 7) * 8;
        cp_async16(sb + OFF_QH + so, g_qh + g);
        cp_async16(sb + OFF_QL + so, g_ql + g);
        cp_async16(sb + OFF_KH + so, g_kh + g);
        cp_async16(sb + OFF_KL + so, g_kl + g);
    }
    cp_commit();
    // ---- group 2: v, Sx (lands during phase 1) ----
    {
        const size_t sxb = ((size_t)bh * Nch + c) * (Hd * Hd);
        for (int i = tid; i < 128 * 8; i += 256) {
            const uint32_t so = (uint32_t)((i >> 3) * (QK_STR * 2) + (i & 7) * 16);
            const size_t g = base + (size_t)(i >> 3) * Hd + (i & 7) * 8;
            cp_async16(sb + OFF_VH + so, g_vh + g);
            cp_async16(sb + OFF_VL + so, g_vl + g);
            if (i < 64 * 8) {
                const size_t gx = sxb + (size_t)(i >> 3) * Hd + (i & 7) * 8;
                cp_async16(sb + OFF_SXH + so, g_sph + gx);
                cp_async16(sb + OFF_SXL + so, g_spl + gx);
            }
        }
        cp_commit();
    }
    cp_wait1();         // q,k ready (v,Sx still in flight)
    __syncthreads();

    const int fr = lane >> 2;
    const int fc = (lane & 3) << 1;

    // ---- phase 1: sc = q.k^T (128x128, K=64), 3-term ----
    {
        float acc[4][4][4];
#pragma unroll
        for (int i = 0; i < 4; i++)
#pragma unroll
            for (int j = 0; j < 4; j++)
#pragma unroll
                for (int r = 0; r < 4; r++) acc[i][j][r] = 0.f;

#pragma unroll
        for (int ksk = 0; ksk < 64; ksk += 16) {
            uint32_t bh_[4][2], bl_[4][2];
            const uint32_t brow = (uint32_t)(wn * 32 + (lane & 7));
            const uint32_t bk_  = (uint32_t)(ksk + ((lane >> 3) & 1) * 8);
#pragma unroll
            for (int an = 0; an < 4; an++) {
                const uint32_t off = ((brow + an * 8) * QK_STR + bk_) * 2;
                ldsm_x2(bh_[an], sb + OFF_KH + off);
                ldsm_x2(bl_[an], sb + OFF_KL + off);
            }
            const uint32_t arow = (uint32_t)(wm * 64 + (lane & 15));
            const uint32_t ak_  = (uint32_t)(ksk + (lane >> 4) * 8);
#pragma unroll
            for (int am = 0; am < 4; am++) {
                uint32_t ah_[4], al_[4];
                const uint32_t off = ((arow + am * 16) * QK_STR + ak_) * 2;
                ldsm_x4(ah_, sb + OFF_QH + off);
                ldsm_x4(al_, sb + OFF_QL + off);
#pragma unroll
                for (int an = 0; an < 4; an++) {
                    mma_f16(acc[am][an], ah_, bh_[an]);
                    mma_f16(acc[am][an], ah_, bl_[an]);
                    mma_f16(acc[am][an], al_, bh_[an]);
                }
            }
        }

        // mask + row-sum partials + fp16-split store to smem
        float rs[8];
#pragma unroll
        for (int i = 0; i < 8; i++) rs[i] = 0.f;
#pragma unroll
        for (int am = 0; am < 4; am++) {
            const int t0r = wm * 64 + am * 16 + fr;
#pragma unroll
            for (int an = 0; an < 4; an++) {
                const int u0 = wn * 32 + an * 8 + fc;
#pragma unroll
                for (int half = 0; half < 2; half++) {
                    const int t = t0r + half * 8;
                    float v0 = (u0     <= t) ? acc[am][an][2 * half]     : 0.f;
                    float v1 = (u0 + 1 <= t) ? acc[am][an][2 * half + 1] : 0.f;
                    rs[am * 2 + half] += v0 + v1;
                    uint32_t hi, lo;
                    cvt_pair(v0, v1, hi, lo);
                    *(uint32_t*)(dsm + OFF_SCH + (t * SC_STR + u0) * 2) = hi;
                    *(uint32_t*)(dsm + OFF_SCL + (t * SC_STR + u0) * 2) = lo;
                }
            }
        }
#pragma unroll
        for (int idx = 0; idx < 8; idx++) {
            float s = rs[idx];
            s += __shfl_xor_sync(0xffffffffu, s, 1);
            s += __shfl_xor_sync(0xffffffffu, s, 2);
            if ((lane & 3) == 0) {
                const int row = wm * 64 + (idx >> 1) * 16 + fr + (idx & 1) * 8;
                *(float*)(dsm + OFF_DENP + (row * 4 + wn) * 4) = s;
            }
        }
    }
    cp_wait0();         // v, Sx ready
    __syncthreads();

    // ---- den (parallel over 256 threads: 2 per row) ----
    {
        const int t  = tid >> 1;
        const int d0 = (tid & 1) << 5;
        float s = 0.f;
        if ((tid & 1) == 0) {
#pragma unroll
            for (int j = 0; j < 4; j++)
                s += *(float*)(dsm + OFF_DENP + (t * 4 + j) * 4);
        }
        const float* z = g_zp + ((size_t)bh * Nch + c) * Hd + d0;
#pragma unroll
        for (int d = 0; d < 32; d++) {
            const uint16_t hb = *(const uint16_t*)(dsm + OFF_QH + (t * QK_STR + d0 + d) * 2);
            const uint16_t lb = *(const uint16_t*)(dsm + OFF_QL + (t * QK_STR + d0 + d) * 2);
            s = fmaf(h2f16(hb) + h2f16(lb), z[d], s);
        }
        s += __shfl_xor_sync(0xffffffffu, s, 1);
        if ((tid & 1) == 0) *(float*)(dsm + OFF_DEN + t * 4) = s;
    }
    __syncthreads();

    // ---- phase 2: num = sc@V (K=128) + q@Sx (K=64), 128x64, 3-term ----
    float a2[4][2][4];
#pragma unroll
    for (int i = 0; i < 4; i++)
#pragma unroll
        for (int j = 0; j < 2; j++)
#pragma unroll
            for (int r = 0; r < 4; r++) a2[i][j][r] = 0.f;

#pragma unroll
    for (int ksk = 0; ksk < 128; ksk += 16) {
        uint32_t bh2[2][2], bl2[2][2];
        const uint32_t krow = (uint32_t)(ksk + (lane & 15));
#pragma unroll
        for (int an = 0; an < 2; an++) {
            const uint32_t n0 = (uint32_t)(wn * 16 + an * 8);
            const uint32_t off = (krow * QK_STR + n0) * 2;
            ldsm_x2_t(bh2[an], sb + OFF_VH + off);
            ldsm_x2_t(bl2[an], sb + OFF_VL + off);
        }
        const uint32_t arow = (uint32_t)(wm * 64 + (lane & 15));
        const uint32_t ak_  = (uint32_t)(ksk + (lane >> 4) * 8);
#pragma unroll
        for (int am = 0; am < 4; am++) {
            uint32_t ah_[4], al_[4];
            const uint32_t off = ((arow + am * 16) * SC_STR + ak_) * 2;
            ldsm_x4(ah_, sb + OFF_SCH + off);
            ldsm_x4(al_, sb + OFF_SCL + off);
#pragma unroll
            for (int an = 0; an < 2; an++) {
                mma_f16(a2[am][an], ah_, bh2[an]);
                mma_f16(a2[am][an], ah_, bl2[an]);
                mma_f16(a2[am][an], al_, bh2[an]);
            }
        }
    }
#pragma unroll
    for (int ksk = 0; ksk < 64; ksk += 16) {
        uint32_t bh2[2][2], bl2[2][2];
        const uint32_t krow = (uint32_t)(ksk + (lane & 15));
#pragma unroll
        for (int an = 0; an < 2; an++) {
            const uint32_t n0 = (uint32_t)(wn * 16 + an * 8);
            const uint32_t off = (krow * QK_STR + n0) * 2;
            ldsm_x2_t(bh2[an], sb + OFF_SXH + off);
            ldsm_x2_t(bl2[an], sb + OFF_SXL + off);
        }
        const uint32_t arow = (uint32_t)(wm * 64 + (lane & 15));
        const uint32_t ak_  = (uint32_t)(ksk + (lane >> 4) * 8);
#pragma unroll
        for (int am = 0; am < 4; am++) {
            uint32_t ah_[4], al_[4];
            const uint32_t off = ((arow + am * 16) * QK_STR + ak_) * 2;
            ldsm_x4(ah_, sb + OFF_QH + off);
            ldsm_x4(al_, sb + OFF_QL + off);
#pragma unroll
            for (int an = 0; an < 2; an++) {
                mma_f16(a2[am][an], ah_, bh2[an]);
                mma_f16(a2[am][an], ah_, bl2[an]);
                mma_f16(a2[am][an], al_, bh2[an]);
            }
        }
    }

    // ---- epilogue: divide by den, write fp16 hi/lo att ----
    const int b = bh >> 4, h = bh & 15;
#pragma unroll
    for (int am = 0; am < 4; am++) {
        const int t0r = wm * 64 + am * 16 + fr;
        const float inv0 = 1.f / *(const float*)(dsm + OFF_DEN + t0r * 4);
        const float inv1 = 1.f / *(const float*)(dsm + OFF_DEN + (t0r + 8) * 4);
#pragma unroll
        for (int an = 0; an < 2; an++) {
            const int e0 = wn * 16 + an * 8 + fc;
            const size_t idx0 = ((size_t)b * Sq + (size_t)c * Ck + t0r) * Dm + h * Hd + e0;
            uint32_t hi, lo;
            cvt_pair(a2[am][an][0] * inv0, a2[am][an][1] * inv0, hi, lo);
            *(uint32_t*)(g_ath + idx0) = hi;
            *(uint32_t*)(g_atl + idx0) = lo;
            cvt_pair(a2[am][an][2] * inv1, a2[am][an][3] * inv1, hi, lo);
            *(uint32_t*)(g_ath + idx0 + (size_t)8 * Dm) = hi;
            *(uint32_t*)(g_atl + idx0 + (size_t)8 * Dm) = lo;
        }
    }
}

// ---------------------------------------------------------------------------
extern "C" void kernel_launch(void* const* d_in, const int* in_sizes, int n_in,
                              void* d_out, int out_size)
{
    const float* x = nullptr;
    const float* Ws[4] = {nullptr, nullptr, nullptr, nullptr};
    const float* bs[4] = {nullptr, nullptr, nullptr, nullptr};
    int wi = 0, bi = 0;
    for (int i = 0; i < n_in; i++) {
        const int sz = in_sizes[i];
        if (sz == Mtot * Dm)      { x = (const float*)d_in[i]; }
        else if (sz == DD)        { if (wi < 4) Ws[wi++] = (const float*)d_in[i]; }
        else if (sz == Dm)        { if (bi < 4) bs[bi++] = (const float*)d_in[i]; }
    }
    float* out = (float*)d_out;

    // TRUE device addresses (never pass __device__ symbols from host — ATS!)
    float *psp;
    uint16_t *pxh, *pxl, *pwh, *pwl, *pqh, *pql, *pkh, *pkl, *pvh, *pvl;
    uint16_t *psph, *pspl, *path, *patl;
    cudaGetSymbolAddress((void**)&psp,  g_Sp);
    cudaGetSymbolAddress((void**)&pxh,  g_xh);
    cudaGetSymbolAddress((void**)&pxl,  g_xl);
    cudaGetSymbolAddress((void**)&pwh,  g_wh);
    cudaGetSymbolAddress((void**)&pwl,  g_wl);
    cudaGetSymbolAddress((void**)&pqh,  g_qh);
    cudaGetSymbolAddress((void**)&pql,  g_ql);
    cudaGetSymbolAddress((void**)&pkh,  g_kh);
    cudaGetSymbolAddress((void**)&pkl,  g_kl);
    cudaGetSymbolAddress((void**)&pvh,  g_vh);
    cudaGetSymbolAddress((void**)&pvl,  g_vl);
    cudaGetSymbolAddress((void**)&psph, g_sph);
    cudaGetSymbolAddress((void**)&pspl, g_spl);
    cudaGetSymbolAddress((void**)&path, g_ath);
    cudaGetSymbolAddress((void**)&patl, g_atl);

    cudaFuncSetAttribute(fp_gemm_k<0>, cudaFuncAttributeMaxDynamicSharedMemorySize, GEMM_DSMEM);
    cudaFuncSetAttribute(fp_gemm_k<1>, cudaFuncAttributeMaxDynamicSharedMemorySize, GEMM_DSMEM);
    cudaFuncSetAttribute(fp_gemm_k<2>, cudaFuncAttributeMaxDynamicSharedMemorySize, GEMM_DSMEM);
    cudaFuncSetAttribute(attn_fused_k, cudaFuncAttributeMaxDynamicSharedMemorySize, ATTN_SMEM);

    // Pre-convert operands to fp16 hi/lo (once).
    cvt_split_k<<<4096, 256>>>(x, pxh, pxl, Mtot * Dm / 8);
    for (int i = 0; i < 4; i++)
        cvt_split_k<<<512, 256>>>(Ws[i], pwh + (size_t)i * DD, pwl + (size_t)i * DD, DD / 8);

    const dim3 gg(Dm / 256, Mtot / 128);   // (4, 128)
    fp_gemm_k<1><<<gg, 512, GEMM_DSMEM>>>(pxh, pxl, pwh + 0 * (size_t)DD,
                                          bs[0], nullptr, pqh, pql);
    fp_gemm_k<1><<<gg, 512, GEMM_DSMEM>>>(pxh, pxl, pwh + 1 * (size_t)DD,
                                          bs[1], nullptr, pkh, pkl);
    fp_gemm_k<2><<<gg, 512, GEMM_DSMEM>>>(pxh, pxl, pwh + 2 * (size_t)DD,
                                          bs[2], nullptr, pvh, pvl);

    chunk_kv_k<<<dim3(Nch, BHn), 256>>>();
    scan_k<<<BHn, 256>>>();
    cvt_split_k<<<2048, 256>>>(psp, psph, pspl, BHn * Nch * Hd * Hd / 8);
    attn_fused_k<<<dim3(Nch, BHn), 256, ATTN_SMEM>>>();

    fp_gemm_k<0><<<gg, 512, GEMM_DSMEM>>>(path, patl, pwh + 3 * (size_t)DD,
                                          bs[3], out, nullptr, nullptr);
}

// round 15
// speedup vs baseline: 2.3555x; 1.3952x over previous
#include <cuda_runtime.h>
#include <cuda_fp16.h>
#include <cstdint>

// ---------------------------------------------------------------------------
// LinearMultiheadAttention: x:(4,4096,1024), 16 heads x 64 dim, chunk 128.
// R15: calibrated-precision fp16. GEMMs 1-term (Ah.Bh); attention 2-term
// ((Ah+Al).Bh). Error model: 1.4e-4 per dropped term, quadrature ->
// predicted ~4.9e-4 (budget 1e-3). chunk_kv/den stay exact fp32.
// RULE: __device__ symbols passed as kernel args MUST go through
// cudaGetSymbolAddress (GB300 ATS makes the host-shadow silently writable).
// ---------------------------------------------------------------------------

// ---------------- tensor-core helpers (sm_80 baseline ISA) ----------------
__device__ __forceinline__ uint32_t smem_u32(const void* p) {
    return (uint32_t)__cvta_generic_to_shared(p);
}
__device__ __forceinline__ void ldsm_x4(uint32_t* r, uint32_t addr) {
    asm volatile("ldmatrix.sync.aligned.m8n8.x4.shared.b16 {%0,%1,%2,%3}, [%4];"
                 : "=r"(r[0]), "=r"(r[1]), "=r"(r[2]), "=r"(r[3]) : "r"(addr));
}
__device__ __forceinline__ void ldsm_x2(uint32_t* r, uint32_t addr) {
    asm volatile("ldmatrix.sync.aligned.m8n8.x2.shared.b16 {%0,%1}, [%2];"
                 : "=r"(r[0]), "=r"(r[1]) : "r"(addr));
}
__device__ __forceinline__ void ldsm_x2_t(uint32_t* r, uint32_t addr) {
    asm volatile("ldmatrix.sync.aligned.m8n8.x2.trans.shared.b16 {%0,%1}, [%2];"
                 : "=r"(r[0]), "=r"(r[1]) : "r"(addr));
}
__device__ __forceinline__ void mma_f16(float* c, const uint32_t* a, const uint32_t* b) {
    asm volatile(
        "mma.sync.aligned.m16n8k16.row.col.f32.f16.f16.f32 "
        "{%0,%1,%2,%3}, {%4,%5,%6,%7}, {%8,%9}, {%0,%1,%2,%3};"
        : "+f"(c[0]), "+f"(c[1]), "+f"(c[2]), "+f"(c[3])
        : "r"(a[0]), "r"(a[1]), "r"(a[2]), "r"(a[3]), "r"(b[0]), "r"(b[1]));
}
__device__ __forceinline__ void cp_async16(uint32_t smem, const void* g) {
    asm volatile("cp.async.cg.shared.global [%0], [%1], 16;" :: "r"(smem), "l"(g));
}
__device__ __forceinline__ void cp_commit() {
    asm volatile("cp.async.commit_group;" ::: "memory");
}
__device__ __forceinline__ void cp_wait0() {
    asm volatile("cp.async.wait_group 0;" ::: "memory");
}
__device__ __forceinline__ void cp_wait1() {
    asm volatile("cp.async.wait_group 1;" ::: "memory");
}
// fp32 pair -> fp16 hi pair + fp16 lo residual pair (packed u32, elem0 low)
__device__ __forceinline__ void cvt_pair(float y0, float y1, uint32_t& hi, uint32_t& lo)
{
    __half2 h2 = __floats2half2_rn(y0, y1);
    hi = *reinterpret_cast<uint32_t*>(&h2);
    const float2 r = __half22float2(h2);
    __half2 l2 = __floats2half2_rn(y0 - r.x, y1 - r.y);
    lo = *reinterpret_cast<uint32_t*>(&l2);
}
__device__ __forceinline__ uint32_t cvt_hi(float y0, float y1)
{
    __half2 h2 = __floats2half2_rn(y0, y1);
    return *reinterpret_cast<uint32_t*>(&h2);
}
__device__ __forceinline__ float h2f16(uint16_t u) {
    return __half2float(__ushort_as_half(u));
}
__device__ __forceinline__ float u32lo(uint32_t u) { return h2f16((uint16_t)(u & 0xFFFFu)); }
__device__ __forceinline__ float u32hi(uint32_t u) { return h2f16((uint16_t)(u >> 16)); }

constexpr int Bn   = 4;
constexpr int Sq   = 4096;
constexpr int Dm   = 1024;
constexpr int Hn   = 16;
constexpr int Hd   = 64;
constexpr int Mtot = Bn * Sq;     // 16384
constexpr int Ck   = 128;
constexpr int Nch  = Sq / Ck;     // 32
constexpr int BHn  = Bn * Hn;     // 64
constexpr int DD   = Dm * Dm;

__device__ __align__(16) float g_Sp[(size_t)BHn * Nch * Hd * Hd];
__device__ __align__(16) float g_zp[(size_t)BHn * Nch * Hd];
// fp16 operands (hi; lo only where needed)
__device__ __align__(16) uint16_t g_xh[(size_t)Mtot * Dm];
__device__ __align__(16) uint16_t g_wh[(size_t)4 * DD];
__device__ __align__(16) uint16_t g_qh[(size_t)Mtot * Dm];
__device__ __align__(16) uint16_t g_ql[(size_t)Mtot * Dm];
__device__ __align__(16) uint16_t g_kh[(size_t)Mtot * Dm];
__device__ __align__(16) uint16_t g_kl[(size_t)Mtot * Dm];
__device__ __align__(16) uint16_t g_vh[(size_t)Mtot * Dm];
__device__ __align__(16) uint16_t g_vl[(size_t)Mtot * Dm];
__device__ __align__(16) uint16_t g_sph[(size_t)BHn * Nch * Hd * Hd];
__device__ __align__(16) uint16_t g_ath[(size_t)Mtot * Dm];

// ---------------------------------------------------------------------------
// fp32 -> fp16 hi only, 8 elems/thread, grid-stride.
// ---------------------------------------------------------------------------
__global__ void __launch_bounds__(256)
cvt_hi_k(const float* __restrict__ src, uint16_t* __restrict__ hi, int n8)
{
    int i = blockIdx.x * blockDim.x + threadIdx.x;
    const int stride = gridDim.x * blockDim.x;
    for (; i < n8; i += stride) {
        const float4 f0 = ((const float4*)src)[2 * i];
        const float4 f1 = ((const float4*)src)[2 * i + 1];
        uint4 h;
        h.x = cvt_hi(f0.x, f0.y);
        h.y = cvt_hi(f0.z, f0.w);
        h.z = cvt_hi(f1.x, f1.y);
        h.w = cvt_hi(f1.z, f1.w);
        ((uint4*)hi)[i] = h;
    }
}

// ---------------------------------------------------------------------------
// HMMA GEMM, fp16 1-term: Y ~= Ah . Bh^T + bias.
// MODE 0: fp32 plain | MODE 1: phi + hi/lo permuted | MODE 2: hi/lo permuted
// Tile 128(M) x 256(N), BK=32, 512 threads, 16 warps (2m x 8n), warp 64x32.
// cp.async 2-stage pipeline, 60KB smem.
// ---------------------------------------------------------------------------
constexpr int BK  = 32;
constexpr int LDK = 40;                        // padded smem row (80B)
constexpr int A_TILE_B = 128 * LDK * 2;        // 10240
constexpr int B_TILE_B = 256 * LDK * 2;        // 20480
constexpr int STAGE_B  = A_TILE_B + B_TILE_B;  // 30720
constexpr int GEMM_DSMEM = 2 * STAGE_B;        // 61440

template <int MODE>
__global__ void __launch_bounds__(512)
fp_gemm_k(const uint16_t* __restrict__ Ah_g, const uint16_t* __restrict__ Bh_g,
          const float* __restrict__ bias, float* __restrict__ out,
          uint16_t* __restrict__ outh, uint16_t* __restrict__ outl)
{
    extern __shared__ char dsm[];
    const uint32_t sbase = smem_u32(dsm);

    const int tid  = threadIdx.x;
    const int lane = tid & 31;
    const int wid  = tid >> 5;        // 0..15
    const int wm   = wid >> 3;        // 0..1
    const int wn   = wid & 7;         // 0..7
    const int bm   = blockIdx.y << 7;   // M tile 128
    const int bn   = blockIdx.x << 8;   // N tile 256

    const int lrow  = tid >> 1;
    const int lhalf = (tid & 1) << 4;
    const uint16_t* pBh = Bh_g + (size_t)(bn + lrow) * Dm + lhalf;
    const uint16_t* pAh = Ah_g + (size_t)(bm + (lrow & 127)) * Dm + lhalf;
    const uint32_t sbA = (uint32_t)((lrow & 127) * LDK + lhalf) * 2;
    const uint32_t sbB = (uint32_t)(lrow * LDK + lhalf) * 2;

    float acc[4][4][4];
#pragma unroll
    for (int i = 0; i < 4; i++)
#pragma unroll
        for (int j = 0; j < 4; j++)
#pragma unroll
            for (int r = 0; r < 4; r++) acc[i][j][r] = 0.f;

#define ISSUE(stage, kc) do {                                                  \
        const uint32_t s0 = sbase + (stage) * STAGE_B;                         \
        const size_t go = (size_t)(kc) * BK;                                   \
        if (tid < 256) {                                                       \
            cp_async16(s0 + sbA,      pAh + go);                               \
            cp_async16(s0 + sbA + 16, pAh + go + 8);                           \
        }                                                                      \
        const uint32_t b0 = s0 + A_TILE_B;                                     \
        cp_async16(b0 + sbB,      pBh + go);                                   \
        cp_async16(b0 + sbB + 16, pBh + go + 8);                               \
        cp_commit();                                                           \
    } while (0)

    constexpr int NK = Dm / BK;
    ISSUE(0, 0);

    for (int kc = 0; kc < NK; kc++) {
        cp_wait0();
        __syncthreads();
        if (kc + 1 < NK) ISSUE((kc + 1) & 1, kc + 1);

        const uint32_t st = sbase + (kc & 1) * STAGE_B;
        const uint32_t aB = st;
        const uint32_t bB = st + A_TILE_B;

#pragma unroll
        for (int ks = 0; ks < BK; ks += 16) {
            uint32_t bh_[4][2];
            const uint32_t brow = (uint32_t)(wn * 32 + (lane & 7));
            const uint32_t bk_  = (uint32_t)(ks + ((lane >> 3) & 1) * 8);
#pragma unroll
            for (int an = 0; an < 4; an++) {
                const uint32_t off = ((brow + an * 8) * LDK + bk_) * 2;
                ldsm_x2(bh_[an], bB + off);
            }
            const uint32_t arow = (uint32_t)(wm * 64 + (lane & 15));
            const uint32_t ak_  = (uint32_t)(ks + (lane >> 4) * 8);
#pragma unroll
            for (int am = 0; am < 4; am++) {
                uint32_t ah_[4];
                const uint32_t off = ((arow + am * 16) * LDK + ak_) * 2;
                ldsm_x4(ah_, aB + off);
#pragma unroll
                for (int an = 0; an < 4; an++)
                    mma_f16(acc[am][an], ah_, bh_[an]);
            }
        }
    }
#undef ISSUE

    const int fr = lane >> 2;
    const int fc = (lane & 3) << 1;
#pragma unroll
    for (int am = 0; am < 4; am++) {
        const int m0 = bm + wm * 64 + am * 16 + fr;
#pragma unroll
        for (int an = 0; an < 4; an++) {
            const int c = bn + wn * 32 + an * 8 + fc;
            const float b0 = bias[c], b1 = bias[c + 1];
#pragma unroll
            for (int half = 0; half < 2; half++) {
                const int m = m0 + half * 8;
                float y0 = acc[am][an][2 * half]     + b0;
                float y1 = acc[am][an][2 * half + 1] + b1;
                if (MODE == 1) {
                    y0 = (y0 > 0.f) ? (y0 + 1.f) : __expf(y0);
                    y1 = (y1 > 0.f) ? (y1 + 1.f) : __expf(y1);
                }
                if (MODE == 0) {
                    *(float2*)(out + (size_t)m * Dm + c) = make_float2(y0, y1);
                } else {
                    const int b  = m >> 12;
                    const int s  = m & 4095;
                    const int h  = c >> 6;
                    const int e0 = c & 63;
                    const size_t idx = ((size_t)(b * Hn + h) * Sq + s) * Hd + e0;
                    uint32_t hi, lo;
                    cvt_pair(y0, y1, hi, lo);
                    *(uint32_t*)(outh + idx) = hi;
                    *(uint32_t*)(outl + idx) = lo;
                }
            }
        }
    }
}

// ---------------------------------------------------------------------------
// Per-chunk partials from fp16 hi/lo (exact fp32 reconstruct):
// Sp = sum_t k^T v; zp = sum_t k
// ---------------------------------------------------------------------------
__global__ void __launch_bounds__(256)
chunk_kv_k()
{
    __shared__ __align__(16) float ks[64 * Hd];
    __shared__ __align__(16) float vs[64 * Hd];
    const int c   = blockIdx.x;
    const int bh  = blockIdx.y;
    const int tid = threadIdx.x;
    const size_t base = ((size_t)bh * Sq + (size_t)c * Ck) * Hd;

    const int r  = tid & 63;
    const int j0 = (tid >> 6) << 4;

    float acc[16];
#pragma unroll
    for (int j = 0; j < 16; j++) acc[j] = 0.f;
    float zacc = 0.f;

    for (int half = 0; half < 2; half++) {
        const size_t hb = base + (size_t)half * 64 * Hd;
        __syncthreads();
        for (int i = tid; i < 64 * Hd / 4; i += 256) {
            const uint2 kh = ((const uint2*)(g_kh + hb))[i];
            const uint2 kl = ((const uint2*)(g_kl + hb))[i];
            const uint2 vh = ((const uint2*)(g_vh + hb))[i];
            const uint2 vl = ((const uint2*)(g_vl + hb))[i];
            ((float4*)ks)[i] = make_float4(
                u32lo(kh.x) + u32lo(kl.x), u32hi(kh.x) + u32hi(kl.x),
                u32lo(kh.y) + u32lo(kl.y), u32hi(kh.y) + u32hi(kl.y));
            ((float4*)vs)[i] = make_float4(
                u32lo(vh.x) + u32lo(vl.x), u32hi(vh.x) + u32hi(vl.x),
                u32lo(vh.y) + u32lo(vl.y), u32hi(vh.y) + u32hi(vl.y));
        }
        __syncthreads();
        for (int t = 0; t < 64; t++) {
            const float kv = ks[t * Hd + r];
            zacc += kv;
#pragma unroll
            for (int j = 0; j < 16; j++)
                acc[j] = fmaf(kv, vs[t * Hd + j0 + j], acc[j]);
        }
    }

    float* Sd = g_Sp + ((size_t)bh * Nch + c) * (Hd * Hd) + r * Hd + j0;
#pragma unroll
    for (int j = 0; j < 16; j++) Sd[j] = acc[j];
    if (tid < Hd) g_zp[((size_t)bh * Nch + c) * Hd + tid] = zacc;
}

// ---------------------------------------------------------------------------
__global__ void __launch_bounds__(256)
scan_k()
{
    const int bh = blockIdx.x;
    float* Sb = g_Sp + (size_t)bh * Nch * Hd * Hd;
    for (int e = threadIdx.x; e < Hd * Hd; e += 256) {
        float acc = 0.f;
        for (int c2 = 0; c2 < Nch; c2++) {
            const float v = Sb[(size_t)c2 * Hd * Hd + e];
            Sb[(size_t)c2 * Hd * Hd + e] = acc;
            acc += v;
        }
    }
    if (threadIdx.x < Hd) {
        float* zb = g_zp + (size_t)bh * Nch * Hd + threadIdx.x;
        float acc = 0.f;
        for (int c2 = 0; c2 < Nch; c2++) {
            const float v = zb[(size_t)c2 * Hd];
            zb[(size_t)c2 * Hd] = acc;
            acc += v;
        }
    }
}

// ---------------------------------------------------------------------------
// Fused attention per (chunk, bh): 2-term ((Ah+Al).Bh).
// cp.async everything; v/Sx prefetch rides under phase-1 MMAs.
// ---------------------------------------------------------------------------
constexpr int QK_STR = 72;    // fp16 elems/row (144B)
constexpr int SC_STR = 136;   // (272B)
constexpr int OFF_QH  = 0;
constexpr int OFF_QL  = OFF_QH + 128 * QK_STR * 2;   // 18432
constexpr int OFF_KH  = OFF_QL + 18432;              // 36864
constexpr int OFF_VH  = OFF_KH + 18432;              // 55296
constexpr int OFF_SXH = OFF_VH + 18432;              // 73728
constexpr int OFF_SCH = OFF_SXH + 64 * QK_STR * 2;   // 82944
constexpr int OFF_SCL = OFF_SCH + 128 * SC_STR * 2;  // 117760
constexpr int OFF_DEN = OFF_SCL + 34816;             // 152576
constexpr int OFF_DENP = OFF_DEN + 512;              // 153088
constexpr int ATTN_SMEM = OFF_DENP + 2048;           // 155136

__global__ void __launch_bounds__(256)
attn_fused_k()
{
    extern __shared__ char dsm[];
    const uint32_t sb = smem_u32(dsm);
    const int c    = blockIdx.x;
    const int bh   = blockIdx.y;
    const int tid  = threadIdx.x;
    const int lane = tid & 31;
    const int wid  = tid >> 5;
    const int wm   = wid >> 2;
    const int wn   = wid & 3;
    const size_t base = ((size_t)bh * Sq + (size_t)c * Ck) * Hd;

    // ---- group 1: q hi/lo, k hi ----
    for (int i = tid; i < 128 * 8; i += 256) {
        const uint32_t so = (uint32_t)((i >> 3) * (QK_STR * 2) + (i & 7) * 16);
        const size_t g = base + (size_t)(i >> 3) * Hd + (i & 7) * 8;
        cp_async16(sb + OFF_QH + so, g_qh + g);
        cp_async16(sb + OFF_QL + so, g_ql + g);
        cp_async16(sb + OFF_KH + so, g_kh + g);
    }
    cp_commit();
    // ---- group 2: v hi, Sx hi (lands during phase 1) ----
    {
        const size_t sxb = ((size_t)bh * Nch + c) * (Hd * Hd);
        for (int i = tid; i < 128 * 8; i += 256) {
            const uint32_t so = (uint32_t)((i >> 3) * (QK_STR * 2) + (i & 7) * 16);
            const size_t g = base + (size_t)(i >> 3) * Hd + (i & 7) * 8;
            cp_async16(sb + OFF_VH + so, g_vh + g);
            if (i < 64 * 8) {
                const size_t gx = sxb + (size_t)(i >> 3) * Hd + (i & 7) * 8;
                cp_async16(sb + OFF_SXH + so, g_sph + gx);
            }
        }
        cp_commit();
    }
    cp_wait1();         // q,k ready (v,Sx still in flight)
    __syncthreads();

    const int fr = lane >> 2;
    const int fc = (lane & 3) << 1;

    // ---- phase 1: sc = q.k^T (128x128, K=64), 2-term ----
    {
        float acc[4][4][4];
#pragma unroll
        for (int i = 0; i < 4; i++)
#pragma unroll
            for (int j = 0; j < 4; j++)
#pragma unroll
                for (int r = 0; r < 4; r++) acc[i][j][r] = 0.f;

#pragma unroll
        for (int ksk = 0; ksk < 64; ksk += 16) {
            uint32_t bh_[4][2];
            const uint32_t brow = (uint32_t)(wn * 32 + (lane & 7));
            const uint32_t bk_  = (uint32_t)(ksk + ((lane >> 3) & 1) * 8);
#pragma unroll
            for (int an = 0; an < 4; an++) {
                const uint32_t off = ((brow + an * 8) * QK_STR + bk_) * 2;
                ldsm_x2(bh_[an], sb + OFF_KH + off);
            }
            const uint32_t arow = (uint32_t)(wm * 64 + (lane & 15));
            const uint32_t ak_  = (uint32_t)(ksk + (lane >> 4) * 8);
#pragma unroll
            for (int am = 0; am < 4; am++) {
                uint32_t ah_[4], al_[4];
                const uint32_t off = ((arow + am * 16) * QK_STR + ak_) * 2;
                ldsm_x4(ah_, sb + OFF_QH + off);
                ldsm_x4(al_, sb + OFF_QL + off);
#pragma unroll
                for (int an = 0; an < 4; an++) {
                    mma_f16(acc[am][an], ah_, bh_[an]);
                    mma_f16(acc[am][an], al_, bh_[an]);
                }
            }
        }

        // mask + row-sum partials + fp16-split store to smem
        float rs[8];
#pragma unroll
        for (int i = 0; i < 8; i++) rs[i] = 0.f;
#pragma unroll
        for (int am = 0; am < 4; am++) {
            const int t0r = wm * 64 + am * 16 + fr;
#pragma unroll
            for (int an = 0; an < 4; an++) {
                const int u0 = wn * 32 + an * 8 + fc;
#pragma unroll
                for (int half = 0; half < 2; half++) {
                    const int t = t0r + half * 8;
                    float v0 = (u0     <= t) ? acc[am][an][2 * half]     : 0.f;
                    float v1 = (u0 + 1 <= t) ? acc[am][an][2 * half + 1] : 0.f;
                    rs[am * 2 + half] += v0 + v1;
                    uint32_t hi, lo;
                    cvt_pair(v0, v1, hi, lo);
                    *(uint32_t*)(dsm + OFF_SCH + (t * SC_STR + u0) * 2) = hi;
                    *(uint32_t*)(dsm + OFF_SCL + (t * SC_STR + u0) * 2) = lo;
                }
            }
        }
#pragma unroll
        for (int idx = 0; idx < 8; idx++) {
            float s = rs[idx];
            s += __shfl_xor_sync(0xffffffffu, s, 1);
            s += __shfl_xor_sync(0xffffffffu, s, 2);
            if ((lane & 3) == 0) {
                const int row = wm * 64 + (idx >> 1) * 16 + fr + (idx & 1) * 8;
                *(float*)(dsm + OFF_DENP + (row * 4 + wn) * 4) = s;
            }
        }
    }
    cp_wait0();         // v, Sx ready
    __syncthreads();

    // ---- den (parallel over 256 threads: 2 per row) ----
    {
        const int t  = tid >> 1;
        const int d0 = (tid & 1) << 5;
        float s = 0.f;
        if ((tid & 1) == 0) {
#pragma unroll
            for (int j = 0; j < 4; j++)
                s += *(float*)(dsm + OFF_DENP + (t * 4 + j) * 4);
        }
        const float* z = g_zp + ((size_t)bh * Nch + c) * Hd + d0;
#pragma unroll
        for (int d = 0; d < 32; d++) {
            const uint16_t hb = *(const uint16_t*)(dsm + OFF_QH + (t * QK_STR + d0 + d) * 2);
            const uint16_t lb = *(const uint16_t*)(dsm + OFF_QL + (t * QK_STR + d0 + d) * 2);
            s = fmaf(h2f16(hb) + h2f16(lb), z[d], s);
        }
        s += __shfl_xor_sync(0xffffffffu, s, 1);
        if ((tid & 1) == 0) *(float*)(dsm + OFF_DEN + t * 4) = s;
    }
    __syncthreads();

    // ---- phase 2: num = sc@V (K=128) + q@Sx (K=64), 128x64, 2-term ----
    float a2[4][2][4];
#pragma unroll
    for (int i = 0; i < 4; i++)
#pragma unroll
        for (int j = 0; j < 2; j++)
#pragma unroll
            for (int r = 0; r < 4; r++) a2[i][j][r] = 0.f;

#pragma unroll
    for (int ksk = 0; ksk < 128; ksk += 16) {
        uint32_t bh2[2][2];
        const uint32_t krow = (uint32_t)(ksk + (lane & 15));
#pragma unroll
        for (int an = 0; an < 2; an++) {
            const uint32_t n0 = (uint32_t)(wn * 16 + an * 8);
            const uint32_t off = (krow * QK_STR + n0) * 2;
            ldsm_x2_t(bh2[an], sb + OFF_VH + off);
        }
        const uint32_t arow = (uint32_t)(wm * 64 + (lane & 15));
        const uint32_t ak_  = (uint32_t)(ksk + (lane >> 4) * 8);
#pragma unroll
        for (int am = 0; am < 4; am++) {
            uint32_t ah_[4], al_[4];
            const uint32_t off = ((arow + am * 16) * SC_STR + ak_) * 2;
            ldsm_x4(ah_, sb + OFF_SCH + off);
            ldsm_x4(al_, sb + OFF_SCL + off);
#pragma unroll
            for (int an = 0; an < 2; an++) {
                mma_f16(a2[am][an], ah_, bh2[an]);
                mma_f16(a2[am][an], al_, bh2[an]);
            }
        }
    }
#pragma unroll
    for (int ksk = 0; ksk < 64; ksk += 16) {
        uint32_t bh2[2][2];
        const uint32_t krow = (uint32_t)(ksk + (lane & 15));
#pragma unroll
        for (int an = 0; an < 2; an++) {
            const uint32_t n0 = (uint32_t)(wn * 16 + an * 8);
            const uint32_t off = (krow * QK_STR + n0) * 2;
            ldsm_x2_t(bh2[an], sb + OFF_SXH + off);
        }
        const uint32_t arow = (uint32_t)(wm * 64 + (lane & 15));
        const uint32_t ak_  = (uint32_t)(ksk + (lane >> 4) * 8);
#pragma unroll
        for (int am = 0; am < 4; am++) {
            uint32_t ah_[4], al_[4];
            const uint32_t off = ((arow + am * 16) * QK_STR + ak_) * 2;
            ldsm_x4(ah_, sb + OFF_QH + off);
            ldsm_x4(al_, sb + OFF_QL + off);
#pragma unroll
            for (int an = 0; an < 2; an++) {
                mma_f16(a2[am][an], ah_, bh2[an]);
                mma_f16(a2[am][an], al_, bh2[an]);
            }
        }
    }

    // ---- epilogue: divide by den, write fp16 hi att ----
    const int b = bh >> 4, h = bh & 15;
#pragma unroll
    for (int am = 0; am < 4; am++) {
        const int t0r = wm * 64 + am * 16 + fr;
        const float inv0 = 1.f / *(const float*)(dsm + OFF_DEN + t0r * 4);
        const float inv1 = 1.f / *(const float*)(dsm + OFF_DEN + (t0r + 8) * 4);
#pragma unroll
        for (int an = 0; an < 2; an++) {
            const int e0 = wn * 16 + an * 8 + fc;
            const size_t idx0 = ((size_t)b * Sq + (size_t)c * Ck + t0r) * Dm + h * Hd + e0;
            *(uint32_t*)(g_ath + idx0) =
                cvt_hi(a2[am][an][0] * inv0, a2[am][an][1] * inv0);
            *(uint32_t*)(g_ath + idx0 + (size_t)8 * Dm) =
                cvt_hi(a2[am][an][2] * inv1, a2[am][an][3] * inv1);
        }
    }
}

// ---------------------------------------------------------------------------
extern "C" void kernel_launch(void* const* d_in, const int* in_sizes, int n_in,
                              void* d_out, int out_size)
{
    const float* x = nullptr;
    const float* Ws[4] = {nullptr, nullptr, nullptr, nullptr};
    const float* bs[4] = {nullptr, nullptr, nullptr, nullptr};
    int wi = 0, bi = 0;
    for (int i = 0; i < n_in; i++) {
        const int sz = in_sizes[i];
        if (sz == Mtot * Dm)      { x = (const float*)d_in[i]; }
        else if (sz == DD)        { if (wi < 4) Ws[wi++] = (const float*)d_in[i]; }
        else if (sz == Dm)        { if (bi < 4) bs[bi++] = (const float*)d_in[i]; }
    }
    float* out = (float*)d_out;

    // TRUE device addresses (never pass __device__ symbols from host — ATS!)
    float *psp;
    uint16_t *pxh, *pwh, *pqh, *pql, *pkh, *pkl, *pvh, *pvl, *psph, *path;
    cudaGetSymbolAddress((void**)&psp,  g_Sp);
    cudaGetSymbolAddress((void**)&pxh,  g_xh);
    cudaGetSymbolAddress((void**)&pwh,  g_wh);
    cudaGetSymbolAddress((void**)&pqh,  g_qh);
    cudaGetSymbolAddress((void**)&pql,  g_ql);
    cudaGetSymbolAddress((void**)&pkh,  g_kh);
    cudaGetSymbolAddress((void**)&pkl,  g_kl);
    cudaGetSymbolAddress((void**)&pvh,  g_vh);
    cudaGetSymbolAddress((void**)&pvl,  g_vl);
    cudaGetSymbolAddress((void**)&psph, g_sph);
    cudaGetSymbolAddress((void**)&path, g_ath);

    cudaFuncSetAttribute(fp_gemm_k<0>, cudaFuncAttributeMaxDynamicSharedMemorySize, GEMM_DSMEM);
    cudaFuncSetAttribute(fp_gemm_k<1>, cudaFuncAttributeMaxDynamicSharedMemorySize, GEMM_DSMEM);
    cudaFuncSetAttribute(fp_gemm_k<2>, cudaFuncAttributeMaxDynamicSharedMemorySize, GEMM_DSMEM);
    cudaFuncSetAttribute(attn_fused_k, cudaFuncAttributeMaxDynamicSharedMemorySize, ATTN_SMEM);

    // Pre-convert operands to fp16 hi (once).
    cvt_hi_k<<<4096, 256>>>(x, pxh, Mtot * Dm / 8);
    for (int i = 0; i < 4; i++)
        cvt_hi_k<<<512, 256>>>(Ws[i], pwh + (size_t)i * DD, DD / 8);

    const dim3 gg(Dm / 256, Mtot / 128);   // (4, 128)
    fp_gemm_k<1><<<gg, 512, GEMM_DSMEM>>>(pxh, pwh + 0 * (size_t)DD,
                                          bs[0], nullptr, pqh, pql);
    fp_gemm_k<1><<<gg, 512, GEMM_DSMEM>>>(pxh, pwh + 1 * (size_t)DD,
                                          bs[1], nullptr, pkh, pkl);
    fp_gemm_k<2><<<gg, 512, GEMM_DSMEM>>>(pxh, pwh + 2 * (size_t)DD,
                                          bs[2], nullptr, pvh, pvl);

    chunk_kv_k<<<dim3(Nch, BHn), 256>>>();
    scan_k<<<BHn, 256>>>();
    cvt_hi_k<<<2048, 256>>>(psp, psph, BHn * Nch * Hd * Hd / 8);
    attn_fused_k<<<dim3(Nch, BHn), 256, ATTN_SMEM>>>();

    fp_gemm_k<0><<<gg, 512, GEMM_DSMEM>>>(path, pwh + 3 * (size_t)DD,
                                          bs[3], out, nullptr, nullptr);
}

// round 16
// speedup vs baseline: 2.6246x; 1.1143x over previous
#include <cuda_runtime.h>
#include <cuda_fp16.h>
#include <cstdint>

// ---------------------------------------------------------------------------
// LinearMultiheadAttention: x:(4,4096,1024), 16 heads x 64 dim, chunk 128.
// R16: uniform 1-term fp16 (calibrated error model: 19 dropped terms x
// 1.27e-4 in quadrature -> ~5.6e-4, budget 1e-3). Attention smem 102KB ->
// 2 CTAs/SM. chunk_kv hi-only loads. den fp32 from q-hi.
// RULE: __device__ symbols passed as kernel args MUST go through
// cudaGetSymbolAddress (GB300 ATS makes the host-shadow silently writable).
// ---------------------------------------------------------------------------

// ---------------- tensor-core helpers (sm_80 baseline ISA) ----------------
__device__ __forceinline__ uint32_t smem_u32(const void* p) {
    return (uint32_t)__cvta_generic_to_shared(p);
}
__device__ __forceinline__ void ldsm_x4(uint32_t* r, uint32_t addr) {
    asm volatile("ldmatrix.sync.aligned.m8n8.x4.shared.b16 {%0,%1,%2,%3}, [%4];"
                 : "=r"(r[0]), "=r"(r[1]), "=r"(r[2]), "=r"(r[3]) : "r"(addr));
}
__device__ __forceinline__ void ldsm_x2(uint32_t* r, uint32_t addr) {
    asm volatile("ldmatrix.sync.aligned.m8n8.x2.shared.b16 {%0,%1}, [%2];"
                 : "=r"(r[0]), "=r"(r[1]) : "r"(addr));
}
__device__ __forceinline__ void ldsm_x2_t(uint32_t* r, uint32_t addr) {
    asm volatile("ldmatrix.sync.aligned.m8n8.x2.trans.shared.b16 {%0,%1}, [%2];"
                 : "=r"(r[0]), "=r"(r[1]) : "r"(addr));
}
__device__ __forceinline__ void mma_f16(float* c, const uint32_t* a, const uint32_t* b) {
    asm volatile(
        "mma.sync.aligned.m16n8k16.row.col.f32.f16.f16.f32 "
        "{%0,%1,%2,%3}, {%4,%5,%6,%7}, {%8,%9}, {%0,%1,%2,%3};"
        : "+f"(c[0]), "+f"(c[1]), "+f"(c[2]), "+f"(c[3])
        : "r"(a[0]), "r"(a[1]), "r"(a[2]), "r"(a[3]), "r"(b[0]), "r"(b[1]));
}
__device__ __forceinline__ void cp_async16(uint32_t smem, const void* g) {
    asm volatile("cp.async.cg.shared.global [%0], [%1], 16;" :: "r"(smem), "l"(g));
}
__device__ __forceinline__ void cp_commit() {
    asm volatile("cp.async.commit_group;" ::: "memory");
}
__device__ __forceinline__ void cp_wait0() {
    asm volatile("cp.async.wait_group 0;" ::: "memory");
}
__device__ __forceinline__ void cp_wait1() {
    asm volatile("cp.async.wait_group 1;" ::: "memory");
}
__device__ __forceinline__ uint32_t cvt_hi(float y0, float y1)
{
    __half2 h2 = __floats2half2_rn(y0, y1);
    return *reinterpret_cast<uint32_t*>(&h2);
}
__device__ __forceinline__ float h2f16(uint16_t u) {
    return __half2float(__ushort_as_half(u));
}
__device__ __forceinline__ float u32lo(uint32_t u) { return h2f16((uint16_t)(u & 0xFFFFu)); }
__device__ __forceinline__ float u32hi(uint32_t u) { return h2f16((uint16_t)(u >> 16)); }

constexpr int Bn   = 4;
constexpr int Sq   = 4096;
constexpr int Dm   = 1024;
constexpr int Hn   = 16;
constexpr int Hd   = 64;
constexpr int Mtot = Bn * Sq;     // 16384
constexpr int Ck   = 128;
constexpr int Nch  = Sq / Ck;     // 32
constexpr int BHn  = Bn * Hn;     // 64
constexpr int DD   = Dm * Dm;

__device__ __align__(16) float g_Sp[(size_t)BHn * Nch * Hd * Hd];
__device__ __align__(16) float g_zp[(size_t)BHn * Nch * Hd];
// fp16 hi operands
__device__ __align__(16) uint16_t g_xh[(size_t)Mtot * Dm];
__device__ __align__(16) uint16_t g_wh[(size_t)4 * DD];
__device__ __align__(16) uint16_t g_qh[(size_t)Mtot * Dm];
__device__ __align__(16) uint16_t g_kh[(size_t)Mtot * Dm];
__device__ __align__(16) uint16_t g_vh[(size_t)Mtot * Dm];
__device__ __align__(16) uint16_t g_sph[(size_t)BHn * Nch * Hd * Hd];
__device__ __align__(16) uint16_t g_ath[(size_t)Mtot * Dm];

// ---------------------------------------------------------------------------
// fp32 -> fp16 hi only, 8 elems/thread, grid-stride.
// ---------------------------------------------------------------------------
__global__ void __launch_bounds__(256)
cvt_hi_k(const float* __restrict__ src, uint16_t* __restrict__ hi, int n8)
{
    int i = blockIdx.x * blockDim.x + threadIdx.x;
    const int stride = gridDim.x * blockDim.x;
    for (; i < n8; i += stride) {
        const float4 f0 = ((const float4*)src)[2 * i];
        const float4 f1 = ((const float4*)src)[2 * i + 1];
        uint4 h;
        h.x = cvt_hi(f0.x, f0.y);
        h.y = cvt_hi(f0.z, f0.w);
        h.z = cvt_hi(f1.x, f1.y);
        h.w = cvt_hi(f1.z, f1.w);
        ((uint4*)hi)[i] = h;
    }
}

// ---------------------------------------------------------------------------
// HMMA GEMM, fp16 1-term: Y ~= Ah . Bh^T + bias.
// MODE 0: fp32 plain | MODE 1: phi + hi permuted | MODE 2: hi permuted
// Tile 128(M) x 256(N), BK=32, 512 threads, 16 warps (2m x 8n), warp 64x32.
// cp.async 2-stage pipeline, 60KB smem.
// ---------------------------------------------------------------------------
constexpr int BK  = 32;
constexpr int LDK = 40;                        // padded smem row (80B)
constexpr int A_TILE_B = 128 * LDK * 2;        // 10240
constexpr int B_TILE_B = 256 * LDK * 2;        // 20480
constexpr int STAGE_B  = A_TILE_B + B_TILE_B;  // 30720
constexpr int GEMM_DSMEM = 2 * STAGE_B;        // 61440

template <int MODE>
__global__ void __launch_bounds__(512)
fp_gemm_k(const uint16_t* __restrict__ Ah_g, const uint16_t* __restrict__ Bh_g,
          const float* __restrict__ bias, float* __restrict__ out,
          uint16_t* __restrict__ outh)
{
    extern __shared__ char dsm[];
    const uint32_t sbase = smem_u32(dsm);

    const int tid  = threadIdx.x;
    const int lane = tid & 31;
    const int wid  = tid >> 5;        // 0..15
    const int wm   = wid >> 3;        // 0..1
    const int wn   = wid & 7;         // 0..7
    const int bm   = blockIdx.y << 7;   // M tile 128
    const int bn   = blockIdx.x << 8;   // N tile 256

    const int lrow  = tid >> 1;
    const int lhalf = (tid & 1) << 4;
    const uint16_t* pBh = Bh_g + (size_t)(bn + lrow) * Dm + lhalf;
    const uint16_t* pAh = Ah_g + (size_t)(bm + (lrow & 127)) * Dm + lhalf;
    const uint32_t sbA = (uint32_t)((lrow & 127) * LDK + lhalf) * 2;
    const uint32_t sbB = (uint32_t)(lrow * LDK + lhalf) * 2;

    float acc[4][4][4];
#pragma unroll
    for (int i = 0; i < 4; i++)
#pragma unroll
        for (int j = 0; j < 4; j++)
#pragma unroll
            for (int r = 0; r < 4; r++) acc[i][j][r] = 0.f;

#define ISSUE(stage, kc) do {                                                  \
        const uint32_t s0 = sbase + (stage) * STAGE_B;                         \
        const size_t go = (size_t)(kc) * BK;                                   \
        if (tid < 256) {                                                       \
            cp_async16(s0 + sbA,      pAh + go);                               \
            cp_async16(s0 + sbA + 16, pAh + go + 8);                           \
        }                                                                      \
        const uint32_t b0 = s0 + A_TILE_B;                                     \
        cp_async16(b0 + sbB,      pBh + go);                                   \
        cp_async16(b0 + sbB + 16, pBh + go + 8);                               \
        cp_commit();                                                           \
    } while (0)

    constexpr int NK = Dm / BK;
    ISSUE(0, 0);

    for (int kc = 0; kc < NK; kc++) {
        cp_wait0();
        __syncthreads();
        if (kc + 1 < NK) ISSUE((kc + 1) & 1, kc + 1);

        const uint32_t st = sbase + (kc & 1) * STAGE_B;
        const uint32_t aB = st;
        const uint32_t bB = st + A_TILE_B;

#pragma unroll
        for (int ks = 0; ks < BK; ks += 16) {
            uint32_t bh_[4][2];
            const uint32_t brow = (uint32_t)(wn * 32 + (lane & 7));
            const uint32_t bk_  = (uint32_t)(ks + ((lane >> 3) & 1) * 8);
#pragma unroll
            for (int an = 0; an < 4; an++) {
                const uint32_t off = ((brow + an * 8) * LDK + bk_) * 2;
                ldsm_x2(bh_[an], bB + off);
            }
            const uint32_t arow = (uint32_t)(wm * 64 + (lane & 15));
            const uint32_t ak_  = (uint32_t)(ks + (lane >> 4) * 8);
#pragma unroll
            for (int am = 0; am < 4; am++) {
                uint32_t ah_[4];
                const uint32_t off = ((arow + am * 16) * LDK + ak_) * 2;
                ldsm_x4(ah_, aB + off);
#pragma unroll
                for (int an = 0; an < 4; an++)
                    mma_f16(acc[am][an], ah_, bh_[an]);
            }
        }
    }
#undef ISSUE

    const int fr = lane >> 2;
    const int fc = (lane & 3) << 1;
#pragma unroll
    for (int am = 0; am < 4; am++) {
        const int m0 = bm + wm * 64 + am * 16 + fr;
#pragma unroll
        for (int an = 0; an < 4; an++) {
            const int c = bn + wn * 32 + an * 8 + fc;
            const float b0 = bias[c], b1 = bias[c + 1];
#pragma unroll
            for (int half = 0; half < 2; half++) {
                const int m = m0 + half * 8;
                float y0 = acc[am][an][2 * half]     + b0;
                float y1 = acc[am][an][2 * half + 1] + b1;
                if (MODE == 1) {
                    y0 = (y0 > 0.f) ? (y0 + 1.f) : __expf(y0);
                    y1 = (y1 > 0.f) ? (y1 + 1.f) : __expf(y1);
                }
                if (MODE == 0) {
                    *(float2*)(out + (size_t)m * Dm + c) = make_float2(y0, y1);
                } else {
                    const int b  = m >> 12;
                    const int s  = m & 4095;
                    const int h  = c >> 6;
                    const int e0 = c & 63;
                    const size_t idx = ((size_t)(b * Hn + h) * Sq + s) * Hd + e0;
                    *(uint32_t*)(outh + idx) = cvt_hi(y0, y1);
                }
            }
        }
    }
}

// ---------------------------------------------------------------------------
// Per-chunk partials (fp16-hi inputs, fp32 accum): Sp = sum_t k^T v; zp = sum_t k
// ---------------------------------------------------------------------------
__global__ void __launch_bounds__(256)
chunk_kv_k()
{
    __shared__ __align__(16) float ks[64 * Hd];
    __shared__ __align__(16) float vs[64 * Hd];
    const int c   = blockIdx.x;
    const int bh  = blockIdx.y;
    const int tid = threadIdx.x;
    const size_t base = ((size_t)bh * Sq + (size_t)c * Ck) * Hd;

    const int r  = tid & 63;
    const int j0 = (tid >> 6) << 4;

    float acc[16];
#pragma unroll
    for (int j = 0; j < 16; j++) acc[j] = 0.f;
    float zacc = 0.f;

    for (int half = 0; half < 2; half++) {
        const size_t hb = base + (size_t)half * 64 * Hd;
        __syncthreads();
        for (int i = tid; i < 64 * Hd / 4; i += 256) {
            const uint2 kh = ((const uint2*)(g_kh + hb))[i];
            const uint2 vh = ((const uint2*)(g_vh + hb))[i];
            ((float4*)ks)[i] = make_float4(u32lo(kh.x), u32hi(kh.x),
                                           u32lo(kh.y), u32hi(kh.y));
            ((float4*)vs)[i] = make_float4(u32lo(vh.x), u32hi(vh.x),
                                           u32lo(vh.y), u32hi(vh.y));
        }
        __syncthreads();
        for (int t = 0; t < 64; t++) {
            const float kv = ks[t * Hd + r];
            zacc += kv;
#pragma unroll
            for (int j = 0; j < 16; j++)
                acc[j] = fmaf(kv, vs[t * Hd + j0 + j], acc[j]);
        }
    }

    float* Sd = g_Sp + ((size_t)bh * Nch + c) * (Hd * Hd) + r * Hd + j0;
#pragma unroll
    for (int j = 0; j < 16; j++) Sd[j] = acc[j];
    if (tid < Hd) g_zp[((size_t)bh * Nch + c) * Hd + tid] = zacc;
}

// ---------------------------------------------------------------------------
__global__ void __launch_bounds__(256)
scan_k()
{
    const int bh = blockIdx.x;
    float* Sb = g_Sp + (size_t)bh * Nch * Hd * Hd;
    for (int e = threadIdx.x; e < Hd * Hd; e += 256) {
        float acc = 0.f;
        for (int c2 = 0; c2 < Nch; c2++) {
            const float v = Sb[(size_t)c2 * Hd * Hd + e];
            Sb[(size_t)c2 * Hd * Hd + e] = acc;
            acc += v;
        }
    }
    if (threadIdx.x < Hd) {
        float* zb = g_zp + (size_t)bh * Nch * Hd + threadIdx.x;
        float acc = 0.f;
        for (int c2 = 0; c2 < Nch; c2++) {
            const float v = zb[(size_t)c2 * Hd];
            zb[(size_t)c2 * Hd] = acc;
            acc += v;
        }
    }
}

// ---------------------------------------------------------------------------
// Fused attention per (chunk, bh): 1-term fp16. 102KB smem -> 2 CTAs/SM.
// cp.async everything; v/Sx prefetch rides under phase-1 MMAs.
// ---------------------------------------------------------------------------
constexpr int QK_STR = 72;    // fp16 elems/row (144B)
constexpr int SC_STR = 136;   // (272B)
constexpr int OFF_QH  = 0;
constexpr int OFF_KH  = OFF_QH + 128 * QK_STR * 2;   // 18432
constexpr int OFF_VH  = OFF_KH + 18432;              // 36864
constexpr int OFF_SXH = OFF_VH + 18432;              // 55296
constexpr int OFF_SCH = OFF_SXH + 64 * QK_STR * 2;   // 64512
constexpr int OFF_DEN = OFF_SCH + 128 * SC_STR * 2;  // 99328
constexpr int OFF_DENP = OFF_DEN + 512;              // 99840
constexpr int ATTN_SMEM = OFF_DENP + 2048;           // 101888

__global__ void __launch_bounds__(256)
attn_fused_k()
{
    extern __shared__ char dsm[];
    const uint32_t sb = smem_u32(dsm);
    const int c    = blockIdx.x;
    const int bh   = blockIdx.y;
    const int tid  = threadIdx.x;
    const int lane = tid & 31;
    const int wid  = tid >> 5;
    const int wm   = wid >> 2;
    const int wn   = wid & 3;
    const size_t base = ((size_t)bh * Sq + (size_t)c * Ck) * Hd;

    // ---- group 1: q hi, k hi ----
    for (int i = tid; i < 128 * 8; i += 256) {
        const uint32_t so = (uint32_t)((i >> 3) * (QK_STR * 2) + (i & 7) * 16);
        const size_t g = base + (size_t)(i >> 3) * Hd + (i & 7) * 8;
        cp_async16(sb + OFF_QH + so, g_qh + g);
        cp_async16(sb + OFF_KH + so, g_kh + g);
    }
    cp_commit();
    // ---- group 2: v hi, Sx hi (lands during phase 1) ----
    {
        const size_t sxb = ((size_t)bh * Nch + c) * (Hd * Hd);
        for (int i = tid; i < 128 * 8; i += 256) {
            const uint32_t so = (uint32_t)((i >> 3) * (QK_STR * 2) + (i & 7) * 16);
            const size_t g = base + (size_t)(i >> 3) * Hd + (i & 7) * 8;
            cp_async16(sb + OFF_VH + so, g_vh + g);
            if (i < 64 * 8) {
                const size_t gx = sxb + (size_t)(i >> 3) * Hd + (i & 7) * 8;
                cp_async16(sb + OFF_SXH + so, g_sph + gx);
            }
        }
        cp_commit();
    }
    cp_wait1();         // q,k ready (v,Sx still in flight)
    __syncthreads();

    const int fr = lane >> 2;
    const int fc = (lane & 3) << 1;

    // ---- phase 1: sc = q.k^T (128x128, K=64), 1-term ----
    {
        float acc[4][4][4];
#pragma unroll
        for (int i = 0; i < 4; i++)
#pragma unroll
            for (int j = 0; j < 4; j++)
#pragma unroll
                for (int r = 0; r < 4; r++) acc[i][j][r] = 0.f;

#pragma unroll
        for (int ksk = 0; ksk < 64; ksk += 16) {
            uint32_t bh_[4][2];
            const uint32_t brow = (uint32_t)(wn * 32 + (lane & 7));
            const uint32_t bk_  = (uint32_t)(ksk + ((lane >> 3) & 1) * 8);
#pragma unroll
            for (int an = 0; an < 4; an++) {
                const uint32_t off = ((brow + an * 8) * QK_STR + bk_) * 2;
                ldsm_x2(bh_[an], sb + OFF_KH + off);
            }
            const uint32_t arow = (uint32_t)(wm * 64 + (lane & 15));
            const uint32_t ak_  = (uint32_t)(ksk + (lane >> 4) * 8);
#pragma unroll
            for (int am = 0; am < 4; am++) {
                uint32_t ah_[4];
                const uint32_t off = ((arow + am * 16) * QK_STR + ak_) * 2;
                ldsm_x4(ah_, sb + OFF_QH + off);
#pragma unroll
                for (int an = 0; an < 4; an++)
                    mma_f16(acc[am][an], ah_, bh_[an]);
            }
        }

        // mask + row-sum partials + fp16-hi store to smem
        float rs[8];
#pragma unroll
        for (int i = 0; i < 8; i++) rs[i] = 0.f;
#pragma unroll
        for (int am = 0; am < 4; am++) {
            const int t0r = wm * 64 + am * 16 + fr;
#pragma unroll
            for (int an = 0; an < 4; an++) {
                const int u0 = wn * 32 + an * 8 + fc;
#pragma unroll
                for (int half = 0; half < 2; half++) {
                    const int t = t0r + half * 8;
                    float v0 = (u0     <= t) ? acc[am][an][2 * half]     : 0.f;
                    float v1 = (u0 + 1 <= t) ? acc[am][an][2 * half + 1] : 0.f;
                    rs[am * 2 + half] += v0 + v1;
                    *(uint32_t*)(dsm + OFF_SCH + (t * SC_STR + u0) * 2) =
                        cvt_hi(v0, v1);
                }
            }
        }
#pragma unroll
        for (int idx = 0; idx < 8; idx++) {
            float s = rs[idx];
            s += __shfl_xor_sync(0xffffffffu, s, 1);
            s += __shfl_xor_sync(0xffffffffu, s, 2);
            if ((lane & 3) == 0) {
                const int row = wm * 64 + (idx >> 1) * 16 + fr + (idx & 1) * 8;
                *(float*)(dsm + OFF_DENP + (row * 4 + wn) * 4) = s;
            }
        }
    }
    cp_wait0();         // v, Sx ready
    __syncthreads();

    // ---- den (parallel over 256 threads: 2 per row) ----
    {
        const int t  = tid >> 1;
        const int d0 = (tid & 1) << 5;
        float s = 0.f;
        if ((tid & 1) == 0) {
#pragma unroll
            for (int j = 0; j < 4; j++)
                s += *(float*)(dsm + OFF_DENP + (t * 4 + j) * 4);
        }
        const float* z = g_zp + ((size_t)bh * Nch + c) * Hd + d0;
#pragma unroll
        for (int d = 0; d < 32; d++) {
            const uint16_t hb = *(const uint16_t*)(dsm + OFF_QH + (t * QK_STR + d0 + d) * 2);
            s = fmaf(h2f16(hb), z[d], s);
        }
        s += __shfl_xor_sync(0xffffffffu, s, 1);
        if ((tid & 1) == 0) *(float*)(dsm + OFF_DEN + t * 4) = s;
    }
    __syncthreads();

    // ---- phase 2: num = sc@V (K=128) + q@Sx (K=64), 128x64, 1-term ----
    float a2[4][2][4];
#pragma unroll
    for (int i = 0; i < 4; i++)
#pragma unroll
        for (int j = 0; j < 2; j++)
#pragma unroll
            for (int r = 0; r < 4; r++) a2[i][j][r] = 0.f;

#pragma unroll
    for (int ksk = 0; ksk < 128; ksk += 16) {
        uint32_t bh2[2][2];
        const uint32_t krow = (uint32_t)(ksk + (lane & 15));
#pragma unroll
        for (int an = 0; an < 2; an++) {
            const uint32_t n0 = (uint32_t)(wn * 16 + an * 8);
            const uint32_t off = (krow * QK_STR + n0) * 2;
            ldsm_x2_t(bh2[an], sb + OFF_VH + off);
        }
        const uint32_t arow = (uint32_t)(wm * 64 + (lane & 15));
        const uint32_t ak_  = (uint32_t)(ksk + (lane >> 4) * 8);
#pragma unroll
        for (int am = 0; am < 4; am++) {
            uint32_t ah_[4];
            const uint32_t off = ((arow + am * 16) * SC_STR + ak_) * 2;
            ldsm_x4(ah_, sb + OFF_SCH + off);
#pragma unroll
            for (int an = 0; an < 2; an++)
                mma_f16(a2[am][an], ah_, bh2[an]);
        }
    }
#pragma unroll
    for (int ksk = 0; ksk < 64; ksk += 16) {
        uint32_t bh2[2][2];
        const uint32_t krow = (uint32_t)(ksk + (lane & 15));
#pragma unroll
        for (int an = 0; an < 2; an++) {
            const uint32_t n0 = (uint32_t)(wn * 16 + an * 8);
            const uint32_t off = (krow * QK_STR + n0) * 2;
            ldsm_x2_t(bh2[an], sb + OFF_SXH + off);
        }
        const uint32_t arow = (uint32_t)(wm * 64 + (lane & 15));
        const uint32_t ak_  = (uint32_t)(ksk + (lane >> 4) * 8);
#pragma unroll
        for (int am = 0; am < 4; am++) {
            uint32_t ah_[4];
            const uint32_t off = ((arow + am * 16) * QK_STR + ak_) * 2;
            ldsm_x4(ah_, sb + OFF_QH + off);
#pragma unroll
            for (int an = 0; an < 2; an++)
                mma_f16(a2[am][an], ah_, bh2[an]);
        }
    }

    // ---- epilogue: divide by den, write fp16 hi att ----
    const int b = bh >> 4, h = bh & 15;
#pragma unroll
    for (int am = 0; am < 4; am++) {
        const int t0r = wm * 64 + am * 16 + fr;
        const float inv0 = 1.f / *(const float*)(dsm + OFF_DEN + t0r * 4);
        const float inv1 = 1.f / *(const float*)(dsm + OFF_DEN + (t0r + 8) * 4);
#pragma unroll
        for (int an = 0; an < 2; an++) {
            const int e0 = wn * 16 + an * 8 + fc;
            const size_t idx0 = ((size_t)b * Sq + (size_t)c * Ck + t0r) * Dm + h * Hd + e0;
            *(uint32_t*)(g_ath + idx0) =
                cvt_hi(a2[am][an][0] * inv0, a2[am][an][1] * inv0);
            *(uint32_t*)(g_ath + idx0 + (size_t)8 * Dm) =
                cvt_hi(a2[am][an][2] * inv1, a2[am][an][3] * inv1);
        }
    }
}

// ---------------------------------------------------------------------------
extern "C" void kernel_launch(void* const* d_in, const int* in_sizes, int n_in,
                              void* d_out, int out_size)
{
    const float* x = nullptr;
    const float* Ws[4] = {nullptr, nullptr, nullptr, nullptr};
    const float* bs[4] = {nullptr, nullptr, nullptr, nullptr};
    int wi = 0, bi = 0;
    for (int i = 0; i < n_in; i++) {
        const int sz = in_sizes[i];
        if (sz == Mtot * Dm)      { x = (const float*)d_in[i]; }
        else if (sz == DD)        { if (wi < 4) Ws[wi++] = (const float*)d_in[i]; }
        else if (sz == Dm)        { if (bi < 4) bs[bi++] = (const float*)d_in[i]; }
    }
    float* out = (float*)d_out;

    // TRUE device addresses (never pass __device__ symbols from host — ATS!)
    float *psp;
    uint16_t *pxh, *pwh, *pqh, *pkh, *pvh, *psph, *path;
    cudaGetSymbolAddress((void**)&psp,  g_Sp);
    cudaGetSymbolAddress((void**)&pxh,  g_xh);
    cudaGetSymbolAddress((void**)&pwh,  g_wh);
    cudaGetSymbolAddress((void**)&pqh,  g_qh);
    cudaGetSymbolAddress((void**)&pkh,  g_kh);
    cudaGetSymbolAddress((void**)&pvh,  g_vh);
    cudaGetSymbolAddress((void**)&psph, g_sph);
    cudaGetSymbolAddress((void**)&path, g_ath);

    cudaFuncSetAttribute(fp_gemm_k<0>, cudaFuncAttributeMaxDynamicSharedMemorySize, GEMM_DSMEM);
    cudaFuncSetAttribute(fp_gemm_k<1>, cudaFuncAttributeMaxDynamicSharedMemorySize, GEMM_DSMEM);
    cudaFuncSetAttribute(fp_gemm_k<2>, cudaFuncAttributeMaxDynamicSharedMemorySize, GEMM_DSMEM);
    cudaFuncSetAttribute(attn_fused_k, cudaFuncAttributeMaxDynamicSharedMemorySize, ATTN_SMEM);

    // Pre-convert operands to fp16 hi (once).
    cvt_hi_k<<<4096, 256>>>(x, pxh, Mtot * Dm / 8);
    for (int i = 0; i < 4; i++)
        cvt_hi_k<<<512, 256>>>(Ws[i], pwh + (size_t)i * DD, DD / 8);

    const dim3 gg(Dm / 256, Mtot / 128);   // (4, 128)
    fp_gemm_k<1><<<gg, 512, GEMM_DSMEM>>>(pxh, pwh + 0 * (size_t)DD, bs[0], nullptr, pqh);
    fp_gemm_k<1><<<gg, 512, GEMM_DSMEM>>>(pxh, pwh + 1 * (size_t)DD, bs[1], nullptr, pkh);
    fp_gemm_k<2><<<gg, 512, GEMM_DSMEM>>>(pxh, pwh + 2 * (size_t)DD, bs[2], nullptr, pvh);

    chunk_kv_k<<<dim3(Nch, BHn), 256>>>();
    scan_k<<<BHn, 256>>>();
    cvt_hi_k<<<2048, 256>>>(psp, psph, BHn * Nch * Hd * Hd / 8);
    attn_fused_k<<<dim3(Nch, BHn), 256, ATTN_SMEM>>>();

    fp_gemm_k<0><<<gg, 512, GEMM_DSMEM>>>(path, pwh + 3 * (size_t)DD, bs[3], out, nullptr);
}

// round 17
// speedup vs baseline: 2.7711x; 1.0558x over previous
#include <cuda_runtime.h>
#include <cuda_fp16.h>
#include <cstdint>

// ---------------------------------------------------------------------------
// LinearMultiheadAttention: x:(4,4096,1024), 16 heads x 64 dim, chunk 128.
// R17: 3-stage cp.async GEMM pipeline (wait_group 1); q/k/v GEMMs fused into
// ONE launch (wave packing); scan one-thread-per-element; chunk_kv float4.
// Precision unchanged from R16 (uniform 1-term fp16, rel_err ~4.8e-4).
// RULE: __device__ symbols passed as kernel args MUST go through
// cudaGetSymbolAddress (GB300 ATS makes the host-shadow silently writable).
// ---------------------------------------------------------------------------

__device__ __forceinline__ uint32_t smem_u32(const void* p) {
    return (uint32_t)__cvta_generic_to_shared(p);
}
__device__ __forceinline__ void ldsm_x4(uint32_t* r, uint32_t addr) {
    asm volatile("ldmatrix.sync.aligned.m8n8.x4.shared.b16 {%0,%1,%2,%3}, [%4];"
                 : "=r"(r[0]), "=r"(r[1]), "=r"(r[2]), "=r"(r[3]) : "r"(addr));
}
__device__ __forceinline__ void ldsm_x2(uint32_t* r, uint32_t addr) {
    asm volatile("ldmatrix.sync.aligned.m8n8.x2.shared.b16 {%0,%1}, [%2];"
                 : "=r"(r[0]), "=r"(r[1]) : "r"(addr));
}
__device__ __forceinline__ void ldsm_x2_t(uint32_t* r, uint32_t addr) {
    asm volatile("ldmatrix.sync.aligned.m8n8.x2.trans.shared.b16 {%0,%1}, [%2];"
                 : "=r"(r[0]), "=r"(r[1]) : "r"(addr));
}
__device__ __forceinline__ void mma_f16(float* c, const uint32_t* a, const uint32_t* b) {
    asm volatile(
        "mma.sync.aligned.m16n8k16.row.col.f32.f16.f16.f32 "
        "{%0,%1,%2,%3}, {%4,%5,%6,%7}, {%8,%9}, {%0,%1,%2,%3};"
        : "+f"(c[0]), "+f"(c[1]), "+f"(c[2]), "+f"(c[3])
        : "r"(a[0]), "r"(a[1]), "r"(a[2]), "r"(a[3]), "r"(b[0]), "r"(b[1]));
}
__device__ __forceinline__ void cp_async16(uint32_t smem, const void* g) {
    asm volatile("cp.async.cg.shared.global [%0], [%1], 16;" :: "r"(smem), "l"(g));
}
__device__ __forceinline__ void cp_commit() {
    asm volatile("cp.async.commit_group;" ::: "memory");
}
__device__ __forceinline__ void cp_wait0() {
    asm volatile("cp.async.wait_group 0;" ::: "memory");
}
__device__ __forceinline__ void cp_wait1() {
    asm volatile("cp.async.wait_group 1;" ::: "memory");
}
__device__ __forceinline__ uint32_t cvt_hi(float y0, float y1)
{
    __half2 h2 = __floats2half2_rn(y0, y1);
    return *reinterpret_cast<uint32_t*>(&h2);
}
__device__ __forceinline__ float h2f16(uint16_t u) {
    return __half2float(__ushort_as_half(u));
}
__device__ __forceinline__ float u32lo(uint32_t u) { return h2f16((uint16_t)(u & 0xFFFFu)); }
__device__ __forceinline__ float u32hi(uint32_t u) { return h2f16((uint16_t)(u >> 16)); }

constexpr int Bn   = 4;
constexpr int Sq   = 4096;
constexpr int Dm   = 1024;
constexpr int Hn   = 16;
constexpr int Hd   = 64;
constexpr int Mtot = Bn * Sq;     // 16384
constexpr int Ck   = 128;
constexpr int Nch  = Sq / Ck;     // 32
constexpr int BHn  = Bn * Hn;     // 64
constexpr int DD   = Dm * Dm;

__device__ __align__(16) float g_Sp[(size_t)BHn * Nch * Hd * Hd];
__device__ __align__(16) float g_zp[(size_t)BHn * Nch * Hd];
__device__ __align__(16) uint16_t g_xh[(size_t)Mtot * Dm];
__device__ __align__(16) uint16_t g_wh[(size_t)4 * DD];
__device__ __align__(16) uint16_t g_qh[(size_t)Mtot * Dm];
__device__ __align__(16) uint16_t g_kh[(size_t)Mtot * Dm];
__device__ __align__(16) uint16_t g_vh[(size_t)Mtot * Dm];
__device__ __align__(16) uint16_t g_sph[(size_t)BHn * Nch * Hd * Hd];
__device__ __align__(16) uint16_t g_ath[(size_t)Mtot * Dm];

// ---------------------------------------------------------------------------
__global__ void __launch_bounds__(256)
cvt_hi_k(const float* __restrict__ src, uint16_t* __restrict__ hi, int n8)
{
    int i = blockIdx.x * blockDim.x + threadIdx.x;
    const int stride = gridDim.x * blockDim.x;
    for (; i < n8; i += stride) {
        const float4 f0 = ((const float4*)src)[2 * i];
        const float4 f1 = ((const float4*)src)[2 * i + 1];
        uint4 h;
        h.x = cvt_hi(f0.x, f0.y);
        h.y = cvt_hi(f0.z, f0.w);
        h.z = cvt_hi(f1.x, f1.y);
        h.w = cvt_hi(f1.z, f1.w);
        ((uint4*)hi)[i] = h;
    }
}

// ---------------------------------------------------------------------------
// HMMA GEMM core, fp16 1-term, 3-stage cp.async pipeline.
// Tile 128(M) x 256(N), BK=32, 512 threads, 16 warps (2m x 8n), warp 64x32.
// FUSED=1: grid.x spans 3 weight matrices (q,k,v); wsel = bn>>10.
// FUSED=0: single output GEMM to fp32 out.
// ---------------------------------------------------------------------------
constexpr int BK  = 32;
constexpr int LDK = 40;                        // padded smem row (80B)
constexpr int A_TILE_B = 128 * LDK * 2;        // 10240
constexpr int B_TILE_B = 256 * LDK * 2;        // 20480
constexpr int STAGE_B  = A_TILE_B + B_TILE_B;  // 30720
constexpr int GEMM_DSMEM = 3 * STAGE_B;        // 92160

template <int FUSED>
__global__ void __launch_bounds__(512)
fp_gemm_k(const uint16_t* __restrict__ Ah_g, const uint16_t* __restrict__ Wh_g,
          const float* __restrict__ b0p, const float* __restrict__ b1p,
          const float* __restrict__ b2p, float* __restrict__ out,
          uint16_t* __restrict__ o0, uint16_t* __restrict__ o1,
          uint16_t* __restrict__ o2)
{
    extern __shared__ char dsm[];
    const uint32_t sbase = smem_u32(dsm);

    const int tid  = threadIdx.x;
    const int lane = tid & 31;
    const int wid  = tid >> 5;
    const int wm   = wid >> 3;
    const int wn   = wid & 7;
    const int bm   = blockIdx.y << 7;
    const int bn_g = blockIdx.x << 8;
    const int wsel = FUSED ? (bn_g >> 10) : 0;
    const int bn   = FUSED ? (bn_g & 1023) : bn_g;

    const float* bias = b0p;
    uint16_t* outh = o0;
    if (FUSED) {
        if (wsel == 1) { bias = b1p; outh = o1; }
        else if (wsel == 2) { bias = b2p; outh = o2; }
    }
    const uint16_t* Bh_g = Wh_g + (FUSED ? (size_t)wsel * DD : 0);

    const int lrow  = tid >> 1;
    const int lhalf = (tid & 1) << 4;
    const uint16_t* pBh = Bh_g + (size_t)(bn + lrow) * Dm + lhalf;
    const uint16_t* pAh = Ah_g + (size_t)(bm + (lrow & 127)) * Dm + lhalf;
    const uint32_t sbA = (uint32_t)((lrow & 127) * LDK + lhalf) * 2;
    const uint32_t sbB = (uint32_t)(lrow * LDK + lhalf) * 2;

    float acc[4][4][4];
#pragma unroll
    for (int i = 0; i < 4; i++)
#pragma unroll
        for (int j = 0; j < 4; j++)
#pragma unroll
            for (int r = 0; r < 4; r++) acc[i][j][r] = 0.f;

#define ISSUE(stage, kc) do {                                                  \
        const uint32_t s0 = sbase + (stage) * STAGE_B;                         \
        const size_t go = (size_t)(kc) * BK;                                   \
        if (tid < 256) {                                                       \
            cp_async16(s0 + sbA,      pAh + go);                               \
            cp_async16(s0 + sbA + 16, pAh + go + 8);                           \
        }                                                                      \
        const uint32_t b0s = s0 + A_TILE_B;                                    \
        cp_async16(b0s + sbB,      pBh + go);                                  \
        cp_async16(b0s + sbB + 16, pBh + go + 8);                              \
        cp_commit();                                                           \
    } while (0)

    constexpr int NK = Dm / BK;   // 32
    ISSUE(0, 0);
    ISSUE(1, 1);

    for (int kc = 0; kc < NK; kc++) {
        cp_wait1();               // stage kc landed (kc+1 may be in flight)
        __syncthreads();          // all warps done with stage (kc+2)%3's old data
        if (kc + 2 < NK) ISSUE((kc + 2) % 3, kc + 2);

        const uint32_t st = sbase + (kc % 3) * STAGE_B;
        const uint32_t aB = st;
        const uint32_t bB = st + A_TILE_B;

#pragma unroll
        for (int ks = 0; ks < BK; ks += 16) {
            uint32_t bh_[4][2];
            const uint32_t brow = (uint32_t)(wn * 32 + (lane & 7));
            const uint32_t bk_  = (uint32_t)(ks + ((lane >> 3) & 1) * 8);
#pragma unroll
            for (int an = 0; an < 4; an++) {
                const uint32_t off = ((brow + an * 8) * LDK + bk_) * 2;
                ldsm_x2(bh_[an], bB + off);
            }
            const uint32_t arow = (uint32_t)(wm * 64 + (lane & 15));
            const uint32_t ak_  = (uint32_t)(ks + (lane >> 4) * 8);
#pragma unroll
            for (int am = 0; am < 4; am++) {
                uint32_t ah_[4];
                const uint32_t off = ((arow + am * 16) * LDK + ak_) * 2;
                ldsm_x4(ah_, aB + off);
#pragma unroll
                for (int an = 0; an < 4; an++)
                    mma_f16(acc[am][an], ah_, bh_[an]);
            }
        }
    }
#undef ISSUE

    const int fr = lane >> 2;
    const int fc = (lane & 3) << 1;
    const bool phi = FUSED && (wsel < 2);
#pragma unroll
    for (int am = 0; am < 4; am++) {
        const int m0 = bm + wm * 64 + am * 16 + fr;
#pragma unroll
        for (int an = 0; an < 4; an++) {
            const int c = bn + wn * 32 + an * 8 + fc;
            const float bb0 = bias[c], bb1 = bias[c + 1];
#pragma unroll
            for (int half = 0; half < 2; half++) {
                const int m = m0 + half * 8;
                float y0 = acc[am][an][2 * half]     + bb0;
                float y1 = acc[am][an][2 * half + 1] + bb1;
                if (FUSED) {
                    if (phi) {
                        y0 = (y0 > 0.f) ? (y0 + 1.f) : __expf(y0);
                        y1 = (y1 > 0.f) ? (y1 + 1.f) : __expf(y1);
                    }
                    const int b  = m >> 12;
                    const int s  = m & 4095;
                    const int h  = c >> 6;
                    const int e0 = c & 63;
                    const size_t idx = ((size_t)(b * Hn + h) * Sq + s) * Hd + e0;
                    *(uint32_t*)(outh + idx) = cvt_hi(y0, y1);
                } else {
                    *(float2*)(out + (size_t)m * Dm + c) = make_float2(y0, y1);
                }
            }
        }
    }
}

// ---------------------------------------------------------------------------
// Per-chunk partials (fp16-hi inputs, fp32 accum): Sp = sum_t k^T v; zp
// ---------------------------------------------------------------------------
__global__ void __launch_bounds__(256)
chunk_kv_k()
{
    __shared__ __align__(16) float ks[64 * Hd];
    __shared__ __align__(16) float vs[64 * Hd];
    const int c   = blockIdx.x;
    const int bh  = blockIdx.y;
    const int tid = threadIdx.x;
    const size_t base = ((size_t)bh * Sq + (size_t)c * Ck) * Hd;

    const int r  = tid & 63;
    const int j0 = (tid >> 6) << 4;

    float acc[16];
#pragma unroll
    for (int j = 0; j < 16; j++) acc[j] = 0.f;
    float zacc = 0.f;

    for (int half = 0; half < 2; half++) {
        const size_t hb = base + (size_t)half * 64 * Hd;
        __syncthreads();
        for (int i = tid; i < 64 * Hd / 4; i += 256) {
            const uint2 kh = ((const uint2*)(g_kh + hb))[i];
            const uint2 vh = ((const uint2*)(g_vh + hb))[i];
            ((float4*)ks)[i] = make_float4(u32lo(kh.x), u32hi(kh.x),
                                           u32lo(kh.y), u32hi(kh.y));
            ((float4*)vs)[i] = make_float4(u32lo(vh.x), u32hi(vh.x),
                                           u32lo(vh.y), u32hi(vh.y));
        }
        __syncthreads();
        for (int t = 0; t < 64; t++) {
            const float kv = ks[t * Hd + r];
            zacc += kv;
            const float4* vrow = (const float4*)&vs[t * Hd + j0];
            const float4 v0 = vrow[0], v1 = vrow[1], v2 = vrow[2], v3 = vrow[3];
            acc[0]  = fmaf(kv, v0.x, acc[0]);  acc[1]  = fmaf(kv, v0.y, acc[1]);
            acc[2]  = fmaf(kv, v0.z, acc[2]);  acc[3]  = fmaf(kv, v0.w, acc[3]);
            acc[4]  = fmaf(kv, v1.x, acc[4]);  acc[5]  = fmaf(kv, v1.y, acc[5]);
            acc[6]  = fmaf(kv, v1.z, acc[6]);  acc[7]  = fmaf(kv, v1.w, acc[7]);
            acc[8]  = fmaf(kv, v2.x, acc[8]);  acc[9]  = fmaf(kv, v2.y, acc[9]);
            acc[10] = fmaf(kv, v2.z, acc[10]); acc[11] = fmaf(kv, v2.w, acc[11]);
            acc[12] = fmaf(kv, v3.x, acc[12]); acc[13] = fmaf(kv, v3.y, acc[13]);
            acc[14] = fmaf(kv, v3.z, acc[14]); acc[15] = fmaf(kv, v3.w, acc[15]);
        }
    }

    float* Sd = g_Sp + ((size_t)bh * Nch + c) * (Hd * Hd) + r * Hd + j0;
#pragma unroll
    for (int j = 0; j < 16; j++) Sd[j] = acc[j];
    if (tid < Hd) g_zp[((size_t)bh * Nch + c) * Hd + tid] = zacc;
}

// ---------------------------------------------------------------------------
// Exclusive scan over chunks: one thread per S element (coalesced per step).
// grid (BHn*Hd*Hd/256); z handled by first Hd threads of per-bh slice.
// ---------------------------------------------------------------------------
__global__ void __launch_bounds__(256)
scan_k()
{
    const int e   = blockIdx.x * 256 + threadIdx.x;     // 0 .. BHn*Hd*Hd-1
    const int bh  = e >> 12;                            // /4096
    const int el  = e & 4095;
    float* Sb = g_Sp + (size_t)bh * Nch * Hd * Hd + el;
    float acc = 0.f;
#pragma unroll 4
    for (int c2 = 0; c2 < Nch; c2++) {
        const float v = Sb[(size_t)c2 * Hd * Hd];
        Sb[(size_t)c2 * Hd * Hd] = acc;
        acc += v;
    }
    if (el < Hd) {
        float* zb = g_zp + (size_t)bh * Nch * Hd + el;
        float za = 0.f;
#pragma unroll 4
        for (int c2 = 0; c2 < Nch; c2++) {
            const float v = zb[(size_t)c2 * Hd];
            zb[(size_t)c2 * Hd] = za;
            za += v;
        }
    }
}

// ---------------------------------------------------------------------------
// Fused attention per (chunk, bh): 1-term fp16, 102KB smem (2 CTAs/SM).
// ---------------------------------------------------------------------------
constexpr int QK_STR = 72;
constexpr int SC_STR = 136;
constexpr int OFF_QH  = 0;
constexpr int OFF_KH  = OFF_QH + 128 * QK_STR * 2;   // 18432
constexpr int OFF_VH  = OFF_KH + 18432;              // 36864
constexpr int OFF_SXH = OFF_VH + 18432;              // 55296
constexpr int OFF_SCH = OFF_SXH + 64 * QK_STR * 2;   // 64512
constexpr int OFF_DEN = OFF_SCH + 128 * SC_STR * 2;  // 99328
constexpr int OFF_DENP = OFF_DEN + 512;              // 99840
constexpr int ATTN_SMEM = OFF_DENP + 2048;           // 101888

__global__ void __launch_bounds__(256)
attn_fused_k()
{
    extern __shared__ char dsm[];
    const uint32_t sb = smem_u32(dsm);
    const int c    = blockIdx.x;
    const int bh   = blockIdx.y;
    const int tid  = threadIdx.x;
    const int lane = tid & 31;
    const int wid  = tid >> 5;
    const int wm   = wid >> 2;
    const int wn   = wid & 3;
    const size_t base = ((size_t)bh * Sq + (size_t)c * Ck) * Hd;

    for (int i = tid; i < 128 * 8; i += 256) {
        const uint32_t so = (uint32_t)((i >> 3) * (QK_STR * 2) + (i & 7) * 16);
        const size_t g = base + (size_t)(i >> 3) * Hd + (i & 7) * 8;
        cp_async16(sb + OFF_QH + so, g_qh + g);
        cp_async16(sb + OFF_KH + so, g_kh + g);
    }
    cp_commit();
    {
        const size_t sxb = ((size_t)bh * Nch + c) * (Hd * Hd);
        for (int i = tid; i < 128 * 8; i += 256) {
            const uint32_t so = (uint32_t)((i >> 3) * (QK_STR * 2) + (i & 7) * 16);
            const size_t g = base + (size_t)(i >> 3) * Hd + (i & 7) * 8;
            cp_async16(sb + OFF_VH + so, g_vh + g);
            if (i < 64 * 8) {
                const size_t gx = sxb + (size_t)(i >> 3) * Hd + (i & 7) * 8;
                cp_async16(sb + OFF_SXH + so, g_sph + gx);
            }
        }
        cp_commit();
    }
    cp_wait1();
    __syncthreads();

    const int fr = lane >> 2;
    const int fc = (lane & 3) << 1;

    // phase 1: sc = q.k^T
    {
        float acc[4][4][4];
#pragma unroll
        for (int i = 0; i < 4; i++)
#pragma unroll
            for (int j = 0; j < 4; j++)
#pragma unroll
                for (int r = 0; r < 4; r++) acc[i][j][r] = 0.f;

#pragma unroll
        for (int ksk = 0; ksk < 64; ksk += 16) {
            uint32_t bh_[4][2];
            const uint32_t brow = (uint32_t)(wn * 32 + (lane & 7));
            const uint32_t bk_  = (uint32_t)(ksk + ((lane >> 3) & 1) * 8);
#pragma unroll
            for (int an = 0; an < 4; an++) {
                const uint32_t off = ((brow + an * 8) * QK_STR + bk_) * 2;
                ldsm_x2(bh_[an], sb + OFF_KH + off);
            }
            const uint32_t arow = (uint32_t)(wm * 64 + (lane & 15));
            const uint32_t ak_  = (uint32_t)(ksk + (lane >> 4) * 8);
#pragma unroll
            for (int am = 0; am < 4; am++) {
                uint32_t ah_[4];
                const uint32_t off = ((arow + am * 16) * QK_STR + ak_) * 2;
                ldsm_x4(ah_, sb + OFF_QH + off);
#pragma unroll
                for (int an = 0; an < 4; an++)
                    mma_f16(acc[am][an], ah_, bh_[an]);
            }
        }

        float rs[8];
#pragma unroll
        for (int i = 0; i < 8; i++) rs[i] = 0.f;
#pragma unroll
        for (int am = 0; am < 4; am++) {
            const int t0r = wm * 64 + am * 16 + fr;
#pragma unroll
            for (int an = 0; an < 4; an++) {
                const int u0 = wn * 32 + an * 8 + fc;
#pragma unroll
                for (int half = 0; half < 2; half++) {
                    const int t = t0r + half * 8;
                    float v0 = (u0     <= t) ? acc[am][an][2 * half]     : 0.f;
                    float v1 = (u0 + 1 <= t) ? acc[am][an][2 * half + 1] : 0.f;
                    rs[am * 2 + half] += v0 + v1;
                    *(uint32_t*)(dsm + OFF_SCH + (t * SC_STR + u0) * 2) =
                        cvt_hi(v0, v1);
                }
            }
        }
#pragma unroll
        for (int idx = 0; idx < 8; idx++) {
            float s = rs[idx];
            s += __shfl_xor_sync(0xffffffffu, s, 1);
            s += __shfl_xor_sync(0xffffffffu, s, 2);
            if ((lane & 3) == 0) {
                const int row = wm * 64 + (idx >> 1) * 16 + fr + (idx & 1) * 8;
                *(float*)(dsm + OFF_DENP + (row * 4 + wn) * 4) = s;
            }
        }
    }
    cp_wait0();
    __syncthreads();

    // den
    {
        const int t  = tid >> 1;
        const int d0 = (tid & 1) << 5;
        float s = 0.f;
        if ((tid & 1) == 0) {
#pragma unroll
            for (int j = 0; j < 4; j++)
                s += *(float*)(dsm + OFF_DENP + (t * 4 + j) * 4);
        }
        const float* z = g_zp + ((size_t)bh * Nch + c) * Hd + d0;
#pragma unroll
        for (int d = 0; d < 32; d++) {
            const uint16_t hb = *(const uint16_t*)(dsm + OFF_QH + (t * QK_STR + d0 + d) * 2);
            s = fmaf(h2f16(hb), z[d], s);
        }
        s += __shfl_xor_sync(0xffffffffu, s, 1);
        if ((tid & 1) == 0) *(float*)(dsm + OFF_DEN + t * 4) = s;
    }
    __syncthreads();

    // phase 2: num = sc@V + q@Sx
    float a2[4][2][4];
#pragma unroll
    for (int i = 0; i < 4; i++)
#pragma unroll
        for (int j = 0; j < 2; j++)
#pragma unroll
            for (int r = 0; r < 4; r++) a2[i][j][r] = 0.f;

#pragma unroll
    for (int ksk = 0; ksk < 128; ksk += 16) {
        uint32_t bh2[2][2];
        const uint32_t krow = (uint32_t)(ksk + (lane & 15));
#pragma unroll
        for (int an = 0; an < 2; an++) {
            const uint32_t n0 = (uint32_t)(wn * 16 + an * 8);
            const uint32_t off = (krow * QK_STR + n0) * 2;
            ldsm_x2_t(bh2[an], sb + OFF_VH + off);
        }
        const uint32_t arow = (uint32_t)(wm * 64 + (lane & 15));
        const uint32_t ak_  = (uint32_t)(ksk + (lane >> 4) * 8);
#pragma unroll
        for (int am = 0; am < 4; am++) {
            uint32_t ah_[4];
            const uint32_t off = ((arow + am * 16) * SC_STR + ak_) * 2;
            ldsm_x4(ah_, sb + OFF_SCH + off);
#pragma unroll
            for (int an = 0; an < 2; an++)
                mma_f16(a2[am][an], ah_, bh2[an]);
        }
    }
#pragma unroll
    for (int ksk = 0; ksk < 64; ksk += 16) {
        uint32_t bh2[2][2];
        const uint32_t krow = (uint32_t)(ksk + (lane & 15));
#pragma unroll
        for (int an = 0; an < 2; an++) {
            const uint32_t n0 = (uint32_t)(wn * 16 + an * 8);
            const uint32_t off = (krow * QK_STR + n0) * 2;
            ldsm_x2_t(bh2[an], sb + OFF_SXH + off);
        }
        const uint32_t arow = (uint32_t)(wm * 64 + (lane & 15));
        const uint32_t ak_  = (uint32_t)(ksk + (lane >> 4) * 8);
#pragma unroll
        for (int am = 0; am < 4; am++) {
            uint32_t ah_[4];
            const uint32_t off = ((arow + am * 16) * QK_STR + ak_) * 2;
            ldsm_x4(ah_, sb + OFF_QH + off);
#pragma unroll
            for (int an = 0; an < 2; an++)
                mma_f16(a2[am][an], ah_, bh2[an]);
        }
    }

    // epilogue
    const int b = bh >> 4, h = bh & 15;
#pragma unroll
    for (int am = 0; am < 4; am++) {
        const int t0r = wm * 64 + am * 16 + fr;
        const float inv0 = 1.f / *(const float*)(dsm + OFF_DEN + t0r * 4);
        const float inv1 = 1.f / *(const float*)(dsm + OFF_DEN + (t0r + 8) * 4);
#pragma unroll
        for (int an = 0; an < 2; an++) {
            const int e0 = wn * 16 + an * 8 + fc;
            const size_t idx0 = ((size_t)b * Sq + (size_t)c * Ck + t0r) * Dm + h * Hd + e0;
            *(uint32_t*)(g_ath + idx0) =
                cvt_hi(a2[am][an][0] * inv0, a2[am][an][1] * inv0);
            *(uint32_t*)(g_ath + idx0 + (size_t)8 * Dm) =
                cvt_hi(a2[am][an][2] * inv1, a2[am][an][3] * inv1);
        }
    }
}

// ---------------------------------------------------------------------------
extern "C" void kernel_launch(void* const* d_in, const int* in_sizes, int n_in,
                              void* d_out, int out_size)
{
    const float* x = nullptr;
    const float* Ws[4] = {nullptr, nullptr, nullptr, nullptr};
    const float* bs[4] = {nullptr, nullptr, nullptr, nullptr};
    int wi = 0, bi = 0;
    for (int i = 0; i < n_in; i++) {
        const int sz = in_sizes[i];
        if (sz == Mtot * Dm)      { x = (const float*)d_in[i]; }
        else if (sz == DD)        { if (wi < 4) Ws[wi++] = (const float*)d_in[i]; }
        else if (sz == Dm)        { if (bi < 4) bs[bi++] = (const float*)d_in[i]; }
    }
    float* out = (float*)d_out;

    // TRUE device addresses (never pass __device__ symbols from host — ATS!)
    float *psp;
    uint16_t *pxh, *pwh, *pqh, *pkh, *pvh, *psph, *path;
    cudaGetSymbolAddress((void**)&psp,  g_Sp);
    cudaGetSymbolAddress((void**)&pxh,  g_xh);
    cudaGetSymbolAddress((void**)&pwh,  g_wh);
    cudaGetSymbolAddress((void**)&pqh,  g_qh);
    cudaGetSymbolAddress((void**)&pkh,  g_kh);
    cudaGetSymbolAddress((void**)&pvh,  g_vh);
    cudaGetSymbolAddress((void**)&psph, g_sph);
    cudaGetSymbolAddress((void**)&path, g_ath);

    cudaFuncSetAttribute(fp_gemm_k<0>, cudaFuncAttributeMaxDynamicSharedMemorySize, GEMM_DSMEM);
    cudaFuncSetAttribute(fp_gemm_k<1>, cudaFuncAttributeMaxDynamicSharedMemorySize, GEMM_DSMEM);
    cudaFuncSetAttribute(attn_fused_k, cudaFuncAttributeMaxDynamicSharedMemorySize, ATTN_SMEM);

    // Pre-convert operands to fp16 hi (once).
    cvt_hi_k<<<4096, 256>>>(x, pxh, Mtot * Dm / 8);
    for (int i = 0; i < 4; i++)
        cvt_hi_k<<<512, 256>>>(Ws[i], pwh + (size_t)i * DD, DD / 8);

    // Fused q/k/v projections: grid.x spans 3 weight matrices.
    fp_gemm_k<1><<<dim3(3 * Dm / 256, Mtot / 128), 512, GEMM_DSMEM>>>(
        pxh, pwh, bs[0], bs[1], bs[2], nullptr, pqh, pkh, pvh);

    chunk_kv_k<<<dim3(Nch, BHn), 256>>>();
    scan_k<<<BHn * Hd * Hd / 256, 256>>>();
    cvt_hi_k<<<2048, 256>>>(psp, psph, BHn * Nch * Hd * Hd / 8);
    attn_fused_k<<<dim3(Nch, BHn), 256, ATTN_SMEM>>>();

    fp_gemm_k<0><<<dim3(Dm / 256, Mtot / 128), 512, GEMM_DSMEM>>>(
        path, pwh + 3 * (size_t)DD, bs[3], nullptr, nullptr, out,
        nullptr, nullptr, nullptr);
}